// round 1
// baseline (speedup 1.0000x reference)
#include <cuda_runtime.h>
#include <math.h>

#define B_ROWS 65536
#define D_IN   784
#define D_HID  512
#define D_LAT  256
#define N_CODES 256

// ---------------- scratch (device globals; no allocation allowed) ----------
__device__ float g_h  [(size_t)B_ROWS * D_HID];   // encoder hidden
__device__ float g_enc[(size_t)B_ROWS * D_LAT];   // encoder latent
__device__ float g_r  [(size_t)B_ROWS * D_LAT];   // residual
__device__ float g_q  [(size_t)B_ROWS * D_LAT];   // quantized
__device__ float g_S  [(size_t)B_ROWS * N_CODES]; // VQ scores
__device__ float g_d  [(size_t)B_ROWS * D_HID];   // decoder hidden
__device__ float g_cbT[2 * N_CODES * D_LAT];      // transposed codebooks
__device__ float g_cnorm[2 * N_CODES];            // per-code squared norms
__device__ double g_loss[3];                      // recon_sum, commit0, commit1

// ---------------- small helpers -------------------------------------------
__global__ void init_k() {
    if (threadIdx.x < 3) g_loss[threadIdx.x] = 0.0;
}

// one block per codebook: transpose + squared norms
__global__ void prep_cb_k(const float* __restrict__ cb0,
                          const float* __restrict__ cb1) {
    int c = blockIdx.x;
    const float* cb = c ? cb1 : cb0;
    float* T = g_cbT + (size_t)c * N_CODES * D_LAT;
    int n = threadIdx.x;  // 256 threads, one per code
    float s = 0.f;
    for (int k = 0; k < D_LAT; k++) {
        float v = cb[(size_t)n * D_LAT + k];
        T[(size_t)k * N_CODES + n] = v;
        s = fmaf(v, v, s);
    }
    g_cnorm[c * N_CODES + n] = s;
}

__global__ void finalize_k(float* __restrict__ out_loss) {
    double loss = g_loss[0] / ((double)B_ROWS * (double)D_IN)
                + 0.25 * ((g_loss[1] + g_loss[2]) / ((double)B_ROWS * (double)D_LAT));
    out_loss[0] = (float)loss;
}

// ---------------- SGEMM: C[M,N] = A[M,K] @ B[K,N] (row-major) --------------
// EPI: 0 = none, 1 = +bias, 2 = +bias,relu, 3 = +bias,tanh, write recon,
//      accumulate sum((recon - X)^2) into lossAcc.
#define BM 128
#define BN 128
#define BKK 16

template <int EPI>
__global__ void __launch_bounds__(256)
sgemm_k(const float* __restrict__ A, const float* __restrict__ Bm,
        const float* __restrict__ bias, float* __restrict__ C,
        int M, int N, int K,
        const float* __restrict__ X, double* __restrict__ lossAcc) {
    __shared__ float As[BKK][BM];
    __shared__ float Bs[BKK][BN + 4];

    int tid = threadIdx.x;
    int tx = tid & 15, ty = tid >> 4;
    int m0 = blockIdx.y * BM, n0 = blockIdx.x * BN;

    float acc[8][8];
#pragma unroll
    for (int i = 0; i < 8; i++)
#pragma unroll
        for (int j = 0; j < 8; j++) acc[i][j] = 0.f;

    const float* Ab = A + (size_t)m0 * K;

    for (int k0 = 0; k0 < K; k0 += BKK) {
        // Load A tile (BM x BKK): 512 float4s over 256 threads
#pragma unroll
        for (int i = 0; i < 2; i++) {
            int id = tid + i * 256;
            int row = id >> 2;
            int kk = (id & 3) << 2;
            float4 v = *(const float4*)(Ab + (size_t)row * K + k0 + kk);
            As[kk + 0][row] = v.x;
            As[kk + 1][row] = v.y;
            As[kk + 2][row] = v.z;
            As[kk + 3][row] = v.w;
        }
        // Load B tile (BKK x BN) with N-bounds predication (N%4==0 always)
#pragma unroll
        for (int i = 0; i < 2; i++) {
            int id = tid + i * 256;
            int kr = id >> 5;
            int c4 = (id & 31) << 2;
            int gc = n0 + c4;
            float4 v;
            if (gc < N) v = *(const float4*)(Bm + (size_t)(k0 + kr) * N + gc);
            else        v = make_float4(0.f, 0.f, 0.f, 0.f);
            *(float4*)&Bs[kr][c4] = v;
        }
        __syncthreads();

#pragma unroll
        for (int k = 0; k < BKK; k++) {
            float4 a0 = *(const float4*)&As[k][ty * 8];
            float4 a1 = *(const float4*)&As[k][ty * 8 + 4];
            float4 b0 = *(const float4*)&Bs[k][tx * 8];
            float4 b1 = *(const float4*)&Bs[k][tx * 8 + 4];
            float am[8] = {a0.x, a0.y, a0.z, a0.w, a1.x, a1.y, a1.z, a1.w};
            float bn[8] = {b0.x, b0.y, b0.z, b0.w, b1.x, b1.y, b1.z, b1.w};
#pragma unroll
            for (int i = 0; i < 8; i++)
#pragma unroll
                for (int j = 0; j < 8; j++)
                    acc[i][j] = fmaf(am[i], bn[j], acc[i][j]);
        }
        __syncthreads();
    }

    float lsum = 0.f;
#pragma unroll
    for (int i = 0; i < 8; i++) {
        int gm = m0 + ty * 8 + i;
#pragma unroll
        for (int j = 0; j < 8; j++) {
            int gn = n0 + tx * 8 + j;
            if (gn < N) {
                float v = acc[i][j];
                if (EPI >= 1) v += bias[gn];
                if (EPI == 2) v = fmaxf(v, 0.f);
                if (EPI == 3) {
                    v = tanhf(v);
                    float dd = v - X[(size_t)gm * N + gn];
                    lsum = fmaf(dd, dd, lsum);
                }
                C[(size_t)gm * N + gn] = v;
            }
        }
    }

    if (EPI == 3) {
        __shared__ float red[256];
        red[tid] = lsum;
        __syncthreads();
        for (int s = 128; s > 0; s >>= 1) {
            if (tid < s) red[tid] += red[tid + s];
            __syncthreads();
        }
        if (tid == 0) atomicAdd(lossAcc, (double)red[0]);
    }
}

// ---------------- VQ: argmin + gather + residual update --------------------
// One warp handles one row at a time; block = 8 warps x 8 rows = 64 rows.
// d_j = cnorm[j] - 2*S[m,j]  (row-constant ||r||^2 dropped; first-min tiebreak
// matches jnp.argmin).
__global__ void __launch_bounds__(256)
vq_pass_k(const float* __restrict__ S, const float* __restrict__ cb,
          const float* __restrict__ cnorm,
          const float* __restrict__ rin, float* __restrict__ rout,
          const float* __restrict__ enc, float* __restrict__ quant,
          float* __restrict__ idx_out, int pass, double* __restrict__ commitAcc) {
    int warp = threadIdx.x >> 5, lane = threadIdx.x & 31;
    __shared__ float wsum[8];
    float csum = 0.f;

    for (int r = 0; r < 8; r++) {
        int m = blockIdx.x * 64 + warp * 8 + r;
        const float* Sr = S + (size_t)m * N_CODES;

        float best = 3.4e38f;
        int bi = 0x7fffffff;
#pragma unroll
        for (int t = 0; t < 8; t++) {
            int j = t * 32 + lane;  // increasing j per lane -> first-min kept
            float dv = fmaf(-2.f, Sr[j], cnorm[j]);
            if (dv < best) { best = dv; bi = j; }
        }
#pragma unroll
        for (int off = 16; off > 0; off >>= 1) {
            float ov = __shfl_down_sync(0xffffffffu, best, off);
            int   oi = __shfl_down_sync(0xffffffffu, bi, off);
            if (ov < best || (ov == best && oi < bi)) { best = ov; bi = oi; }
        }
        bi = __shfl_sync(0xffffffffu, bi, 0);
        if (lane == 0) idx_out[(size_t)m * 2 + pass] = (float)bi;

        const float4* rin4 = (const float4*)(rin + (size_t)m * D_LAT);
        float4*       rout4 = (float4*)(rout + (size_t)m * D_LAT);
        const float4* cb4 = (const float4*)(cb + (size_t)bi * D_LAT);
#pragma unroll
        for (int t = 0; t < 2; t++) {
            int e = t * 32 + lane;
            float4 rv = rin4[e], cv = cb4[e];
            float4 o;
            o.x = rv.x - cv.x; o.y = rv.y - cv.y;
            o.z = rv.z - cv.z; o.w = rv.w - cv.w;
            rout4[e] = o;
            csum += o.x * o.x + o.y * o.y + o.z * o.z + o.w * o.w;
            if (pass) {
                const float4* enc4 = (const float4*)(enc + (size_t)m * D_LAT);
                float4 ev = enc4[e];
                float4 q;
                q.x = ev.x - o.x; q.y = ev.y - o.y;
                q.z = ev.z - o.z; q.w = ev.w - o.w;
                ((float4*)(quant + (size_t)m * D_LAT))[e] = q;
            }
        }
    }

#pragma unroll
    for (int off = 16; off > 0; off >>= 1)
        csum += __shfl_down_sync(0xffffffffu, csum, off);
    if (lane == 0) wsum[warp] = csum;
    __syncthreads();
    if (threadIdx.x == 0) {
        float s = 0.f;
        for (int i = 0; i < 8; i++) s += wsum[i];
        atomicAdd(commitAcc, (double)s);
    }
}

// ---------------- launch ----------------------------------------------------
extern "C" void kernel_launch(void* const* d_in, const int* in_sizes, int n_in,
                              void* d_out, int out_size) {
    const float* x   = (const float*)d_in[0];
    const float* We1 = (const float*)d_in[1];
    const float* be1 = (const float*)d_in[2];
    const float* We2 = (const float*)d_in[3];
    const float* be2 = (const float*)d_in[4];
    const float* cb0 = (const float*)d_in[5];
    const float* cb1 = (const float*)d_in[6];
    const float* Wd1 = (const float*)d_in[7];
    const float* bd1 = (const float*)d_in[8];
    const float* Wd2 = (const float*)d_in[9];
    const float* bd2 = (const float*)d_in[10];

    float* out       = (float*)d_out;
    float* out_recon = out;                                  // [B,784]
    float* out_idx   = out + (size_t)B_ROWS * D_IN;          // [B,2] as f32
    float* out_loss  = out + (size_t)B_ROWS * D_IN + (size_t)B_ROWS * 2;

    float *ph, *penc, *pr, *pq, *pS, *pd, *pcbT, *pcn;
    double* pl;
    cudaGetSymbolAddress((void**)&ph,   g_h);
    cudaGetSymbolAddress((void**)&penc, g_enc);
    cudaGetSymbolAddress((void**)&pr,   g_r);
    cudaGetSymbolAddress((void**)&pq,   g_q);
    cudaGetSymbolAddress((void**)&pS,   g_S);
    cudaGetSymbolAddress((void**)&pd,   g_d);
    cudaGetSymbolAddress((void**)&pcbT, g_cbT);
    cudaGetSymbolAddress((void**)&pcn,  g_cnorm);
    cudaGetSymbolAddress((void**)&pl,   g_loss);

    dim3 blk(256);

    init_k<<<1, 32>>>();
    prep_cb_k<<<2, 256>>>(cb0, cb1);

    // encoder
    sgemm_k<2><<<dim3(D_HID / BN, B_ROWS / BM), blk>>>(
        x, We1, be1, ph, B_ROWS, D_HID, D_IN, nullptr, nullptr);
    sgemm_k<1><<<dim3(D_LAT / BN, B_ROWS / BM), blk>>>(
        ph, We2, be2, penc, B_ROWS, D_LAT, D_HID, nullptr, nullptr);

    // VQ quantizer 0
    sgemm_k<0><<<dim3(N_CODES / BN, B_ROWS / BM), blk>>>(
        penc, pcbT, nullptr, pS, B_ROWS, N_CODES, D_LAT, nullptr, nullptr);
    vq_pass_k<<<B_ROWS / 64, 256>>>(pS, cb0, pcn, penc, pr,
                                    nullptr, nullptr, out_idx, 0, pl + 1);
    // VQ quantizer 1 (also emits quantized = enc - r_final)
    sgemm_k<0><<<dim3(N_CODES / BN, B_ROWS / BM), blk>>>(
        pr, pcbT + N_CODES * D_LAT, nullptr, pS, B_ROWS, N_CODES, D_LAT,
        nullptr, nullptr);
    vq_pass_k<<<B_ROWS / 64, 256>>>(pS, cb1, pcn + N_CODES, pr, pr,
                                    penc, pq, out_idx, 1, pl + 2);

    // decoder
    sgemm_k<2><<<dim3(D_HID / BN, B_ROWS / BM), blk>>>(
        pq, Wd1, bd1, pd, B_ROWS, D_HID, D_LAT, nullptr, nullptr);
    sgemm_k<3><<<dim3((D_IN + BN - 1) / BN, B_ROWS / BM), blk>>>(
        pd, Wd2, bd2, out_recon, B_ROWS, D_IN, D_HID, x, pl + 0);

    finalize_k<<<1, 1>>>(out_loss);
}

// round 4
// speedup vs baseline: 1.3116x; 1.3116x over previous
#include <cuda_runtime.h>
#include <cuda_bf16.h>
#include <cstdint>
#include <math.h>

#define B_ROWS 65536
#define D_IN   784
#define D_HID  512
#define D_LAT  256
#define N_CODES 256
#define N_PAD  896           // dec2 N padded to 7*128
#define K1X    (3 * D_LAT)   // 768  : dec1 extended K
#define K2X    (3 * D_HID)   // 1536 : dec2 extended K

// ---------------- scratch (device globals; no allocation allowed) ----------
__device__ float g_h  [(size_t)B_ROWS * D_HID];   // encoder hidden (fp32)
__device__ float g_enc[(size_t)B_ROWS * D_LAT];   // encoder latent
__device__ float g_r  [(size_t)B_ROWS * D_LAT];   // residual
__device__ float g_S  [(size_t)B_ROWS * N_CODES]; // VQ scores
__device__ __nv_bfloat16 g_q3[(size_t)B_ROWS * K1X];   // [qh|ql|qh]
__device__ __nv_bfloat16 g_d3[(size_t)B_ROWS * K2X];   // [dh|dl|dh]
__device__ __nv_bfloat16 g_W1b[(size_t)D_HID * K1X];   // [Wh|Wh|Wl] of Wd1^T
__device__ __nv_bfloat16 g_W2b[(size_t)N_PAD * K2X];   // [Wh|Wh|Wl] of Wd2^T
__device__ float g_cbT[2 * N_CODES * D_LAT];      // transposed codebooks
__device__ float g_cnorm[2 * N_CODES];            // per-code squared norms
__device__ double g_loss[3];                      // recon_sum, commit0, commit1

// ====================== PTX helpers (base-target safe) =====================
__device__ __forceinline__ uint32_t smem_u32(const void* p) {
    uint32_t a;
    asm("{ .reg .u64 t; cvta.to.shared.u64 t, %1; cvt.u32.u64 %0, t; }"
        : "=r"(a) : "l"(p));
    return a;
}
#define CP16(dst, src) \
    asm volatile("cp.async.cg.shared.global [%0], [%1], 16;" :: "r"(dst), "l"(src) : "memory")
#define CP_COMMIT() asm volatile("cp.async.commit_group;" ::: "memory")
#define CP_WAIT(n)  asm volatile("cp.async.wait_group %0;" :: "n"(n) : "memory")

__device__ __forceinline__ void ldsm_x4(uint32_t* r, uint32_t addr) {
    asm volatile("ldmatrix.sync.aligned.m8n8.x4.shared.b16 {%0,%1,%2,%3}, [%4];"
        : "=r"(r[0]), "=r"(r[1]), "=r"(r[2]), "=r"(r[3]) : "r"(addr));
}
__device__ __forceinline__ void mma_bf16(float* c, const uint32_t* a, const uint32_t* b) {
    asm volatile("mma.sync.aligned.m16n8k16.row.col.f32.bf16.bf16.f32 "
        "{%0,%1,%2,%3}, {%4,%5,%6,%7}, {%8,%9}, {%0,%1,%2,%3};"
        : "+f"(c[0]), "+f"(c[1]), "+f"(c[2]), "+f"(c[3])
        : "r"(a[0]), "r"(a[1]), "r"(a[2]), "r"(a[3]), "r"(b[0]), "r"(b[1]));
}

__device__ __forceinline__ void split_bf16(float v, __nv_bfloat16& hi, __nv_bfloat16& lo) {
    hi = __float2bfloat16_rn(v);
    lo = __float2bfloat16_rn(v - __bfloat162float(hi));
}

// ---------------- small helpers -------------------------------------------
__global__ void init_k() {
    if (threadIdx.x < 3) g_loss[threadIdx.x] = 0.0;
}

__global__ void prep_cb_k(const float* __restrict__ cb0,
                          const float* __restrict__ cb1) {
    int c = blockIdx.x;
    const float* cb = c ? cb1 : cb0;
    float* T = g_cbT + (size_t)c * N_CODES * D_LAT;
    int n = threadIdx.x;
    float s = 0.f;
    for (int k = 0; k < D_LAT; k++) {
        float v = cb[(size_t)n * D_LAT + k];
        T[(size_t)k * N_CODES + n] = v;
        s = fmaf(v, v, s);
    }
    g_cnorm[c * N_CODES + n] = s;
}

// Wd1 [256,512] -> g_W1b [512 rows x 768]: [Wh | Wh | Wl] per row (K-major)
__global__ void prep_wd1_k(const float* __restrict__ Wd1) {
    int idx = blockIdx.x * blockDim.x + threadIdx.x;
    if (idx < D_HID * D_LAT) {
        int n = idx / D_LAT, k = idx % D_LAT;
        __nv_bfloat16 hi, lo;
        split_bf16(Wd1[(size_t)k * D_HID + n], hi, lo);
        g_W1b[(size_t)n * K1X + k]             = hi;
        g_W1b[(size_t)n * K1X + D_LAT + k]     = hi;
        g_W1b[(size_t)n * K1X + 2 * D_LAT + k] = lo;
    }
}
// Wd2 [512,784] -> g_W2b [896 rows x 1536]: [Wh | Wh | Wl] (zeros for n>=784)
__global__ void prep_wd2_k(const float* __restrict__ Wd2) {
    int idx = blockIdx.x * blockDim.x + threadIdx.x;
    if (idx < N_PAD * D_HID) {
        int n = idx / D_HID, k = idx % D_HID;
        __nv_bfloat16 hi, lo;
        if (n < D_IN) split_bf16(Wd2[(size_t)k * D_IN + n], hi, lo);
        else { hi = __float2bfloat16(0.f); lo = hi; }
        g_W2b[(size_t)n * K2X + k]             = hi;
        g_W2b[(size_t)n * K2X + D_HID + k]     = hi;
        g_W2b[(size_t)n * K2X + 2 * D_HID + k] = lo;
    }
}

__global__ void finalize_k(float* __restrict__ out_loss) {
    double loss = g_loss[0] / ((double)B_ROWS * (double)D_IN)
                + 0.25 * ((g_loss[1] + g_loss[2]) / ((double)B_ROWS * (double)D_LAT));
    out_loss[0] = (float)loss;
}

// ---------------- fp32 SGEMM (encoder + VQ scores) -------------------------
#define BM 128
#define BN 128
#define BKK 16

template <int EPI>  // 0=none 1=+bias 2=+bias,relu
__global__ void __launch_bounds__(256)
sgemm_k(const float* __restrict__ A, const float* __restrict__ Bm,
        const float* __restrict__ bias, float* __restrict__ C,
        int M, int N, int K) {
    __shared__ float As[BKK][BM];
    __shared__ float Bs[BKK][BN + 4];

    int tid = threadIdx.x;
    int tx = tid & 15, ty = tid >> 4;
    int m0 = blockIdx.y * BM, n0 = blockIdx.x * BN;

    float acc[8][8];
#pragma unroll
    for (int i = 0; i < 8; i++)
#pragma unroll
        for (int j = 0; j < 8; j++) acc[i][j] = 0.f;

    const float* Ab = A + (size_t)m0 * K;

    for (int k0 = 0; k0 < K; k0 += BKK) {
#pragma unroll
        for (int i = 0; i < 2; i++) {
            int id = tid + i * 256;
            int row = id >> 2;
            int kk = (id & 3) << 2;
            float4 v = *(const float4*)(Ab + (size_t)row * K + k0 + kk);
            As[kk + 0][row] = v.x;
            As[kk + 1][row] = v.y;
            As[kk + 2][row] = v.z;
            As[kk + 3][row] = v.w;
        }
#pragma unroll
        for (int i = 0; i < 2; i++) {
            int id = tid + i * 256;
            int kr = id >> 5;
            int c4 = (id & 31) << 2;
            int gc = n0 + c4;
            float4 v;
            if (gc < N) v = *(const float4*)(Bm + (size_t)(k0 + kr) * N + gc);
            else        v = make_float4(0.f, 0.f, 0.f, 0.f);
            *(float4*)&Bs[kr][c4] = v;
        }
        __syncthreads();

#pragma unroll
        for (int k = 0; k < BKK; k++) {
            float4 a0 = *(const float4*)&As[k][ty * 8];
            float4 a1 = *(const float4*)&As[k][ty * 8 + 4];
            float4 b0 = *(const float4*)&Bs[k][tx * 8];
            float4 b1 = *(const float4*)&Bs[k][tx * 8 + 4];
            float am[8] = {a0.x, a0.y, a0.z, a0.w, a1.x, a1.y, a1.z, a1.w};
            float bn[8] = {b0.x, b0.y, b0.z, b0.w, b1.x, b1.y, b1.z, b1.w};
#pragma unroll
            for (int i = 0; i < 8; i++)
#pragma unroll
                for (int j = 0; j < 8; j++)
                    acc[i][j] = fmaf(am[i], bn[j], acc[i][j]);
        }
        __syncthreads();
    }

#pragma unroll
    for (int i = 0; i < 8; i++) {
        int gm = m0 + ty * 8 + i;
#pragma unroll
        for (int j = 0; j < 8; j++) {
            int gn = n0 + tx * 8 + j;
            if (gn < N) {
                float v = acc[i][j];
                if (EPI >= 1) v += bias[gn];
                if (EPI == 2) v = fmaxf(v, 0.f);
                C[(size_t)gm * N + gn] = v;
            }
        }
    }
}

// ---------------- bf16 HMMA GEMM (decoder, split-fp32 via 3x K) -------------
// C[M,N] = A[M,K] @ BT[N,K]^T, both bf16 with K pre-extended 3x.
// EPI 1: +bias, relu -> write [hi | lo | hi] bf16 triple, row stride ldc.
// EPI 2: +bias, tanh -> write f32 + loss vs X, row stride ldc(=Nout).
#define HM 128
#define HN 128
#define HK 32
#define PITCH 80          // 32 bf16 = 64B row + 16B pad (conflict-free LDSM)

template <int EPI>
__global__ void __launch_bounds__(256)
hmma_gemm_k(const __nv_bfloat16* __restrict__ A, const __nv_bfloat16* __restrict__ BT,
            const float* __restrict__ bias, void* __restrict__ Cout,
            int K, int Nout, int ldc,
            const float* __restrict__ X, double* __restrict__ lossAcc) {
    __shared__ char As[2][HM * PITCH];
    __shared__ char Bs[2][HN * PITCH];
    __shared__ float red[8];

    const int tid = threadIdx.x;
    const int wid = tid >> 5, lane = tid & 31;
    const int warp_m = wid >> 1, warp_n = wid & 1;
    const int m0 = blockIdx.y * HM, n0 = blockIdx.x * HN;
    const int NC = K / HK;

    const int ldrow = tid >> 2;          // 0..63 (+64 for second half)
    const int ldseg = (tid & 3) << 4;    // byte offset 0/16/32/48
    const __nv_bfloat16* Ag = A + (size_t)m0 * K;
    const __nv_bfloat16* Bg = BT + (size_t)n0 * K;

    const int a_row = (lane & 15);
    const int a_kb  = (lane >> 4) << 3;
    const int b_row = (lane & 7) + ((lane >> 4) << 3);
    const int b_kb  = ((lane >> 3) & 1) << 3;

    uint32_t a_sm[2], b_sm[2], a_st[2], b_st[2];
#pragma unroll
    for (int s = 0; s < 2; s++) {
        a_sm[s] = smem_u32(&As[s][0]) + (warp_m * 32 + a_row) * PITCH + a_kb * 2;
        b_sm[s] = smem_u32(&Bs[s][0]) + (warp_n * 64 + b_row) * PITCH + b_kb * 2;
        a_st[s] = smem_u32(&As[s][0]) + ldrow * PITCH + ldseg;
        b_st[s] = smem_u32(&Bs[s][0]) + ldrow * PITCH + ldseg;
    }

    float acc[2][8][4];
#pragma unroll
    for (int i = 0; i < 2; i++)
#pragma unroll
        for (int j = 0; j < 8; j++)
#pragma unroll
            for (int t = 0; t < 4; t++) acc[i][j][t] = 0.f;

    {
        const char* Ap = (const char*)Ag + (size_t)ldrow * K * 2 + ldseg;
        const char* Bp = (const char*)Bg + (size_t)ldrow * K * 2 + ldseg;
        size_t half = (size_t)64 * K * 2;
        CP16(a_st[0], Ap);  CP16(a_st[0] + 64 * PITCH, Ap + half);
        CP16(b_st[0], Bp);  CP16(b_st[0] + 64 * PITCH, Bp + half);
        CP_COMMIT();
    }

    for (int i = 0; i < NC; i++) {
        if (i + 1 < NC) {
            int buf = (i + 1) & 1;
            size_t koff = (size_t)(i + 1) * HK * 2;
            const char* Ap = (const char*)Ag + (size_t)ldrow * K * 2 + koff + ldseg;
            const char* Bp = (const char*)Bg + (size_t)ldrow * K * 2 + koff + ldseg;
            size_t half = (size_t)64 * K * 2;
            CP16(a_st[buf], Ap);  CP16(a_st[buf] + 64 * PITCH, Ap + half);
            CP16(b_st[buf], Bp);  CP16(b_st[buf] + 64 * PITCH, Bp + half);
            CP_COMMIT();
            CP_WAIT(1);
        } else {
            CP_WAIT(0);
        }
        __syncthreads();

        int buf = i & 1;
#pragma unroll
        for (int ks = 0; ks < 2; ks++) {
            uint32_t af[2][4];
#pragma unroll
            for (int im = 0; im < 2; im++)
                ldsm_x4(af[im], a_sm[buf] + im * 16 * PITCH + ks * 32);
            uint32_t bf[4][4];
#pragma unroll
            for (int jp = 0; jp < 4; jp++)
                ldsm_x4(bf[jp], b_sm[buf] + jp * 16 * PITCH + ks * 32);
#pragma unroll
            for (int im = 0; im < 2; im++)
#pragma unroll
                for (int jn = 0; jn < 8; jn++)
                    mma_bf16(acc[im][jn], af[im], &bf[jn >> 1][(jn & 1) * 2]);
        }
        __syncthreads();
    }

    // ---- epilogue: direct register writes
    const int qr = lane >> 2, qc = (lane & 3) * 2;
    float lsum = 0.f;
#pragma unroll
    for (int im = 0; im < 2; im++) {
#pragma unroll
        for (int h = 0; h < 2; h++) {
            int gm = m0 + warp_m * 32 + im * 16 + qr + h * 8;
#pragma unroll
            for (int jn = 0; jn < 8; jn++) {
                int gn = n0 + warp_n * 64 + jn * 8 + qc;
                float v0 = acc[im][jn][h * 2 + 0];
                float v1 = acc[im][jn][h * 2 + 1];
                if (EPI == 1) {
                    v0 = fmaxf(v0 + __ldg(&bias[gn]),     0.f);
                    v1 = fmaxf(v1 + __ldg(&bias[gn + 1]), 0.f);
                    __nv_bfloat16 h0, l0, h1, l1;
                    split_bf16(v0, h0, l0);
                    split_bf16(v1, h1, l1);
                    __nv_bfloat16* Cr = (__nv_bfloat16*)Cout + (size_t)gm * ldc;
                    __nv_bfloat162 hp; hp.x = h0; hp.y = h1;
                    __nv_bfloat162 lp; lp.x = l0; lp.y = l1;
                    *(__nv_bfloat162*)(Cr + gn)             = hp;
                    *(__nv_bfloat162*)(Cr + Nout + gn)      = lp;
                    *(__nv_bfloat162*)(Cr + 2 * Nout + gn)  = hp;
                } else {
                    if (gn < Nout) {
                        v0 = tanhf(v0 + __ldg(&bias[gn]));
                        v1 = tanhf(v1 + __ldg(&bias[gn + 1]));
                        const float* Xr = X + (size_t)gm * Nout + gn;
                        float d0 = v0 - Xr[0], d1 = v1 - Xr[1];
                        lsum = fmaf(d0, d0, fmaf(d1, d1, lsum));
                        *(float2*)((float*)Cout + (size_t)gm * ldc + gn) =
                            make_float2(v0, v1);
                    }
                }
            }
        }
    }

    if (EPI == 2) {
#pragma unroll
        for (int off = 16; off > 0; off >>= 1)
            lsum += __shfl_down_sync(0xffffffffu, lsum, off);
        if (lane == 0) red[wid] = lsum;
        __syncthreads();
        if (tid == 0) {
            float s = 0.f;
#pragma unroll
            for (int i = 0; i < 8; i++) s += red[i];
            atomicAdd(lossAcc, (double)s);
        }
    }
}

// ---------------- VQ: argmin + gather + residual update --------------------
__global__ void __launch_bounds__(256)
vq_pass_k(const float* __restrict__ S, const float* __restrict__ cb,
          const float* __restrict__ cnorm,
          const float* __restrict__ rin, float* __restrict__ rout,
          const float* __restrict__ enc, __nv_bfloat16* __restrict__ q3,
          float* __restrict__ idx_out, int pass, double* __restrict__ commitAcc) {
    int warp = threadIdx.x >> 5, lane = threadIdx.x & 31;
    __shared__ float wsum[8];
    float csum = 0.f;

    for (int r = 0; r < 8; r++) {
        int m = blockIdx.x * 64 + warp * 8 + r;
        const float* Sr = S + (size_t)m * N_CODES;

        float best = 3.4e38f;
        int bi = 0x7fffffff;
#pragma unroll
        for (int t = 0; t < 8; t++) {
            int j = t * 32 + lane;
            float dv = fmaf(-2.f, Sr[j], cnorm[j]);
            if (dv < best) { best = dv; bi = j; }
        }
#pragma unroll
        for (int off = 16; off > 0; off >>= 1) {
            float ov = __shfl_down_sync(0xffffffffu, best, off);
            int   oi = __shfl_down_sync(0xffffffffu, bi, off);
            if (ov < best || (ov == best && oi < bi)) { best = ov; bi = oi; }
        }
        bi = __shfl_sync(0xffffffffu, bi, 0);
        if (lane == 0) idx_out[(size_t)m * 2 + pass] = (float)bi;

        const float4* rin4 = (const float4*)(rin + (size_t)m * D_LAT);
        float4*       rout4 = (float4*)(rout + (size_t)m * D_LAT);
        const float4* cb4 = (const float4*)(cb + (size_t)bi * D_LAT);
#pragma unroll
        for (int t = 0; t < 2; t++) {
            int e = t * 32 + lane;
            float4 rv = rin4[e], cv = cb4[e];
            float4 o;
            o.x = rv.x - cv.x; o.y = rv.y - cv.y;
            o.z = rv.z - cv.z; o.w = rv.w - cv.w;
            rout4[e] = o;
            csum += o.x * o.x + o.y * o.y + o.z * o.z + o.w * o.w;
            if (pass) {
                const float4* enc4 = (const float4*)(enc + (size_t)m * D_LAT);
                float4 ev = enc4[e];
                float q0 = ev.x - o.x, q1 = ev.y - o.y;
                float q2 = ev.z - o.z, q3v = ev.w - o.w;
                __nv_bfloat16 h0, l0, h1, l1, h2, l2, h3, l3;
                split_bf16(q0, h0, l0); split_bf16(q1, h1, l1);
                split_bf16(q2, h2, l2); split_bf16(q3v, h3, l3);
                __nv_bfloat162* Qr = (__nv_bfloat162*)(q3 + (size_t)m * K1X);
                __nv_bfloat162 hp0; hp0.x = h0; hp0.y = h1;
                __nv_bfloat162 hp1; hp1.x = h2; hp1.y = h3;
                __nv_bfloat162 lp0; lp0.x = l0; lp0.y = l1;
                __nv_bfloat162 lp1; lp1.x = l2; lp1.y = l3;
                Qr[e * 2 + 0]       = hp0;  Qr[e * 2 + 1]       = hp1;
                Qr[128 + e * 2 + 0] = lp0;  Qr[128 + e * 2 + 1] = lp1;
                Qr[256 + e * 2 + 0] = hp0;  Qr[256 + e * 2 + 1] = hp1;
            }
        }
    }

#pragma unroll
    for (int off = 16; off > 0; off >>= 1)
        csum += __shfl_down_sync(0xffffffffu, csum, off);
    if (lane == 0) wsum[warp] = csum;
    __syncthreads();
    if (threadIdx.x == 0) {
        float s = 0.f;
        for (int i = 0; i < 8; i++) s += wsum[i];
        atomicAdd(commitAcc, (double)s);
    }
}

// ---------------- launch ----------------------------------------------------
extern "C" void kernel_launch(void* const* d_in, const int* in_sizes, int n_in,
                              void* d_out, int out_size) {
    const float* x   = (const float*)d_in[0];
    const float* We1 = (const float*)d_in[1];
    const float* be1 = (const float*)d_in[2];
    const float* We2 = (const float*)d_in[3];
    const float* be2 = (const float*)d_in[4];
    const float* cb0 = (const float*)d_in[5];
    const float* cb1 = (const float*)d_in[6];
    const float* Wd1 = (const float*)d_in[7];
    const float* bd1 = (const float*)d_in[8];
    const float* Wd2 = (const float*)d_in[9];
    const float* bd2 = (const float*)d_in[10];

    float* out       = (float*)d_out;
    float* out_recon = out;
    float* out_idx   = out + (size_t)B_ROWS * D_IN;
    float* out_loss  = out + (size_t)B_ROWS * D_IN + (size_t)B_ROWS * 2;

    float *ph, *penc, *pr, *pS, *pcbT, *pcn;
    __nv_bfloat16 *pq3, *pd3, *pW1b, *pW2b;
    double* pl;
    cudaGetSymbolAddress((void**)&ph,   g_h);
    cudaGetSymbolAddress((void**)&penc, g_enc);
    cudaGetSymbolAddress((void**)&pr,   g_r);
    cudaGetSymbolAddress((void**)&pS,   g_S);
    cudaGetSymbolAddress((void**)&pq3,  g_q3);
    cudaGetSymbolAddress((void**)&pd3,  g_d3);
    cudaGetSymbolAddress((void**)&pW1b, g_W1b);
    cudaGetSymbolAddress((void**)&pW2b, g_W2b);
    cudaGetSymbolAddress((void**)&pcbT, g_cbT);
    cudaGetSymbolAddress((void**)&pcn,  g_cnorm);
    cudaGetSymbolAddress((void**)&pl,   g_loss);

    dim3 blk(256);

    init_k<<<1, 32>>>();
    prep_cb_k<<<2, 256>>>(cb0, cb1);
    prep_wd1_k<<<(D_HID * D_LAT + 255) / 256, 256>>>(Wd1);
    prep_wd2_k<<<(N_PAD * D_HID + 255) / 256, 256>>>(Wd2);

    // encoder (fp32 exact — protects VQ indices)
    sgemm_k<2><<<dim3(D_HID / BN, B_ROWS / BM), blk>>>(
        x, We1, be1, ph, B_ROWS, D_HID, D_IN);
    sgemm_k<1><<<dim3(D_LAT / BN, B_ROWS / BM), blk>>>(
        ph, We2, be2, penc, B_ROWS, D_LAT, D_HID);

    // VQ quantizer 0
    sgemm_k<0><<<dim3(N_CODES / BN, B_ROWS / BM), blk>>>(
        penc, pcbT, nullptr, pS, B_ROWS, N_CODES, D_LAT);
    vq_pass_k<<<B_ROWS / 64, 256>>>(pS, cb0, pcn, penc, pr,
                                    nullptr, nullptr, out_idx, 0, pl + 1);
    // VQ quantizer 1 (emits split quantized q3 = [qh|ql|qh])
    sgemm_k<0><<<dim3(N_CODES / BN, B_ROWS / BM), blk>>>(
        pr, pcbT + N_CODES * D_LAT, nullptr, pS, B_ROWS, N_CODES, D_LAT);
    vq_pass_k<<<B_ROWS / 64, 256>>>(pS, cb1, pcn + N_CODES, pr, pr,
                                    penc, pq3, out_idx, 1, pl + 2);

    // decoder: split-fp32 bf16 HMMA (K extended 3x)
    hmma_gemm_k<1><<<dim3(D_HID / HN, B_ROWS / HM), blk>>>(
        pq3, pW1b, bd1, pd3, K1X, D_HID, K2X, nullptr, nullptr);
    hmma_gemm_k<2><<<dim3(N_PAD / HN, B_ROWS / HM), blk>>>(
        pd3, pW2b, bd2, out_recon, K2X, D_IN, D_IN, x, pl + 0);

    finalize_k<<<1, 1>>>(out_loss);
}

// round 5
// speedup vs baseline: 2.0065x; 1.5298x over previous
#include <cuda_runtime.h>
#include <cuda_bf16.h>
#include <cstdint>
#include <math.h>

#define B_ROWS 65536
#define D_IN   784
#define D_HID  512
#define D_LAT  256
#define N_CODES 256
#define N_PAD  896            // dec2 N padded to 7*128
#define K_X3   2368           // 3*784=2352 padded to 74*32
#define K_H3   (3 * D_HID)    // 1536
#define K_E3   (3 * D_LAT)    // 768

typedef __nv_bfloat16 bf16;
typedef __nv_bfloat162 bf162;

// ---------------- scratch (device globals; no allocation allowed) ----------
__device__ bf16 g_x3 [(size_t)B_ROWS * K_X3];   // [xh|xl|xh|pad]
__device__ bf16 g_h3 [(size_t)B_ROWS * K_H3];   // [hh|hl|hh]
__device__ float g_enc[(size_t)B_ROWS * D_LAT];
__device__ bf16 g_e3 [(size_t)B_ROWS * K_E3];   // [eh|el|eh] then reused r3
__device__ float g_r  [(size_t)B_ROWS * D_LAT];
__device__ float g_S  [(size_t)B_ROWS * N_CODES];
__device__ bf16 g_q3 [(size_t)B_ROWS * K_E3];   // [qh|ql|qh]
__device__ bf16 g_d3 [(size_t)B_ROWS * K_H3];   // [dh|dl|dh]
__device__ bf16 g_We1b[(size_t)D_HID * K_X3];   // [Wh|Wh|Wl|pad]
__device__ bf16 g_We2b[(size_t)D_LAT * K_H3];
__device__ bf16 g_cb3 [2 * N_CODES * K_E3];     // [ch|ch|cl]
__device__ bf16 g_W1b [(size_t)D_HID * K_E3];
__device__ bf16 g_W2b [(size_t)N_PAD * K_H3];
__device__ float g_cnorm[2 * N_CODES];
__device__ double g_loss[3];                    // recon_sum, commit0, commit1

// ====================== PTX helpers ========================================
__device__ __forceinline__ uint32_t smem_u32(const void* p) {
    uint32_t a;
    asm("{ .reg .u64 t; cvta.to.shared.u64 t, %1; cvt.u32.u64 %0, t; }"
        : "=r"(a) : "l"(p));
    return a;
}
#define CP16(dst, src) \
    asm volatile("cp.async.cg.shared.global [%0], [%1], 16;" :: "r"(dst), "l"(src) : "memory")
#define CP_COMMIT() asm volatile("cp.async.commit_group;" ::: "memory")
#define CP_WAIT(n)  asm volatile("cp.async.wait_group %0;" :: "n"(n) : "memory")

__device__ __forceinline__ void ldsm_x4(uint32_t* r, uint32_t addr) {
    asm volatile("ldmatrix.sync.aligned.m8n8.x4.shared.b16 {%0,%1,%2,%3}, [%4];"
        : "=r"(r[0]), "=r"(r[1]), "=r"(r[2]), "=r"(r[3]) : "r"(addr));
}
__device__ __forceinline__ void mma_bf16(float* c, const uint32_t* a, const uint32_t* b) {
    asm volatile("mma.sync.aligned.m16n8k16.row.col.f32.bf16.bf16.f32 "
        "{%0,%1,%2,%3}, {%4,%5,%6,%7}, {%8,%9}, {%0,%1,%2,%3};"
        : "+f"(c[0]), "+f"(c[1]), "+f"(c[2]), "+f"(c[3])
        : "r"(a[0]), "r"(a[1]), "r"(a[2]), "r"(a[3]), "r"(b[0]), "r"(b[1]));
}
__device__ __forceinline__ void split_bf16(float v, bf16& hi, bf16& lo) {
    hi = __float2bfloat16_rn(v);
    lo = __float2bfloat16_rn(v - __bfloat162float(hi));
}

// ---------------- prep kernels ---------------------------------------------
__global__ void init_k() {
    if (threadIdx.x < 3) g_loss[threadIdx.x] = 0.0;
}

// x [B,784] f32 -> g_x3 [B,2368] bf16 triple + zero pad
__global__ void prep_x_k(const float* __restrict__ x) {
    size_t idx = (size_t)blockIdx.x * blockDim.x + threadIdx.x;
    if (idx >= (size_t)B_ROWS * (D_IN / 4)) return;
    size_t m = idx / (D_IN / 4);
    int c = (int)(idx % (D_IN / 4)) * 4;
    float4 v = *(const float4*)(x + m * D_IN + c);
    bf16 h0, l0, h1, l1, h2, l2, h3, l3;
    split_bf16(v.x, h0, l0); split_bf16(v.y, h1, l1);
    split_bf16(v.z, h2, l2); split_bf16(v.w, h3, l3);
    bf162 hp0; hp0.x = h0; hp0.y = h1;
    bf162 hp1; hp1.x = h2; hp1.y = h3;
    bf162 lp0; lp0.x = l0; lp0.y = l1;
    bf162 lp1; lp1.x = l2; lp1.y = l3;
    bf162* R = (bf162*)(g_x3 + m * K_X3);
    R[c / 2] = hp0; R[c / 2 + 1] = hp1;
    R[(D_IN + c) / 2] = lp0; R[(D_IN + c) / 2 + 1] = lp1;
    R[(2 * D_IN + c) / 2] = hp0; R[(2 * D_IN + c) / 2 + 1] = hp1;
    if (c == 0) {  // zero the 16-col pad
        for (int t = 0; t < 8; t++) {
            bf162 z; z.x = __float2bfloat16(0.f); z.y = z.x;
            R[(3 * D_IN) / 2 + t] = z;
        }
    }
}

// We1 [784,512] -> g_We1b [512, 2368] rows [Wh|Wh|Wl|0]
__global__ void prep_we1_k(const float* __restrict__ We1) {
    int idx = blockIdx.x * blockDim.x + threadIdx.x;
    if (idx < D_HID * D_IN) {
        int n = idx / D_IN, k = idx % D_IN;
        bf16 hi, lo; split_bf16(We1[(size_t)k * D_HID + n], hi, lo);
        bf16* R = g_We1b + (size_t)n * K_X3;
        R[k] = hi; R[D_IN + k] = hi; R[2 * D_IN + k] = lo;
        if (k < 16) R[2352 + k] = __float2bfloat16(0.f);
    }
}
// We2 [512,256] -> g_We2b [256,1536] rows [Wh|Wh|Wl]
__global__ void prep_we2_k(const float* __restrict__ We2) {
    int idx = blockIdx.x * blockDim.x + threadIdx.x;
    if (idx < D_LAT * D_HID) {
        int n = idx / D_HID, k = idx % D_HID;
        bf16 hi, lo; split_bf16(We2[(size_t)k * D_LAT + n], hi, lo);
        bf16* R = g_We2b + (size_t)n * K_H3;
        R[k] = hi; R[D_HID + k] = hi; R[2 * D_HID + k] = lo;
    }
}
// codebooks -> cnorm + cb3 [256,768] rows [ch|ch|cl]
__global__ void prep_cb_k(const float* __restrict__ cb0,
                          const float* __restrict__ cb1) {
    int c = blockIdx.x;
    const float* cb = c ? cb1 : cb0;
    int n = threadIdx.x;
    bf16* R = g_cb3 + ((size_t)c * N_CODES + n) * K_E3;
    float s = 0.f;
    for (int k = 0; k < D_LAT; k++) {
        float v = cb[(size_t)n * D_LAT + k];
        s = fmaf(v, v, s);
        bf16 hi, lo; split_bf16(v, hi, lo);
        R[k] = hi; R[D_LAT + k] = hi; R[2 * D_LAT + k] = lo;
    }
    g_cnorm[c * N_CODES + n] = s;
}
// Wd1 [256,512] -> g_W1b [512,768]
__global__ void prep_wd1_k(const float* __restrict__ Wd1) {
    int idx = blockIdx.x * blockDim.x + threadIdx.x;
    if (idx < D_HID * D_LAT) {
        int n = idx / D_LAT, k = idx % D_LAT;
        bf16 hi, lo; split_bf16(Wd1[(size_t)k * D_HID + n], hi, lo);
        bf16* R = g_W1b + (size_t)n * K_E3;
        R[k] = hi; R[D_LAT + k] = hi; R[2 * D_LAT + k] = lo;
    }
}
// Wd2 [512,784] -> g_W2b [896,1536] (zeros n>=784)
__global__ void prep_wd2_k(const float* __restrict__ Wd2) {
    int idx = blockIdx.x * blockDim.x + threadIdx.x;
    if (idx < N_PAD * D_HID) {
        int n = idx / D_HID, k = idx % D_HID;
        bf16 hi, lo;
        if (n < D_IN) split_bf16(Wd2[(size_t)k * D_IN + n], hi, lo);
        else { hi = __float2bfloat16(0.f); lo = hi; }
        bf16* R = g_W2b + (size_t)n * K_H3;
        R[k] = hi; R[D_HID + k] = hi; R[2 * D_HID + k] = lo;
    }
}

__global__ void finalize_k(float* __restrict__ out_loss) {
    double loss = g_loss[0] / ((double)B_ROWS * (double)D_IN)
                + 0.25 * ((g_loss[1] + g_loss[2]) / ((double)B_ROWS * (double)D_LAT));
    out_loss[0] = (float)loss;
}

// ---------------- universal split-bf16 HMMA GEMM ----------------------------
// C[M,N] = A[M,K] @ BT[N,K]^T  (bf16, K pre-extended 3x, fp32 accum)
// EPI 0: plain f32 store (scores)
// EPI 1: +bias, relu -> triple bf16 [h|l|h], row stride ldc, seg len Nout
// EPI 2: +bias, tanh -> f32 store + sum((v-X)^2) into lossAcc
// EPI 3: +bias -> f32 store (Cout, stride Nout) AND triple bf16 (Cout2, 3*Nout)
#define HM 128
#define HN 128
#define HK 64
#define PITCH 144
#define TILE_B (HM * PITCH)            // 18432
#define SMEM_HMMA (4 * TILE_B)         // 73728

template <int EPI>
__global__ void __launch_bounds__(256)
hmma_k(const bf16* __restrict__ A, const bf16* __restrict__ BT,
       const float* __restrict__ bias, void* __restrict__ Cout,
       void* __restrict__ Cout2, int K, int Nout, int ldc,
       const float* __restrict__ X, double* __restrict__ lossAcc) {
    extern __shared__ char sm[];
    __shared__ float red[8];

    const int tid = threadIdx.x;
    const int wid = tid >> 5, lane = tid & 31;
    const int warp_m = wid >> 1, warp_n = wid & 1;
    const int m0 = blockIdx.y * HM, n0 = blockIdx.x * HN;
    const int NC = K / HK;

    const uint32_t smA = smem_u32(sm);
    const uint32_t smB = smA + 2 * TILE_B;

    // cp.async mapping: 4x16B per thread per tile; row = (tid>>3)+32j, seg const
    const int lrow = tid >> 3;           // 0..31
    const int lseg = (tid & 7) << 4;     // 0,16,...,112
    const size_t rs = (size_t)K * 2;
    const char* Ag = (const char*)(A + (size_t)m0 * K) + (size_t)lrow * rs + lseg;
    const char* Bg = (const char*)(BT + (size_t)n0 * K) + (size_t)lrow * rs + lseg;
    const uint32_t stoff = lrow * PITCH + lseg;

    // ldmatrix lane addressing
    const int a_row = (lane & 15);
    const int a_kb16 = (lane >> 4) << 4;              // byte: 0 or 16
    const int b_row = (lane & 7) + ((lane >> 4) << 3);
    const int b_kb16 = ((lane >> 3) & 1) << 4;

    uint32_t a_sm[2], b_sm[2];
#pragma unroll
    for (int s = 0; s < 2; s++) {
        a_sm[s] = smA + s * TILE_B + (warp_m * 32 + a_row) * PITCH + a_kb16;
        b_sm[s] = smB + s * TILE_B + (warp_n * 64 + b_row) * PITCH + b_kb16;
    }

    float acc[2][8][4];
#pragma unroll
    for (int i = 0; i < 2; i++)
#pragma unroll
        for (int j = 0; j < 8; j++)
#pragma unroll
            for (int t = 0; t < 4; t++) acc[i][j][t] = 0.f;

    // prefetch chunk 0
    {
        uint32_t ast = smA + stoff, bst = smB + stoff;
#pragma unroll
        for (int j = 0; j < 4; j++) {
            CP16(ast + j * 32 * PITCH, Ag + (size_t)j * 32 * rs);
            CP16(bst + j * 32 * PITCH, Bg + (size_t)j * 32 * rs);
        }
        CP_COMMIT();
    }

    for (int i = 0; i < NC; i++) {
        if (i + 1 < NC) {
            int buf = (i + 1) & 1;
            size_t koff = (size_t)(i + 1) * (HK * 2);
            uint32_t ast = smA + buf * TILE_B + stoff;
            uint32_t bst = smB + buf * TILE_B + stoff;
#pragma unroll
            for (int j = 0; j < 4; j++) {
                CP16(ast + j * 32 * PITCH, Ag + (size_t)j * 32 * rs + koff);
                CP16(bst + j * 32 * PITCH, Bg + (size_t)j * 32 * rs + koff);
            }
            CP_COMMIT();
            CP_WAIT(1);
        } else {
            CP_WAIT(0);
        }
        __syncthreads();

        int buf = i & 1;
#pragma unroll
        for (int ks = 0; ks < 4; ks++) {
            uint32_t af[2][4];
#pragma unroll
            for (int im = 0; im < 2; im++)
                ldsm_x4(af[im], a_sm[buf] + im * 16 * PITCH + ks * 32);
            uint32_t bfr[4][4];
#pragma unroll
            for (int jp = 0; jp < 4; jp++)
                ldsm_x4(bfr[jp], b_sm[buf] + jp * 16 * PITCH + ks * 32);
#pragma unroll
            for (int im = 0; im < 2; im++)
#pragma unroll
                for (int jn = 0; jn < 8; jn++)
                    mma_bf16(acc[im][jn], af[im], &bfr[jn >> 1][(jn & 1) * 2]);
        }
        __syncthreads();
    }

    // ---- epilogue
    const int qr = lane >> 2, qc = (lane & 3) * 2;
    float lsum = 0.f;
#pragma unroll
    for (int im = 0; im < 2; im++) {
#pragma unroll
        for (int h = 0; h < 2; h++) {
            int gm = m0 + warp_m * 32 + im * 16 + qr + h * 8;
#pragma unroll
            for (int jn = 0; jn < 8; jn++) {
                int gn = n0 + warp_n * 64 + jn * 8 + qc;
                float v0 = acc[im][jn][h * 2 + 0];
                float v1 = acc[im][jn][h * 2 + 1];
                if (EPI == 0) {
                    *(float2*)((float*)Cout + (size_t)gm * Nout + gn) =
                        make_float2(v0, v1);
                } else if (EPI == 1) {
                    v0 = fmaxf(v0 + __ldg(&bias[gn]),     0.f);
                    v1 = fmaxf(v1 + __ldg(&bias[gn + 1]), 0.f);
                    bf16 h0, l0, h1, l1;
                    split_bf16(v0, h0, l0); split_bf16(v1, h1, l1);
                    bf16* Cr = (bf16*)Cout + (size_t)gm * ldc;
                    bf162 hp; hp.x = h0; hp.y = h1;
                    bf162 lp; lp.x = l0; lp.y = l1;
                    *(bf162*)(Cr + gn)            = hp;
                    *(bf162*)(Cr + Nout + gn)     = lp;
                    *(bf162*)(Cr + 2 * Nout + gn) = hp;
                } else if (EPI == 2) {
                    if (gn < Nout) {
                        v0 = tanhf(v0 + __ldg(&bias[gn]));
                        v1 = tanhf(v1 + __ldg(&bias[gn + 1]));
                        const float* Xr = X + (size_t)gm * Nout + gn;
                        float d0 = v0 - Xr[0], d1 = v1 - Xr[1];
                        lsum = fmaf(d0, d0, fmaf(d1, d1, lsum));
                        *(float2*)((float*)Cout + (size_t)gm * Nout + gn) =
                            make_float2(v0, v1);
                    }
                } else {  // EPI == 3
                    v0 += __ldg(&bias[gn]);
                    v1 += __ldg(&bias[gn + 1]);
                    *(float2*)((float*)Cout + (size_t)gm * Nout + gn) =
                        make_float2(v0, v1);
                    bf16 h0, l0, h1, l1;
                    split_bf16(v0, h0, l0); split_bf16(v1, h1, l1);
                    bf16* Cr = (bf16*)Cout2 + (size_t)gm * (3 * Nout);
                    bf162 hp; hp.x = h0; hp.y = h1;
                    bf162 lp; lp.x = l0; lp.y = l1;
                    *(bf162*)(Cr + gn)            = hp;
                    *(bf162*)(Cr + Nout + gn)     = lp;
                    *(bf162*)(Cr + 2 * Nout + gn) = hp;
                }
            }
        }
    }

    if (EPI == 2) {
#pragma unroll
        for (int off = 16; off > 0; off >>= 1)
            lsum += __shfl_down_sync(0xffffffffu, lsum, off);
        if (lane == 0) red[wid] = lsum;
        __syncthreads();
        if (tid == 0) {
            float s = 0.f;
#pragma unroll
            for (int i = 0; i < 8; i++) s += red[i];
            atomicAdd(lossAcc, (double)s);
        }
    }
}

// ---------------- VQ: argmin + gather + residual + split-triple out --------
// tri_mode 0: tri <- split(residual_new) ; 1: tri <- split(enc - residual_new)
__global__ void __launch_bounds__(256)
vq_pass_k(const float* __restrict__ S, const float* __restrict__ cb,
          const float* __restrict__ cnorm,
          const float* __restrict__ rin, float* __restrict__ rout,
          const float* __restrict__ enc, bf16* __restrict__ tri, int tri_mode,
          float* __restrict__ idx_out, int pass, double* __restrict__ commitAcc) {
    int warp = threadIdx.x >> 5, lane = threadIdx.x & 31;
    __shared__ float wsum[8];
    float csum = 0.f;

    for (int r = 0; r < 8; r++) {
        int m = blockIdx.x * 64 + warp * 8 + r;
        const float* Sr = S + (size_t)m * N_CODES;

        float best = 3.4e38f;
        int bi = 0x7fffffff;
#pragma unroll
        for (int t = 0; t < 8; t++) {
            int j = t * 32 + lane;
            float dv = fmaf(-2.f, Sr[j], cnorm[j]);
            if (dv < best) { best = dv; bi = j; }
        }
#pragma unroll
        for (int off = 16; off > 0; off >>= 1) {
            float ov = __shfl_down_sync(0xffffffffu, best, off);
            int   oi = __shfl_down_sync(0xffffffffu, bi, off);
            if (ov < best || (ov == best && oi < bi)) { best = ov; bi = oi; }
        }
        bi = __shfl_sync(0xffffffffu, bi, 0);
        if (lane == 0) idx_out[(size_t)m * 2 + pass] = (float)bi;

        const float4* rin4 = (const float4*)(rin + (size_t)m * D_LAT);
        float4*       rout4 = (float4*)(rout + (size_t)m * D_LAT);
        const float4* cb4 = (const float4*)(cb + (size_t)bi * D_LAT);
#pragma unroll
        for (int t = 0; t < 2; t++) {
            int e = t * 32 + lane;
            float4 rv = rin4[e], cv = cb4[e];
            float4 o;
            o.x = rv.x - cv.x; o.y = rv.y - cv.y;
            o.z = rv.z - cv.z; o.w = rv.w - cv.w;
            rout4[e] = o;
            csum += o.x * o.x + o.y * o.y + o.z * o.z + o.w * o.w;

            float q0, q1, q2, q3v;
            if (tri_mode) {
                const float4* enc4 = (const float4*)(enc + (size_t)m * D_LAT);
                float4 ev = enc4[e];
                q0 = ev.x - o.x; q1 = ev.y - o.y;
                q2 = ev.z - o.z; q3v = ev.w - o.w;
            } else {
                q0 = o.x; q1 = o.y; q2 = o.z; q3v = o.w;
            }
            bf16 h0, l0, h1, l1, h2, l2, h3, l3;
            split_bf16(q0, h0, l0); split_bf16(q1, h1, l1);
            split_bf16(q2, h2, l2); split_bf16(q3v, h3, l3);
            bf162* Qr = (bf162*)(tri + (size_t)m * K_E3);
            bf162 hp0; hp0.x = h0; hp0.y = h1;
            bf162 hp1; hp1.x = h2; hp1.y = h3;
            bf162 lp0; lp0.x = l0; lp0.y = l1;
            bf162 lp1; lp1.x = l2; lp1.y = l3;
            Qr[e * 2 + 0]       = hp0;  Qr[e * 2 + 1]       = hp1;
            Qr[128 + e * 2 + 0] = lp0;  Qr[128 + e * 2 + 1] = lp1;
            Qr[256 + e * 2 + 0] = hp0;  Qr[256 + e * 2 + 1] = hp1;
        }
    }

#pragma unroll
    for (int off = 16; off > 0; off >>= 1)
        csum += __shfl_down_sync(0xffffffffu, csum, off);
    if (lane == 0) wsum[warp] = csum;
    __syncthreads();
    if (threadIdx.x == 0) {
        float s = 0.f;
        for (int i = 0; i < 8; i++) s += wsum[i];
        atomicAdd(commitAcc, (double)s);
    }
}

// ---------------- launch ----------------------------------------------------
extern "C" void kernel_launch(void* const* d_in, const int* in_sizes, int n_in,
                              void* d_out, int out_size) {
    const float* x   = (const float*)d_in[0];
    const float* We1 = (const float*)d_in[1];
    const float* be1 = (const float*)d_in[2];
    const float* We2 = (const float*)d_in[3];
    const float* be2 = (const float*)d_in[4];
    const float* cb0 = (const float*)d_in[5];
    const float* cb1 = (const float*)d_in[6];
    const float* Wd1 = (const float*)d_in[7];
    const float* bd1 = (const float*)d_in[8];
    const float* Wd2 = (const float*)d_in[9];
    const float* bd2 = (const float*)d_in[10];

    float* out       = (float*)d_out;
    float* out_recon = out;
    float* out_idx   = out + (size_t)B_ROWS * D_IN;
    float* out_loss  = out + (size_t)B_ROWS * D_IN + (size_t)B_ROWS * 2;

    bf16 *px3, *ph3, *pe3, *pq3, *pd3, *pWe1b, *pWe2b, *pcb3, *pW1b, *pW2b;
    float *penc, *pr, *pS, *pcn;
    double* pl;
    cudaGetSymbolAddress((void**)&px3,   g_x3);
    cudaGetSymbolAddress((void**)&ph3,   g_h3);
    cudaGetSymbolAddress((void**)&penc,  g_enc);
    cudaGetSymbolAddress((void**)&pe3,   g_e3);
    cudaGetSymbolAddress((void**)&pr,    g_r);
    cudaGetSymbolAddress((void**)&pS,    g_S);
    cudaGetSymbolAddress((void**)&pq3,   g_q3);
    cudaGetSymbolAddress((void**)&pd3,   g_d3);
    cudaGetSymbolAddress((void**)&pWe1b, g_We1b);
    cudaGetSymbolAddress((void**)&pWe2b, g_We2b);
    cudaGetSymbolAddress((void**)&pcb3,  g_cb3);
    cudaGetSymbolAddress((void**)&pW1b,  g_W1b);
    cudaGetSymbolAddress((void**)&pW2b,  g_W2b);
    cudaGetSymbolAddress((void**)&pcn,   g_cnorm);
    cudaGetSymbolAddress((void**)&pl,    g_loss);

    cudaFuncSetAttribute(hmma_k<0>, cudaFuncAttributeMaxDynamicSharedMemorySize, SMEM_HMMA);
    cudaFuncSetAttribute(hmma_k<1>, cudaFuncAttributeMaxDynamicSharedMemorySize, SMEM_HMMA);
    cudaFuncSetAttribute(hmma_k<2>, cudaFuncAttributeMaxDynamicSharedMemorySize, SMEM_HMMA);
    cudaFuncSetAttribute(hmma_k<3>, cudaFuncAttributeMaxDynamicSharedMemorySize, SMEM_HMMA);

    dim3 blk(256);

    init_k<<<1, 32>>>();
    prep_x_k<<<(int)(((size_t)B_ROWS * (D_IN / 4) + 255) / 256), 256>>>(x);
    prep_we1_k<<<(D_HID * D_IN + 255) / 256, 256>>>(We1);
    prep_we2_k<<<(D_LAT * D_HID + 255) / 256, 256>>>(We2);
    prep_cb_k<<<2, 256>>>(cb0, cb1);
    prep_wd1_k<<<(D_HID * D_LAT + 255) / 256, 256>>>(Wd1);
    prep_wd2_k<<<(N_PAD * D_HID + 255) / 256, 256>>>(Wd2);

    // encoder: h3 = relu(x@We1+be1) split ; enc = h@We2+be2 (f32 + split)
    hmma_k<1><<<dim3(D_HID / HN, B_ROWS / HM), blk, SMEM_HMMA>>>(
        px3, pWe1b, be1, ph3, nullptr, K_X3, D_HID, K_H3, nullptr, nullptr);
    hmma_k<3><<<dim3(D_LAT / HN, B_ROWS / HM), blk, SMEM_HMMA>>>(
        ph3, pWe2b, be2, penc, pe3, K_H3, D_LAT, 0, nullptr, nullptr);

    // VQ quantizer 0: scores via HMMA, then argmin/residual (r3 -> reuse g_e3)
    hmma_k<0><<<dim3(N_CODES / HN, B_ROWS / HM), blk, SMEM_HMMA>>>(
        pe3, pcb3, nullptr, pS, nullptr, K_E3, N_CODES, 0, nullptr, nullptr);
    vq_pass_k<<<B_ROWS / 64, 256>>>(pS, cb0, pcn, penc, pr,
                                    nullptr, pe3, 0, out_idx, 0, pl + 1);
    // VQ quantizer 1
    hmma_k<0><<<dim3(N_CODES / HN, B_ROWS / HM), blk, SMEM_HMMA>>>(
        pe3, pcb3 + (size_t)N_CODES * K_E3, nullptr, pS, nullptr,
        K_E3, N_CODES, 0, nullptr, nullptr);
    vq_pass_k<<<B_ROWS / 64, 256>>>(pS, cb1, pcn + N_CODES, pr, pr,
                                    penc, pq3, 1, out_idx, 1, pl + 2);

    // decoder
    hmma_k<1><<<dim3(D_HID / HN, B_ROWS / HM), blk, SMEM_HMMA>>>(
        pq3, pW1b, bd1, pd3, nullptr, K_E3, D_HID, K_H3, nullptr, nullptr);
    hmma_k<2><<<dim3(N_PAD / HN, B_ROWS / HM), blk, SMEM_HMMA>>>(
        pd3, pW2b, bd2, out_recon, nullptr, K_H3, D_IN, 0, x, pl + 0);

    finalize_k<<<1, 1>>>(out_loss);
}

// round 6
// speedup vs baseline: 2.0148x; 1.0041x over previous
#include <cuda_runtime.h>
#include <cuda_bf16.h>
#include <cstdint>
#include <math.h>

#define B_ROWS 65536
#define D_IN   784
#define D_HID  512
#define D_LAT  256
#define N_CODES 256
#define N_PAD  896            // dec2 N padded to 7*128
#define L_X    832            // D_IN padded to 13*64
#define KA_X   (2 * L_X)      // 1664 : GEMM1 A row ([xh|xl])
#define KB_X   (3 * L_X)      // 2496 : GEMM1 B row ([Wh|Wh|Wl])
#define KA_H   (2 * D_HID)    // 1024
#define KB_H   (3 * D_HID)    // 1536
#define KA_E   (2 * D_LAT)    // 512
#define KB_E   (3 * D_LAT)    // 768

typedef __nv_bfloat16 bf16;
typedef __nv_bfloat162 bf162;

// ---------------- scratch (device globals; no allocation allowed) ----------
__device__ bf16 g_x3 [(size_t)B_ROWS * KA_X];   // [xh|xl]
__device__ bf16 g_h3 [(size_t)B_ROWS * KA_H];   // [hh|hl]
__device__ float g_enc[(size_t)B_ROWS * D_LAT];
__device__ bf16 g_e3 [(size_t)B_ROWS * KA_E];   // [eh|el], reused for r pairs
__device__ float g_r  [(size_t)B_ROWS * D_LAT];
__device__ float2 g_Sp[(size_t)B_ROWS * 2];     // per-128-block (dv, idx)
__device__ bf16 g_q3 [(size_t)B_ROWS * KA_E];   // [qh|ql]
__device__ bf16 g_d3 [(size_t)B_ROWS * KA_H];   // [dh|dl]
__device__ bf16 g_We1b[(size_t)D_HID * KB_X];
__device__ bf16 g_We2b[(size_t)D_LAT * KB_H];
__device__ bf16 g_cb3 [2 * N_CODES * KB_E];
__device__ bf16 g_W1b [(size_t)D_HID * KB_E];
__device__ bf16 g_W2b [(size_t)N_PAD * KB_H];
__device__ float g_cnorm[2 * N_CODES];
__device__ double g_loss[3];                    // recon_sum, commit0, commit1

// ====================== PTX helpers ========================================
__device__ __forceinline__ uint32_t smem_u32(const void* p) {
    uint32_t a;
    asm("{ .reg .u64 t; cvta.to.shared.u64 t, %1; cvt.u32.u64 %0, t; }"
        : "=r"(a) : "l"(p));
    return a;
}
#define CP16(dst, src) \
    asm volatile("cp.async.cg.shared.global [%0], [%1], 16;" :: "r"(dst), "l"(src) : "memory")
#define CP_COMMIT() asm volatile("cp.async.commit_group;" ::: "memory")
#define CP_WAIT(n)  asm volatile("cp.async.wait_group %0;" :: "n"(n) : "memory")

__device__ __forceinline__ void ldsm_x4(uint32_t* r, uint32_t addr) {
    asm volatile("ldmatrix.sync.aligned.m8n8.x4.shared.b16 {%0,%1,%2,%3}, [%4];"
        : "=r"(r[0]), "=r"(r[1]), "=r"(r[2]), "=r"(r[3]) : "r"(addr));
}
__device__ __forceinline__ void mma_bf16(float* c, const uint32_t* a, const uint32_t* b) {
    asm volatile("mma.sync.aligned.m16n8k16.row.col.f32.bf16.bf16.f32 "
        "{%0,%1,%2,%3}, {%4,%5,%6,%7}, {%8,%9}, {%0,%1,%2,%3};"
        : "+f"(c[0]), "+f"(c[1]), "+f"(c[2]), "+f"(c[3])
        : "r"(a[0]), "r"(a[1]), "r"(a[2]), "r"(a[3]), "r"(b[0]), "r"(b[1]));
}
__device__ __forceinline__ void split_bf16(float v, bf16& hi, bf16& lo) {
    hi = __float2bfloat16_rn(v);
    lo = __float2bfloat16_rn(v - __bfloat162float(hi));
}

// ---------------- prep kernels ---------------------------------------------
__global__ void init_k() {
    if (threadIdx.x < 3) g_loss[threadIdx.x] = 0.0;
}

// x [B,784] f32 -> g_x3 [B,1664] = [xh(832)|xl(832)] with zero pad
__global__ void prep_x_k(const float* __restrict__ x) {
    size_t idx = (size_t)blockIdx.x * blockDim.x + threadIdx.x;
    if (idx >= (size_t)B_ROWS * (L_X / 4)) return;
    size_t m = idx / (L_X / 4);
    int c = (int)(idx % (L_X / 4)) * 4;
    bf162 hp0, hp1, lp0, lp1;
    if (c < D_IN) {
        float4 v = *(const float4*)(x + m * D_IN + c);
        bf16 h0, l0, h1, l1, h2, l2, h3, l3;
        split_bf16(v.x, h0, l0); split_bf16(v.y, h1, l1);
        split_bf16(v.z, h2, l2); split_bf16(v.w, h3, l3);
        hp0.x = h0; hp0.y = h1; hp1.x = h2; hp1.y = h3;
        lp0.x = l0; lp0.y = l1; lp1.x = l2; lp1.y = l3;
    } else {
        bf16 z = __float2bfloat16(0.f);
        hp0.x = z; hp0.y = z; hp1 = hp0; lp0 = hp0; lp1 = hp0;
    }
    bf162* R = (bf162*)(g_x3 + m * KA_X);
    R[c / 2] = hp0;             R[c / 2 + 1] = hp1;
    R[(L_X + c) / 2] = lp0;     R[(L_X + c) / 2 + 1] = lp1;
}

// We1 [784,512] -> g_We1b [512, 2496] rows [Wh|Wh|Wl] (zero pad k>=784)
__global__ void prep_we1_k(const float* __restrict__ We1) {
    int idx = blockIdx.x * blockDim.x + threadIdx.x;
    if (idx < D_HID * L_X) {
        int n = idx / L_X, k = idx % L_X;
        float v = (k < D_IN) ? We1[(size_t)k * D_HID + n] : 0.f;
        bf16 hi, lo; split_bf16(v, hi, lo);
        bf16* R = g_We1b + (size_t)n * KB_X;
        R[k] = hi; R[L_X + k] = hi; R[2 * L_X + k] = lo;
    }
}
__global__ void prep_we2_k(const float* __restrict__ We2) {
    int idx = blockIdx.x * blockDim.x + threadIdx.x;
    if (idx < D_LAT * D_HID) {
        int n = idx / D_HID, k = idx % D_HID;
        bf16 hi, lo; split_bf16(We2[(size_t)k * D_LAT + n], hi, lo);
        bf16* R = g_We2b + (size_t)n * KB_H;
        R[k] = hi; R[D_HID + k] = hi; R[2 * D_HID + k] = lo;
    }
}
__global__ void prep_cb_k(const float* __restrict__ cb0,
                          const float* __restrict__ cb1) {
    int c = blockIdx.x;
    const float* cb = c ? cb1 : cb0;
    int n = threadIdx.x;
    bf16* R = g_cb3 + ((size_t)c * N_CODES + n) * KB_E;
    float s = 0.f;
    for (int k = 0; k < D_LAT; k++) {
        float v = cb[(size_t)n * D_LAT + k];
        s = fmaf(v, v, s);
        bf16 hi, lo; split_bf16(v, hi, lo);
        R[k] = hi; R[D_LAT + k] = hi; R[2 * D_LAT + k] = lo;
    }
    g_cnorm[c * N_CODES + n] = s;
}
__global__ void prep_wd1_k(const float* __restrict__ Wd1) {
    int idx = blockIdx.x * blockDim.x + threadIdx.x;
    if (idx < D_HID * D_LAT) {
        int n = idx / D_LAT, k = idx % D_LAT;
        bf16 hi, lo; split_bf16(Wd1[(size_t)k * D_HID + n], hi, lo);
        bf16* R = g_W1b + (size_t)n * KB_E;
        R[k] = hi; R[D_LAT + k] = hi; R[2 * D_LAT + k] = lo;
    }
}
__global__ void prep_wd2_k(const float* __restrict__ Wd2) {
    int idx = blockIdx.x * blockDim.x + threadIdx.x;
    if (idx < N_PAD * D_HID) {
        int n = idx / D_HID, k = idx % D_HID;
        bf16 hi, lo;
        if (n < D_IN) split_bf16(Wd2[(size_t)k * D_IN + n], hi, lo);
        else { hi = __float2bfloat16(0.f); lo = hi; }
        bf16* R = g_W2b + (size_t)n * KB_H;
        R[k] = hi; R[D_HID + k] = hi; R[2 * D_HID + k] = lo;
    }
}

__global__ void finalize_k(float* __restrict__ out_loss) {
    double loss = g_loss[0] / ((double)B_ROWS * (double)D_IN)
                + 0.25 * ((g_loss[1] + g_loss[2]) / ((double)B_ROWS * (double)D_LAT));
    out_loss[0] = (float)loss;
}

// ---------------- universal split-bf16 HMMA GEMM ----------------------------
// C[M,N] = A[M,kA] @ BT[N,K]^T with piecewise K-remap on A:
//   chunks [0, 2L): A linear ([Ah|Al]) vs B [Bh|Bh]
//   chunks [2L,3L): A wraps to Ah      vs B [Bl]
// EPI 1: +bias, relu -> split pair [h|l] bf16, row stride ldc
// EPI 2: +bias, tanh -> f32 store + sum((v-X)^2) into lossAcc
// EPI 3: +bias -> f32 (Cout, stride Nout) AND split pair (Cout2, 2*Nout)
// EPI 4: dv = aux[gn] - 2*acc; per-row argmin over CTA's 128 cols ->
//        float2(dv, idx) at Cout[m * gridDim.x + blockIdx.x]
#define HM 128
#define HN 128
#define HK 64
#define PITCH 144
#define TILE_B (HM * PITCH)            // 18432
#define SMEM_HMMA (4 * TILE_B)         // 73728

template <int EPI>
__global__ void __launch_bounds__(256)
hmma_k(const bf16* __restrict__ A, const bf16* __restrict__ BT,
       const float* __restrict__ aux, void* __restrict__ Cout,
       void* __restrict__ Cout2, int kA, int K, int Nout, int ldc,
       const float* __restrict__ X, double* __restrict__ lossAcc) {
    extern __shared__ char sm[];
    __shared__ float red[8];

    const int tid = threadIdx.x;
    const int wid = tid >> 5, lane = tid & 31;
    const int warp_m = wid >> 1, warp_n = wid & 1;
    const int m0 = blockIdx.y * HM, n0 = blockIdx.x * HN;
    const int NC = K / HK;

    const uint32_t smA = smem_u32(sm);
    const uint32_t smB = smA + 2 * TILE_B;

    const int lrow = tid >> 3;           // 0..31
    const int lseg = (tid & 7) << 4;     // 0,16,...,112
    const size_t rsA = (size_t)kA * 2;
    const size_t rsB = (size_t)K * 2;
    const char* Ag = (const char*)(A + (size_t)m0 * kA) + (size_t)lrow * rsA + lseg;
    const char* Bg = (const char*)(BT + (size_t)n0 * K) + (size_t)lrow * rsB + lseg;
    const uint32_t stoff = lrow * PITCH + lseg;
    const int kAb = kA * 2;  // bytes

    const int a_row = (lane & 15);
    const int a_kb16 = (lane >> 4) << 4;
    const int b_row = (lane & 7) + ((lane >> 4) << 3);
    const int b_kb16 = ((lane >> 3) & 1) << 4;

    uint32_t a_sm[2], b_sm[2];
#pragma unroll
    for (int s = 0; s < 2; s++) {
        a_sm[s] = smA + s * TILE_B + (warp_m * 32 + a_row) * PITCH + a_kb16;
        b_sm[s] = smB + s * TILE_B + (warp_n * 64 + b_row) * PITCH + b_kb16;
    }

    float acc[2][8][4];
#pragma unroll
    for (int i = 0; i < 2; i++)
#pragma unroll
        for (int j = 0; j < 8; j++)
#pragma unroll
            for (int t = 0; t < 4; t++) acc[i][j][t] = 0.f;

    // prefetch chunk 0 (aOff = 0)
    {
        uint32_t ast = smA + stoff, bst = smB + stoff;
#pragma unroll
        for (int j = 0; j < 4; j++) {
            CP16(ast + j * 32 * PITCH, Ag + (size_t)j * 32 * rsA);
            CP16(bst + j * 32 * PITCH, Bg + (size_t)j * 32 * rsB);
        }
        CP_COMMIT();
    }

    for (int i = 0; i < NC; i++) {
        if (i + 1 < NC) {
            int buf = (i + 1) & 1;
            int koffB = (i + 1) * (HK * 2);
            int koffA = (koffB < kAb) ? koffB : koffB - kAb;
            uint32_t ast = smA + buf * TILE_B + stoff;
            uint32_t bst = smB + buf * TILE_B + stoff;
#pragma unroll
            for (int j = 0; j < 4; j++) {
                CP16(ast + j * 32 * PITCH, Ag + (size_t)j * 32 * rsA + koffA);
                CP16(bst + j * 32 * PITCH, Bg + (size_t)j * 32 * rsB + koffB);
            }
            CP_COMMIT();
            CP_WAIT(1);
        } else {
            CP_WAIT(0);
        }
        __syncthreads();

        int buf = i & 1;
#pragma unroll
        for (int ks = 0; ks < 4; ks++) {
            uint32_t af[2][4];
#pragma unroll
            for (int im = 0; im < 2; im++)
                ldsm_x4(af[im], a_sm[buf] + im * 16 * PITCH + ks * 32);
            uint32_t bfr[4][4];
#pragma unroll
            for (int jp = 0; jp < 4; jp++)
                ldsm_x4(bfr[jp], b_sm[buf] + jp * 16 * PITCH + ks * 32);
#pragma unroll
            for (int im = 0; im < 2; im++)
#pragma unroll
                for (int jn = 0; jn < 8; jn++)
                    mma_bf16(acc[im][jn], af[im], &bfr[jn >> 1][(jn & 1) * 2]);
        }
        __syncthreads();
    }

    // ---- epilogue
    const int qr = lane >> 2, qc = (lane & 3) * 2;

    if (EPI == 4) {
        float2* sMin = (float2*)sm;  // [128][2] per-row per-warp_n candidates
        const float* cn = aux;
#pragma unroll
        for (int im = 0; im < 2; im++) {
#pragma unroll
            for (int h = 0; h < 2; h++) {
                int row = warp_m * 32 + im * 16 + h * 8 + qr;
                float bv = 3.4e38f; int bi = 0x7fffffff;
#pragma unroll
                for (int jn = 0; jn < 8; jn++) {
#pragma unroll
                    for (int t = 0; t < 2; t++) {
                        int gn = n0 + warp_n * 64 + jn * 8 + qc + t;
                        float dv = fmaf(-2.f, acc[im][jn][h * 2 + t], __ldg(&cn[gn]));
                        if (dv < bv) { bv = dv; bi = gn; }
                    }
                }
#pragma unroll
                for (int off = 1; off < 4; off <<= 1) {
                    float ov = __shfl_xor_sync(0xffffffffu, bv, off);
                    int   oi = __shfl_xor_sync(0xffffffffu, bi, off);
                    if (ov < bv || (ov == bv && oi < bi)) { bv = ov; bi = oi; }
                }
                if ((lane & 3) == 0)
                    sMin[row * 2 + warp_n] = make_float2(bv, (float)bi);
            }
        }
        __syncthreads();
        if (tid < HM) {
            float2 c0 = sMin[tid * 2 + 0], c1 = sMin[tid * 2 + 1];
            float2 b = (c1.x < c0.x || (c1.x == c0.x && c1.y < c0.y)) ? c1 : c0;
            ((float2*)Cout)[(size_t)(m0 + tid) * gridDim.x + blockIdx.x] = b;
        }
        return;
    }

    float lsum = 0.f;
#pragma unroll
    for (int im = 0; im < 2; im++) {
#pragma unroll
        for (int h = 0; h < 2; h++) {
            int gm = m0 + warp_m * 32 + im * 16 + qr + h * 8;
#pragma unroll
            for (int jn = 0; jn < 8; jn++) {
                int gn = n0 + warp_n * 64 + jn * 8 + qc;
                float v0 = acc[im][jn][h * 2 + 0];
                float v1 = acc[im][jn][h * 2 + 1];
                if (EPI == 1) {
                    v0 = fmaxf(v0 + __ldg(&aux[gn]),     0.f);
                    v1 = fmaxf(v1 + __ldg(&aux[gn + 1]), 0.f);
                    bf16 h0, l0, h1, l1;
                    split_bf16(v0, h0, l0); split_bf16(v1, h1, l1);
                    bf16* Cr = (bf16*)Cout + (size_t)gm * ldc;
                    bf162 hp; hp.x = h0; hp.y = h1;
                    bf162 lp; lp.x = l0; lp.y = l1;
                    *(bf162*)(Cr + gn)        = hp;
                    *(bf162*)(Cr + Nout + gn) = lp;
                } else if (EPI == 2) {
                    if (gn < Nout) {
                        v0 = tanhf(v0 + __ldg(&aux[gn]));
                        v1 = tanhf(v1 + __ldg(&aux[gn + 1]));
                        const float* Xr = X + (size_t)gm * Nout + gn;
                        float d0 = v0 - Xr[0], d1 = v1 - Xr[1];
                        lsum = fmaf(d0, d0, fmaf(d1, d1, lsum));
                        *(float2*)((float*)Cout + (size_t)gm * Nout + gn) =
                            make_float2(v0, v1);
                    }
                } else {  // EPI == 3
                    v0 += __ldg(&aux[gn]);
                    v1 += __ldg(&aux[gn + 1]);
                    *(float2*)((float*)Cout + (size_t)gm * Nout + gn) =
                        make_float2(v0, v1);
                    bf16 h0, l0, h1, l1;
                    split_bf16(v0, h0, l0); split_bf16(v1, h1, l1);
                    bf16* Cr = (bf16*)Cout2 + (size_t)gm * (2 * Nout);
                    bf162 hp; hp.x = h0; hp.y = h1;
                    bf162 lp; lp.x = l0; lp.y = l1;
                    *(bf162*)(Cr + gn)        = hp;
                    *(bf162*)(Cr + Nout + gn) = lp;
                }
            }
        }
    }

    if (EPI == 2) {
#pragma unroll
        for (int off = 16; off > 0; off >>= 1)
            lsum += __shfl_down_sync(0xffffffffu, lsum, off);
        if (lane == 0) red[wid] = lsum;
        __syncthreads();
        if (tid == 0) {
            float s = 0.f;
#pragma unroll
            for (int i = 0; i < 8; i++) s += red[i];
            atomicAdd(lossAcc, (double)s);
        }
    }
}

// ---------------- VQ: combine partial argmins + gather + residual ----------
// tri_mode 0: tri <- split(residual_new) ; 1: tri <- split(enc - residual_new)
__global__ void __launch_bounds__(256)
vq_pass_k(const float2* __restrict__ Sp, const float* __restrict__ cb,
          const float* __restrict__ rin, float* __restrict__ rout,
          const float* __restrict__ enc, bf16* __restrict__ tri, int tri_mode,
          float* __restrict__ idx_out, int pass, double* __restrict__ commitAcc) {
    int warp = threadIdx.x >> 5, lane = threadIdx.x & 31;
    __shared__ float wsum[8];
    float csum = 0.f;

    for (int r = 0; r < 8; r++) {
        int m = blockIdx.x * 64 + warp * 8 + r;
        float2 c0 = Sp[(size_t)m * 2 + 0];
        float2 c1 = Sp[(size_t)m * 2 + 1];
        float2 b = (c1.x < c0.x || (c1.x == c0.x && c1.y < c0.y)) ? c1 : c0;
        int bi = (int)b.y;
        if (lane == 0) idx_out[(size_t)m * 2 + pass] = (float)bi;

        const float4* rin4 = (const float4*)(rin + (size_t)m * D_LAT);
        float4*       rout4 = (float4*)(rout + (size_t)m * D_LAT);
        const float4* cb4 = (const float4*)(cb + (size_t)bi * D_LAT);
#pragma unroll
        for (int t = 0; t < 2; t++) {
            int e = t * 32 + lane;
            float4 rv = rin4[e], cv = cb4[e];
            float4 o;
            o.x = rv.x - cv.x; o.y = rv.y - cv.y;
            o.z = rv.z - cv.z; o.w = rv.w - cv.w;
            rout4[e] = o;
            csum += o.x * o.x + o.y * o.y + o.z * o.z + o.w * o.w;

            float q0, q1, q2, q3v;
            if (tri_mode) {
                const float4* enc4 = (const float4*)(enc + (size_t)m * D_LAT);
                float4 ev = enc4[e];
                q0 = ev.x - o.x; q1 = ev.y - o.y;
                q2 = ev.z - o.z; q3v = ev.w - o.w;
            } else {
                q0 = o.x; q1 = o.y; q2 = o.z; q3v = o.w;
            }
            bf16 h0, l0, h1, l1, h2, l2, h3, l3;
            split_bf16(q0, h0, l0); split_bf16(q1, h1, l1);
            split_bf16(q2, h2, l2); split_bf16(q3v, h3, l3);
            bf162* Qr = (bf162*)(tri + (size_t)m * KA_E);
            bf162 hp0; hp0.x = h0; hp0.y = h1;
            bf162 hp1; hp1.x = h2; hp1.y = h3;
            bf162 lp0; lp0.x = l0; lp0.y = l1;
            bf162 lp1; lp1.x = l2; lp1.y = l3;
            Qr[e * 2 + 0]       = hp0;  Qr[e * 2 + 1]       = hp1;
            Qr[128 + e * 2 + 0] = lp0;  Qr[128 + e * 2 + 1] = lp1;
        }
    }

#pragma unroll
    for (int off = 16; off > 0; off >>= 1)
        csum += __shfl_down_sync(0xffffffffu, csum, off);
    if (lane == 0) wsum[warp] = csum;
    __syncthreads();
    if (threadIdx.x == 0) {
        float s = 0.f;
        for (int i = 0; i < 8; i++) s += wsum[i];
        atomicAdd(commitAcc, (double)s);
    }
}

// ---------------- launch ----------------------------------------------------
extern "C" void kernel_launch(void* const* d_in, const int* in_sizes, int n_in,
                              void* d_out, int out_size) {
    const float* x   = (const float*)d_in[0];
    const float* We1 = (const float*)d_in[1];
    const float* be1 = (const float*)d_in[2];
    const float* We2 = (const float*)d_in[3];
    const float* be2 = (const float*)d_in[4];
    const float* cb0 = (const float*)d_in[5];
    const float* cb1 = (const float*)d_in[6];
    const float* Wd1 = (const float*)d_in[7];
    const float* bd1 = (const float*)d_in[8];
    const float* Wd2 = (const float*)d_in[9];
    const float* bd2 = (const float*)d_in[10];

    float* out       = (float*)d_out;
    float* out_recon = out;
    float* out_idx   = out + (size_t)B_ROWS * D_IN;
    float* out_loss  = out + (size_t)B_ROWS * D_IN + (size_t)B_ROWS * 2;

    bf16 *px3, *ph3, *pe3, *pq3, *pd3, *pWe1b, *pWe2b, *pcb3, *pW1b, *pW2b;
    float *penc, *pr, *pcn;
    float2* pSp;
    double* pl;
    cudaGetSymbolAddress((void**)&px3,   g_x3);
    cudaGetSymbolAddress((void**)&ph3,   g_h3);
    cudaGetSymbolAddress((void**)&penc,  g_enc);
    cudaGetSymbolAddress((void**)&pe3,   g_e3);
    cudaGetSymbolAddress((void**)&pr,    g_r);
    cudaGetSymbolAddress((void**)&pSp,   g_Sp);
    cudaGetSymbolAddress((void**)&pq3,   g_q3);
    cudaGetSymbolAddress((void**)&pd3,   g_d3);
    cudaGetSymbolAddress((void**)&pWe1b, g_We1b);
    cudaGetSymbolAddress((void**)&pWe2b, g_We2b);
    cudaGetSymbolAddress((void**)&pcb3,  g_cb3);
    cudaGetSymbolAddress((void**)&pW1b,  g_W1b);
    cudaGetSymbolAddress((void**)&pW2b,  g_W2b);
    cudaGetSymbolAddress((void**)&pcn,   g_cnorm);
    cudaGetSymbolAddress((void**)&pl,    g_loss);

    cudaFuncSetAttribute(hmma_k<1>, cudaFuncAttributeMaxDynamicSharedMemorySize, SMEM_HMMA);
    cudaFuncSetAttribute(hmma_k<2>, cudaFuncAttributeMaxDynamicSharedMemorySize, SMEM_HMMA);
    cudaFuncSetAttribute(hmma_k<3>, cudaFuncAttributeMaxDynamicSharedMemorySize, SMEM_HMMA);
    cudaFuncSetAttribute(hmma_k<4>, cudaFuncAttributeMaxDynamicSharedMemorySize, SMEM_HMMA);

    dim3 blk(256);

    init_k<<<1, 32>>>();
    prep_x_k<<<(int)(((size_t)B_ROWS * (L_X / 4) + 255) / 256), 256>>>(x);
    prep_we1_k<<<(D_HID * L_X + 255) / 256, 256>>>(We1);
    prep_we2_k<<<(D_LAT * D_HID + 255) / 256, 256>>>(We2);
    prep_cb_k<<<2, 256>>>(cb0, cb1);
    prep_wd1_k<<<(D_HID * D_LAT + 255) / 256, 256>>>(Wd1);
    prep_wd2_k<<<(N_PAD * D_HID + 255) / 256, 256>>>(Wd2);

    // encoder
    hmma_k<1><<<dim3(D_HID / HN, B_ROWS / HM), blk, SMEM_HMMA>>>(
        px3, pWe1b, be1, ph3, nullptr, KA_X, KB_X, D_HID, KA_H, nullptr, nullptr);
    hmma_k<3><<<dim3(D_LAT / HN, B_ROWS / HM), blk, SMEM_HMMA>>>(
        ph3, pWe2b, be2, penc, pe3, KA_H, KB_H, D_LAT, 0, nullptr, nullptr);

    // VQ quantizer 0 (fused per-block argmin in score GEMM epilogue)
    hmma_k<4><<<dim3(N_CODES / HN, B_ROWS / HM), blk, SMEM_HMMA>>>(
        pe3, pcb3, pcn, pSp, nullptr, KA_E, KB_E, N_CODES, 0, nullptr, nullptr);
    vq_pass_k<<<B_ROWS / 64, 256>>>(pSp, cb0, penc, pr,
                                    nullptr, pe3, 0, out_idx, 0, pl + 1);
    // VQ quantizer 1
    hmma_k<4><<<dim3(N_CODES / HN, B_ROWS / HM), blk, SMEM_HMMA>>>(
        pe3, pcb3 + (size_t)N_CODES * KB_E, pcn + N_CODES, pSp, nullptr,
        KA_E, KB_E, N_CODES, 0, nullptr, nullptr);
    vq_pass_k<<<B_ROWS / 64, 256>>>(pSp, cb1, pr, pr,
                                    penc, pq3, 1, out_idx, 1, pl + 2);

    // decoder
    hmma_k<1><<<dim3(D_HID / HN, B_ROWS / HM), blk, SMEM_HMMA>>>(
        pq3, pW1b, bd1, pd3, nullptr, KA_E, KB_E, D_HID, KA_H, nullptr, nullptr);
    hmma_k<2><<<dim3(N_PAD / HN, B_ROWS / HM), blk, SMEM_HMMA>>>(
        pd3, pW2b, bd2, out_recon, nullptr, KA_H, KB_H, D_IN, 0, x, pl + 0);

    finalize_k<<<1, 1>>>(out_loss);
}

// round 7
// speedup vs baseline: 2.0415x; 1.0133x over previous
#include <cuda_runtime.h>
#include <cuda_bf16.h>
#include <cstdint>
#include <math.h>

#define B_ROWS 65536
#define D_IN   784
#define D_HID  512
#define D_LAT  256
#define N_CODES 256
#define N_PAD  896            // dec2 N padded to 7*128
#define L_X    832            // D_IN padded to 13*64
#define KA_X   (2 * L_X)      // 1664 : GEMM1 A row ([xh|xl])
#define KB_X   (3 * L_X)      // 2496 : GEMM1 B row ([Wh|Wh|Wl])
#define KA_H   (2 * D_HID)    // 1024
#define KB_H   (3 * D_HID)    // 1536
#define KA_E   (2 * D_LAT)    // 512
#define KB_E   (3 * D_LAT)    // 768

typedef __nv_bfloat16 bf16;
typedef __nv_bfloat162 bf162;

// ---------------- scratch (device globals; no allocation allowed) ----------
__device__ bf16 g_x3 [(size_t)B_ROWS * KA_X];   // [xh|xl]
__device__ bf16 g_h3 [(size_t)B_ROWS * KA_H];   // [hh|hl]
__device__ float g_enc[(size_t)B_ROWS * D_LAT];
__device__ bf16 g_e3 [(size_t)B_ROWS * KA_E];   // [eh|el], reused for r pairs
__device__ float g_r  [(size_t)B_ROWS * D_LAT];
__device__ float2 g_Sp[(size_t)B_ROWS * 2];     // per-128-block (dv, idx)
__device__ bf16 g_q3 [(size_t)B_ROWS * KA_E];   // [qh|ql]
__device__ bf16 g_d3 [(size_t)B_ROWS * KA_H];   // [dh|dl]
__device__ bf16 g_We1b[(size_t)D_HID * KB_X];
__device__ bf16 g_We2b[(size_t)D_LAT * KB_H];
__device__ bf16 g_cb3 [2 * N_CODES * KB_E];
__device__ bf16 g_W1b [(size_t)D_HID * KB_E];
__device__ bf16 g_W2b [(size_t)N_PAD * KB_H];
__device__ float g_cnorm[2 * N_CODES];
__device__ double g_loss[3];                    // recon_sum, commit0, commit1

// ====================== PTX helpers ========================================
__device__ __forceinline__ uint32_t smem_u32(const void* p) {
    uint32_t a;
    asm("{ .reg .u64 t; cvta.to.shared.u64 t, %1; cvt.u32.u64 %0, t; }"
        : "=r"(a) : "l"(p));
    return a;
}
#define CP16(dst, src) \
    asm volatile("cp.async.cg.shared.global [%0], [%1], 16;" :: "r"(dst), "l"(src) : "memory")
#define CP_COMMIT() asm volatile("cp.async.commit_group;" ::: "memory")
#define CP_WAIT(n)  asm volatile("cp.async.wait_group %0;" :: "n"(n) : "memory")

__device__ __forceinline__ void ldsm_x4(uint32_t* r, uint32_t addr) {
    asm volatile("ldmatrix.sync.aligned.m8n8.x4.shared.b16 {%0,%1,%2,%3}, [%4];"
        : "=r"(r[0]), "=r"(r[1]), "=r"(r[2]), "=r"(r[3]) : "r"(addr));
}
__device__ __forceinline__ void mma_bf16(float* c, const uint32_t* a, const uint32_t* b) {
    asm volatile("mma.sync.aligned.m16n8k16.row.col.f32.bf16.bf16.f32 "
        "{%0,%1,%2,%3}, {%4,%5,%6,%7}, {%8,%9}, {%0,%1,%2,%3};"
        : "+f"(c[0]), "+f"(c[1]), "+f"(c[2]), "+f"(c[3])
        : "r"(a[0]), "r"(a[1]), "r"(a[2]), "r"(a[3]), "r"(b[0]), "r"(b[1]));
}
__device__ __forceinline__ void split_bf16(float v, bf16& hi, bf16& lo) {
    hi = __float2bfloat16_rn(v);
    lo = __float2bfloat16_rn(v - __bfloat162float(hi));
}

// ---------------- prep kernels ---------------------------------------------
__global__ void init_k() {
    if (threadIdx.x < 3) g_loss[threadIdx.x] = 0.0;
}

// x [B,784] f32 -> g_x3 [B,1664] = [xh(832)|xl(832)] with zero pad
__global__ void prep_x_k(const float* __restrict__ x) {
    size_t idx = (size_t)blockIdx.x * blockDim.x + threadIdx.x;
    if (idx >= (size_t)B_ROWS * (L_X / 4)) return;
    size_t m = idx / (L_X / 4);
    int c = (int)(idx % (L_X / 4)) * 4;
    bf162 hp0, hp1, lp0, lp1;
    if (c < D_IN) {
        float4 v = *(const float4*)(x + m * D_IN + c);
        bf16 h0, l0, h1, l1, h2, l2, h3, l3;
        split_bf16(v.x, h0, l0); split_bf16(v.y, h1, l1);
        split_bf16(v.z, h2, l2); split_bf16(v.w, h3, l3);
        hp0.x = h0; hp0.y = h1; hp1.x = h2; hp1.y = h3;
        lp0.x = l0; lp0.y = l1; lp1.x = l2; lp1.y = l3;
    } else {
        bf16 z = __float2bfloat16(0.f);
        hp0.x = z; hp0.y = z; hp1 = hp0; lp0 = hp0; lp1 = hp0;
    }
    bf162* R = (bf162*)(g_x3 + m * KA_X);
    R[c / 2] = hp0;             R[c / 2 + 1] = hp1;
    R[(L_X + c) / 2] = lp0;     R[(L_X + c) / 2 + 1] = lp1;
}

// We1 [784,512] -> g_We1b [512, 2496] rows [Wh|Wh|Wl] (zero pad k>=784)
__global__ void prep_we1_k(const float* __restrict__ We1) {
    int idx = blockIdx.x * blockDim.x + threadIdx.x;
    if (idx < D_HID * L_X) {
        int n = idx / L_X, k = idx % L_X;
        float v = (k < D_IN) ? We1[(size_t)k * D_HID + n] : 0.f;
        bf16 hi, lo; split_bf16(v, hi, lo);
        bf16* R = g_We1b + (size_t)n * KB_X;
        R[k] = hi; R[L_X + k] = hi; R[2 * L_X + k] = lo;
    }
}
__global__ void prep_we2_k(const float* __restrict__ We2) {
    int idx = blockIdx.x * blockDim.x + threadIdx.x;
    if (idx < D_LAT * D_HID) {
        int n = idx / D_HID, k = idx % D_HID;
        bf16 hi, lo; split_bf16(We2[(size_t)k * D_LAT + n], hi, lo);
        bf16* R = g_We2b + (size_t)n * KB_H;
        R[k] = hi; R[D_HID + k] = hi; R[2 * D_HID + k] = lo;
    }
}
__global__ void prep_cb_k(const float* __restrict__ cb0,
                          const float* __restrict__ cb1) {
    int c = blockIdx.x;
    const float* cb = c ? cb1 : cb0;
    int n = threadIdx.x;
    bf16* R = g_cb3 + ((size_t)c * N_CODES + n) * KB_E;
    float s = 0.f;
    for (int k = 0; k < D_LAT; k++) {
        float v = cb[(size_t)n * D_LAT + k];
        s = fmaf(v, v, s);
        bf16 hi, lo; split_bf16(v, hi, lo);
        R[k] = hi; R[D_LAT + k] = hi; R[2 * D_LAT + k] = lo;
    }
    g_cnorm[c * N_CODES + n] = s;
}
__global__ void prep_wd1_k(const float* __restrict__ Wd1) {
    int idx = blockIdx.x * blockDim.x + threadIdx.x;
    if (idx < D_HID * D_LAT) {
        int n = idx / D_LAT, k = idx % D_LAT;
        bf16 hi, lo; split_bf16(Wd1[(size_t)k * D_HID + n], hi, lo);
        bf16* R = g_W1b + (size_t)n * KB_E;
        R[k] = hi; R[D_LAT + k] = hi; R[2 * D_LAT + k] = lo;
    }
}
__global__ void prep_wd2_k(const float* __restrict__ Wd2) {
    int idx = blockIdx.x * blockDim.x + threadIdx.x;
    if (idx < N_PAD * D_HID) {
        int n = idx / D_HID, k = idx % D_HID;
        bf16 hi, lo;
        if (n < D_IN) split_bf16(Wd2[(size_t)k * D_IN + n], hi, lo);
        else { hi = __float2bfloat16(0.f); lo = hi; }
        bf16* R = g_W2b + (size_t)n * KB_H;
        R[k] = hi; R[D_HID + k] = hi; R[2 * D_HID + k] = lo;
    }
}

__global__ void finalize_k(float* __restrict__ out_loss) {
    double loss = g_loss[0] / ((double)B_ROWS * (double)D_IN)
                + 0.25 * ((g_loss[1] + g_loss[2]) / ((double)B_ROWS * (double)D_LAT));
    out_loss[0] = (float)loss;
}

// ---------------- universal split-bf16 HMMA GEMM (3-stage pipeline) ---------
// C[M,N] = A[M,kA] @ BT[N,K]^T with piecewise K-remap on A:
//   chunks [0, 2L): A linear ([Ah|Al]) vs B [Bh|Bh]
//   chunks [2L,3L): A wraps to Ah      vs B [Bl]
// EPI 1: +bias, relu -> split pair [h|l] bf16, row stride ldc
// EPI 2: +bias, tanh -> f32 store + sum((v-X)^2) into lossAcc
// EPI 3: +bias -> f32 (Cout, stride Nout) AND split pair (Cout2, 2*Nout)
// EPI 4: dv = aux[gn] - 2*acc; per-row argmin over CTA's 128 cols ->
//        float2(dv, idx) at Cout[m * gridDim.x + blockIdx.x]
#define HM 128
#define HN 128
#define HK 64
#define PITCH 144
#define NSTAGE 3
#define TILE_B (HM * PITCH)                    // 18432
#define SMEM_HMMA (2 * NSTAGE * TILE_B)        // 110592

template <int EPI>
__global__ void __launch_bounds__(256)
hmma_k(const bf16* __restrict__ A, const bf16* __restrict__ BT,
       const float* __restrict__ aux, void* __restrict__ Cout,
       void* __restrict__ Cout2, int kA, int K, int Nout, int ldc,
       const float* __restrict__ X, double* __restrict__ lossAcc) {
    extern __shared__ char sm[];
    __shared__ float red[8];

    const int tid = threadIdx.x;
    const int wid = tid >> 5, lane = tid & 31;
    const int warp_m = wid >> 1, warp_n = wid & 1;
    const int m0 = blockIdx.y * HM, n0 = blockIdx.x * HN;
    const int NC = K / HK;

    const uint32_t smA = smem_u32(sm);
    const uint32_t smB = smA + NSTAGE * TILE_B;

    const int lrow = tid >> 3;           // 0..31
    const int lseg = (tid & 7) << 4;     // 0,16,...,112
    const size_t rsA = (size_t)kA * 2;
    const size_t rsB = (size_t)K * 2;
    const char* Ag = (const char*)(A + (size_t)m0 * kA) + (size_t)lrow * rsA + lseg;
    const char* Bg = (const char*)(BT + (size_t)n0 * K) + (size_t)lrow * rsB + lseg;
    const uint32_t stoff = lrow * PITCH + lseg;
    const int kAb = kA * 2;  // bytes

    const int a_row = (lane & 15);
    const int a_kb16 = (lane >> 4) << 4;
    const int b_row = (lane & 7) + ((lane >> 4) << 3);
    const int b_kb16 = ((lane >> 3) & 1) << 4;

    uint32_t a_sm[NSTAGE], b_sm[NSTAGE];
#pragma unroll
    for (int s = 0; s < NSTAGE; s++) {
        a_sm[s] = smA + s * TILE_B + (warp_m * 32 + a_row) * PITCH + a_kb16;
        b_sm[s] = smB + s * TILE_B + (warp_n * 64 + b_row) * PITCH + b_kb16;
    }

    float acc[2][8][4];
#pragma unroll
    for (int i = 0; i < 2; i++)
#pragma unroll
        for (int j = 0; j < 8; j++)
#pragma unroll
            for (int t = 0; t < 4; t++) acc[i][j][t] = 0.f;

    // prefetch chunks 0 .. NSTAGE-2
#pragma unroll
    for (int s = 0; s < NSTAGE - 1; s++) {
        int koffB = s * (HK * 2);
        int koffA = (koffB < kAb) ? koffB : koffB - kAb;
        uint32_t ast = smA + s * TILE_B + stoff;
        uint32_t bst = smB + s * TILE_B + stoff;
#pragma unroll
        for (int j = 0; j < 4; j++) {
            CP16(ast + j * 32 * PITCH, Ag + (size_t)j * 32 * rsA + koffA);
            CP16(bst + j * 32 * PITCH, Bg + (size_t)j * 32 * rsB + koffB);
        }
        CP_COMMIT();
    }

    int pf = NSTAGE - 1;  // next chunk index to prefetch
    for (int i = 0; i < NC; i++) {
        CP_WAIT(NSTAGE - 2);      // chunk i resident
        __syncthreads();          // also retires buffer (i-1)%NSTAGE for reuse

        // prefetch chunk pf into buffer pf%NSTAGE (== (i-1)%NSTAGE)
        if (pf < NC) {
            int buf = pf % NSTAGE;
            int koffB = pf * (HK * 2);
            int koffA = (koffB < kAb) ? koffB : koffB - kAb;
            uint32_t ast = smA + buf * TILE_B + stoff;
            uint32_t bst = smB + buf * TILE_B + stoff;
#pragma unroll
            for (int j = 0; j < 4; j++) {
                CP16(ast + j * 32 * PITCH, Ag + (size_t)j * 32 * rsA + koffA);
                CP16(bst + j * 32 * PITCH, Bg + (size_t)j * 32 * rsB + koffB);
            }
        }
        CP_COMMIT();              // empty group when pf >= NC keeps counts aligned
        pf++;

        int buf = i % NSTAGE;
#pragma unroll
        for (int ks = 0; ks < 4; ks++) {
            uint32_t af[2][4];
#pragma unroll
            for (int im = 0; im < 2; im++)
                ldsm_x4(af[im], a_sm[buf] + im * 16 * PITCH + ks * 32);
            uint32_t bfr[4][4];
#pragma unroll
            for (int jp = 0; jp < 4; jp++)
                ldsm_x4(bfr[jp], b_sm[buf] + jp * 16 * PITCH + ks * 32);
#pragma unroll
            for (int im = 0; im < 2; im++)
#pragma unroll
                for (int jn = 0; jn < 8; jn++)
                    mma_bf16(acc[im][jn], af[im], &bfr[jn >> 1][(jn & 1) * 2]);
        }
    }

    // ---- epilogue
    const int qr = lane >> 2, qc = (lane & 3) * 2;

    if (EPI == 4) {
        __syncthreads();  // all compute done before smem reuse as sMin
        float2* sMin = (float2*)sm;  // [128][2] per-row per-warp_n candidates
        const float* cn = aux;
#pragma unroll
        for (int im = 0; im < 2; im++) {
#pragma unroll
            for (int h = 0; h < 2; h++) {
                int row = warp_m * 32 + im * 16 + h * 8 + qr;
                float bv = 3.4e38f; int bi = 0x7fffffff;
#pragma unroll
                for (int jn = 0; jn < 8; jn++) {
#pragma unroll
                    for (int t = 0; t < 2; t++) {
                        int gn = n0 + warp_n * 64 + jn * 8 + qc + t;
                        float dv = fmaf(-2.f, acc[im][jn][h * 2 + t], __ldg(&cn[gn]));
                        if (dv < bv) { bv = dv; bi = gn; }
                    }
                }
#pragma unroll
                for (int off = 1; off < 4; off <<= 1) {
                    float ov = __shfl_xor_sync(0xffffffffu, bv, off);
                    int   oi = __shfl_xor_sync(0xffffffffu, bi, off);
                    if (ov < bv || (ov == bv && oi < bi)) { bv = ov; bi = oi; }
                }
                if ((lane & 3) == 0)
                    sMin[row * 2 + warp_n] = make_float2(bv, (float)bi);
            }
        }
        __syncthreads();
        if (tid < HM) {
            float2 c0 = sMin[tid * 2 + 0], c1 = sMin[tid * 2 + 1];
            float2 b = (c1.x < c0.x || (c1.x == c0.x && c1.y < c0.y)) ? c1 : c0;
            ((float2*)Cout)[(size_t)(m0 + tid) * gridDim.x + blockIdx.x] = b;
        }
        return;
    }

    float lsum = 0.f;
#pragma unroll
    for (int im = 0; im < 2; im++) {
#pragma unroll
        for (int h = 0; h < 2; h++) {
            int gm = m0 + warp_m * 32 + im * 16 + qr + h * 8;
#pragma unroll
            for (int jn = 0; jn < 8; jn++) {
                int gn = n0 + warp_n * 64 + jn * 8 + qc;
                float v0 = acc[im][jn][h * 2 + 0];
                float v1 = acc[im][jn][h * 2 + 1];
                if (EPI == 1) {
                    v0 = fmaxf(v0 + __ldg(&aux[gn]),     0.f);
                    v1 = fmaxf(v1 + __ldg(&aux[gn + 1]), 0.f);
                    bf16 h0, l0, h1, l1;
                    split_bf16(v0, h0, l0); split_bf16(v1, h1, l1);
                    bf16* Cr = (bf16*)Cout + (size_t)gm * ldc;
                    bf162 hp; hp.x = h0; hp.y = h1;
                    bf162 lp; lp.x = l0; lp.y = l1;
                    *(bf162*)(Cr + gn)        = hp;
                    *(bf162*)(Cr + Nout + gn) = lp;
                } else if (EPI == 2) {
                    if (gn < Nout) {
                        v0 = tanhf(v0 + __ldg(&aux[gn]));
                        v1 = tanhf(v1 + __ldg(&aux[gn + 1]));
                        const float* Xr = X + (size_t)gm * Nout + gn;
                        float d0 = v0 - Xr[0], d1 = v1 - Xr[1];
                        lsum = fmaf(d0, d0, fmaf(d1, d1, lsum));
                        *(float2*)((float*)Cout + (size_t)gm * Nout + gn) =
                            make_float2(v0, v1);
                    }
                } else {  // EPI == 3
                    v0 += __ldg(&aux[gn]);
                    v1 += __ldg(&aux[gn + 1]);
                    *(float2*)((float*)Cout + (size_t)gm * Nout + gn) =
                        make_float2(v0, v1);
                    bf16 h0, l0, h1, l1;
                    split_bf16(v0, h0, l0); split_bf16(v1, h1, l1);
                    bf16* Cr = (bf16*)Cout2 + (size_t)gm * (2 * Nout);
                    bf162 hp; hp.x = h0; hp.y = h1;
                    bf162 lp; lp.x = l0; lp.y = l1;
                    *(bf162*)(Cr + gn)        = hp;
                    *(bf162*)(Cr + Nout + gn) = lp;
                }
            }
        }
    }

    if (EPI == 2) {
#pragma unroll
        for (int off = 16; off > 0; off >>= 1)
            lsum += __shfl_down_sync(0xffffffffu, lsum, off);
        if (lane == 0) red[wid] = lsum;
        __syncthreads();
        if (tid == 0) {
            float s = 0.f;
#pragma unroll
            for (int i = 0; i < 8; i++) s += red[i];
            atomicAdd(lossAcc, (double)s);
        }
    }
}

// ---------------- VQ: combine partial argmins + gather + residual ----------
// tri_mode 0: tri <- split(residual_new) ; 1: tri <- split(enc - residual_new)
__global__ void __launch_bounds__(256)
vq_pass_k(const float2* __restrict__ Sp, const float* __restrict__ cb,
          const float* __restrict__ rin, float* __restrict__ rout,
          const float* __restrict__ enc, bf16* __restrict__ tri, int tri_mode,
          float* __restrict__ idx_out, int pass, double* __restrict__ commitAcc) {
    int warp = threadIdx.x >> 5, lane = threadIdx.x & 31;
    __shared__ float wsum[8];
    float csum = 0.f;

    for (int r = 0; r < 8; r++) {
        int m = blockIdx.x * 64 + warp * 8 + r;
        float2 c0 = Sp[(size_t)m * 2 + 0];
        float2 c1 = Sp[(size_t)m * 2 + 1];
        float2 b = (c1.x < c0.x || (c1.x == c0.x && c1.y < c0.y)) ? c1 : c0;
        int bi = (int)b.y;
        if (lane == 0) idx_out[(size_t)m * 2 + pass] = (float)bi;

        const float4* rin4 = (const float4*)(rin + (size_t)m * D_LAT);
        float4*       rout4 = (float4*)(rout + (size_t)m * D_LAT);
        const float4* cb4 = (const float4*)(cb + (size_t)bi * D_LAT);
#pragma unroll
        for (int t = 0; t < 2; t++) {
            int e = t * 32 + lane;
            float4 rv = rin4[e], cv = cb4[e];
            float4 o;
            o.x = rv.x - cv.x; o.y = rv.y - cv.y;
            o.z = rv.z - cv.z; o.w = rv.w - cv.w;
            rout4[e] = o;
            csum += o.x * o.x + o.y * o.y + o.z * o.z + o.w * o.w;

            float q0, q1, q2, q3v;
            if (tri_mode) {
                const float4* enc4 = (const float4*)(enc + (size_t)m * D_LAT);
                float4 ev = enc4[e];
                q0 = ev.x - o.x; q1 = ev.y - o.y;
                q2 = ev.z - o.z; q3v = ev.w - o.w;
            } else {
                q0 = o.x; q1 = o.y; q2 = o.z; q3v = o.w;
            }
            bf16 h0, l0, h1, l1, h2, l2, h3, l3;
            split_bf16(q0, h0, l0); split_bf16(q1, h1, l1);
            split_bf16(q2, h2, l2); split_bf16(q3v, h3, l3);
            bf162* Qr = (bf162*)(tri + (size_t)m * KA_E);
            bf162 hp0; hp0.x = h0; hp0.y = h1;
            bf162 hp1; hp1.x = h2; hp1.y = h3;
            bf162 lp0; lp0.x = l0; lp0.y = l1;
            bf162 lp1; lp1.x = l2; lp1.y = l3;
            Qr[e * 2 + 0]       = hp0;  Qr[e * 2 + 1]       = hp1;
            Qr[128 + e * 2 + 0] = lp0;  Qr[128 + e * 2 + 1] = lp1;
        }
    }

#pragma unroll
    for (int off = 16; off > 0; off >>= 1)
        csum += __shfl_down_sync(0xffffffffu, csum, off);
    if (lane == 0) wsum[warp] = csum;
    __syncthreads();
    if (threadIdx.x == 0) {
        float s = 0.f;
        for (int i = 0; i < 8; i++) s += wsum[i];
        atomicAdd(commitAcc, (double)s);
    }
}

// ---------------- launch ----------------------------------------------------
extern "C" void kernel_launch(void* const* d_in, const int* in_sizes, int n_in,
                              void* d_out, int out_size) {
    const float* x   = (const float*)d_in[0];
    const float* We1 = (const float*)d_in[1];
    const float* be1 = (const float*)d_in[2];
    const float* We2 = (const float*)d_in[3];
    const float* be2 = (const float*)d_in[4];
    const float* cb0 = (const float*)d_in[5];
    const float* cb1 = (const float*)d_in[6];
    const float* Wd1 = (const float*)d_in[7];
    const float* bd1 = (const float*)d_in[8];
    const float* Wd2 = (const float*)d_in[9];
    const float* bd2 = (const float*)d_in[10];

    float* out       = (float*)d_out;
    float* out_recon = out;
    float* out_idx   = out + (size_t)B_ROWS * D_IN;
    float* out_loss  = out + (size_t)B_ROWS * D_IN + (size_t)B_ROWS * 2;

    bf16 *px3, *ph3, *pe3, *pq3, *pd3, *pWe1b, *pWe2b, *pcb3, *pW1b, *pW2b;
    float *penc, *pr, *pcn;
    float2* pSp;
    double* pl;
    cudaGetSymbolAddress((void**)&px3,   g_x3);
    cudaGetSymbolAddress((void**)&ph3,   g_h3);
    cudaGetSymbolAddress((void**)&penc,  g_enc);
    cudaGetSymbolAddress((void**)&pe3,   g_e3);
    cudaGetSymbolAddress((void**)&pr,    g_r);
    cudaGetSymbolAddress((void**)&pSp,   g_Sp);
    cudaGetSymbolAddress((void**)&pq3,   g_q3);
    cudaGetSymbolAddress((void**)&pd3,   g_d3);
    cudaGetSymbolAddress((void**)&pWe1b, g_We1b);
    cudaGetSymbolAddress((void**)&pWe2b, g_We2b);
    cudaGetSymbolAddress((void**)&pcb3,  g_cb3);
    cudaGetSymbolAddress((void**)&pW1b,  g_W1b);
    cudaGetSymbolAddress((void**)&pW2b,  g_W2b);
    cudaGetSymbolAddress((void**)&pcn,   g_cnorm);
    cudaGetSymbolAddress((void**)&pl,    g_loss);

    cudaFuncSetAttribute(hmma_k<1>, cudaFuncAttributeMaxDynamicSharedMemorySize, SMEM_HMMA);
    cudaFuncSetAttribute(hmma_k<2>, cudaFuncAttributeMaxDynamicSharedMemorySize, SMEM_HMMA);
    cudaFuncSetAttribute(hmma_k<3>, cudaFuncAttributeMaxDynamicSharedMemorySize, SMEM_HMMA);
    cudaFuncSetAttribute(hmma_k<4>, cudaFuncAttributeMaxDynamicSharedMemorySize, SMEM_HMMA);

    dim3 blk(256);

    init_k<<<1, 32>>>();
    prep_x_k<<<(int)(((size_t)B_ROWS * (L_X / 4) + 255) / 256), 256>>>(x);
    prep_we1_k<<<(D_HID * L_X + 255) / 256, 256>>>(We1);
    prep_we2_k<<<(D_LAT * D_HID + 255) / 256, 256>>>(We2);
    prep_cb_k<<<2, 256>>>(cb0, cb1);
    prep_wd1_k<<<(D_HID * D_LAT + 255) / 256, 256>>>(Wd1);
    prep_wd2_k<<<(N_PAD * D_HID + 255) / 256, 256>>>(Wd2);

    // encoder
    hmma_k<1><<<dim3(D_HID / HN, B_ROWS / HM), blk, SMEM_HMMA>>>(
        px3, pWe1b, be1, ph3, nullptr, KA_X, KB_X, D_HID, KA_H, nullptr, nullptr);
    hmma_k<3><<<dim3(D_LAT / HN, B_ROWS / HM), blk, SMEM_HMMA>>>(
        ph3, pWe2b, be2, penc, pe3, KA_H, KB_H, D_LAT, 0, nullptr, nullptr);

    // VQ quantizer 0 (fused per-block argmin in score GEMM epilogue)
    hmma_k<4><<<dim3(N_CODES / HN, B_ROWS / HM), blk, SMEM_HMMA>>>(
        pe3, pcb3, pcn, pSp, nullptr, KA_E, KB_E, N_CODES, 0, nullptr, nullptr);
    vq_pass_k<<<B_ROWS / 64, 256>>>(pSp, cb0, penc, pr,
                                    nullptr, pe3, 0, out_idx, 0, pl + 1);
    // VQ quantizer 1
    hmma_k<4><<<dim3(N_CODES / HN, B_ROWS / HM), blk, SMEM_HMMA>>>(
        pe3, pcb3 + (size_t)N_CODES * KB_E, pcn + N_CODES, pSp, nullptr,
        KA_E, KB_E, N_CODES, 0, nullptr, nullptr);
    vq_pass_k<<<B_ROWS / 64, 256>>>(pSp, cb1, pr, pr,
                                    penc, pq3, 1, out_idx, 1, pl + 2);

    // decoder
    hmma_k<1><<<dim3(D_HID / HN, B_ROWS / HM), blk, SMEM_HMMA>>>(
        pq3, pW1b, bd1, pd3, nullptr, KA_E, KB_E, D_HID, KA_H, nullptr, nullptr);
    hmma_k<2><<<dim3(N_PAD / HN, B_ROWS / HM), blk, SMEM_HMMA>>>(
        pd3, pW2b, bd2, out_recon, nullptr, KA_H, KB_H, D_IN, 0, x, pl + 0);

    finalize_k<<<1, 1>>>(out_loss);
}

// round 8
// speedup vs baseline: 2.1812x; 1.0684x over previous
#include <cuda_runtime.h>
#include <cuda_bf16.h>
#include <cstdint>
#include <math.h>

#define B_ROWS 65536
#define D_IN   784
#define D_HID  512
#define D_LAT  256
#define N_CODES 256
#define N_PAD  896            // dec2 B rows allocated (tiles read up to row 799)
#define L_X    832            // D_IN padded to 13*64
#define KA_X   (2 * L_X)      // 1664 : GEMM1 A row ([xh|xl])
#define KB_X   (3 * L_X)      // 2496 : GEMM1 B row ([Wh|Wh|Wl])
#define KA_H   (2 * D_HID)    // 1024
#define KB_H   (3 * D_HID)    // 1536
#define KA_E   (2 * D_LAT)    // 512
#define KB_E   (3 * D_LAT)    // 768

typedef __nv_bfloat16 bf16;
typedef __nv_bfloat162 bf162;

// ---------------- scratch (device globals; no allocation allowed) ----------
__device__ bf16 g_x3 [(size_t)B_ROWS * KA_X];   // [xh|xl]
__device__ bf16 g_h3 [(size_t)B_ROWS * KA_H];   // [hh|hl]
__device__ float g_enc[(size_t)B_ROWS * D_LAT];
__device__ bf16 g_e3 [(size_t)B_ROWS * KA_E];   // [eh|el], reused for r pairs
__device__ float g_r  [(size_t)B_ROWS * D_LAT];
__device__ float2 g_Sp[(size_t)B_ROWS * 2];     // per-128-block (dv, idx)
__device__ bf16 g_q3 [(size_t)B_ROWS * KA_E];   // [qh|ql]
__device__ bf16 g_d3 [(size_t)B_ROWS * KA_H];   // [dh|dl]
__device__ bf16 g_We1b[(size_t)D_HID * KB_X];
__device__ bf16 g_We2b[(size_t)D_LAT * KB_H];
__device__ bf16 g_cb3 [2 * N_CODES * KB_E];
__device__ bf16 g_W1b [(size_t)D_HID * KB_E];
__device__ bf16 g_W2b [(size_t)N_PAD * KB_H];
__device__ float g_cnorm[2 * N_CODES];
__device__ double g_loss[3];                    // recon_sum, commit0, commit1

// ====================== PTX helpers ========================================
__device__ __forceinline__ uint32_t smem_u32(const void* p) {
    uint32_t a;
    asm("{ .reg .u64 t; cvta.to.shared.u64 t, %1; cvt.u32.u64 %0, t; }"
        : "=r"(a) : "l"(p));
    return a;
}
#define CP16(dst, src) \
    asm volatile("cp.async.cg.shared.global [%0], [%1], 16;" :: "r"(dst), "l"(src) : "memory")
#define CP_COMMIT() asm volatile("cp.async.commit_group;" ::: "memory")
#define CP_WAIT(n)  asm volatile("cp.async.wait_group %0;" :: "n"(n) : "memory")

__device__ __forceinline__ void ldsm_x4(uint32_t* r, uint32_t addr) {
    asm volatile("ldmatrix.sync.aligned.m8n8.x4.shared.b16 {%0,%1,%2,%3}, [%4];"
        : "=r"(r[0]), "=r"(r[1]), "=r"(r[2]), "=r"(r[3]) : "r"(addr));
}
__device__ __forceinline__ void ldsm_x2(uint32_t* r, uint32_t addr) {
    asm volatile("ldmatrix.sync.aligned.m8n8.x2.shared.b16 {%0,%1}, [%2];"
        : "=r"(r[0]), "=r"(r[1]) : "r"(addr));
}
__device__ __forceinline__ void mma_bf16(float* c, const uint32_t* a, const uint32_t* b) {
    asm volatile("mma.sync.aligned.m16n8k16.row.col.f32.bf16.bf16.f32 "
        "{%0,%1,%2,%3}, {%4,%5,%6,%7}, {%8,%9}, {%0,%1,%2,%3};"
        : "+f"(c[0]), "+f"(c[1]), "+f"(c[2]), "+f"(c[3])
        : "r"(a[0]), "r"(a[1]), "r"(a[2]), "r"(a[3]), "r"(b[0]), "r"(b[1]));
}
__device__ __forceinline__ void split_bf16(float v, bf16& hi, bf16& lo) {
    hi = __float2bfloat16_rn(v);
    lo = __float2bfloat16_rn(v - __bfloat162float(hi));
}

// ---------------- prep kernels ---------------------------------------------
__global__ void init_k() {
    if (threadIdx.x < 3) g_loss[threadIdx.x] = 0.0;
}

// x [B,784] f32 -> g_x3 [B,1664] = [xh(832)|xl(832)] with zero pad
__global__ void prep_x_k(const float* __restrict__ x) {
    size_t idx = (size_t)blockIdx.x * blockDim.x + threadIdx.x;
    if (idx >= (size_t)B_ROWS * (L_X / 4)) return;
    size_t m = idx / (L_X / 4);
    int c = (int)(idx % (L_X / 4)) * 4;
    bf162 hp0, hp1, lp0, lp1;
    if (c < D_IN) {
        float4 v = *(const float4*)(x + m * D_IN + c);
        bf16 h0, l0, h1, l1, h2, l2, h3, l3;
        split_bf16(v.x, h0, l0); split_bf16(v.y, h1, l1);
        split_bf16(v.z, h2, l2); split_bf16(v.w, h3, l3);
        hp0.x = h0; hp0.y = h1; hp1.x = h2; hp1.y = h3;
        lp0.x = l0; lp0.y = l1; lp1.x = l2; lp1.y = l3;
    } else {
        bf16 z = __float2bfloat16(0.f);
        hp0.x = z; hp0.y = z; hp1 = hp0; lp0 = hp0; lp1 = hp0;
    }
    bf162* R = (bf162*)(g_x3 + m * KA_X);
    R[c / 2] = hp0;             R[c / 2 + 1] = hp1;
    R[(L_X + c) / 2] = lp0;     R[(L_X + c) / 2 + 1] = lp1;
}

// We1 [784,512] -> g_We1b [512, 2496] rows [Wh|Wh|Wl] (zero pad k>=784)
__global__ void prep_we1_k(const float* __restrict__ We1) {
    int idx = blockIdx.x * blockDim.x + threadIdx.x;
    if (idx < D_HID * L_X) {
        int n = idx / L_X, k = idx % L_X;
        float v = (k < D_IN) ? We1[(size_t)k * D_HID + n] : 0.f;
        bf16 hi, lo; split_bf16(v, hi, lo);
        bf16* R = g_We1b + (size_t)n * KB_X;
        R[k] = hi; R[L_X + k] = hi; R[2 * L_X + k] = lo;
    }
}

// merged small preps: We2 (512 blocks) | Wd1 (512) | Wd2 (1792) | codebooks (2)
#define NB_WE2 (D_LAT * D_HID / 256)     // 512
#define NB_WD1 (D_HID * D_LAT / 256)     // 512
#define NB_WD2 (N_PAD * D_HID / 256)     // 1792
__global__ void prep_small_k(const float* __restrict__ We2,
                             const float* __restrict__ Wd1,
                             const float* __restrict__ Wd2,
                             const float* __restrict__ cb0,
                             const float* __restrict__ cb1) {
    int b = blockIdx.x;
    if (b < NB_WE2) {
        int idx = b * 256 + threadIdx.x;
        int n = idx / D_HID, k = idx % D_HID;
        bf16 hi, lo; split_bf16(We2[(size_t)k * D_LAT + n], hi, lo);
        bf16* R = g_We2b + (size_t)n * KB_H;
        R[k] = hi; R[D_HID + k] = hi; R[2 * D_HID + k] = lo;
        return;
    }
    b -= NB_WE2;
    if (b < NB_WD1) {
        int idx = b * 256 + threadIdx.x;
        int n = idx / D_LAT, k = idx % D_LAT;
        bf16 hi, lo; split_bf16(Wd1[(size_t)k * D_HID + n], hi, lo);
        bf16* R = g_W1b + (size_t)n * KB_E;
        R[k] = hi; R[D_LAT + k] = hi; R[2 * D_LAT + k] = lo;
        return;
    }
    b -= NB_WD1;
    if (b < NB_WD2) {
        int idx = b * 256 + threadIdx.x;
        int n = idx / D_HID, k = idx % D_HID;
        bf16 hi, lo;
        if (n < D_IN) split_bf16(Wd2[(size_t)k * D_IN + n], hi, lo);
        else { hi = __float2bfloat16(0.f); lo = hi; }
        bf16* R = g_W2b + (size_t)n * KB_H;
        R[k] = hi; R[D_HID + k] = hi; R[2 * D_HID + k] = lo;
        return;
    }
    b -= NB_WD2;
    {   // codebooks: b in {0,1}
        const float* cb = b ? cb1 : cb0;
        int n = threadIdx.x;
        bf16* R = g_cb3 + ((size_t)b * N_CODES + n) * KB_E;
        float s = 0.f;
        for (int k = 0; k < D_LAT; k++) {
            float v = cb[(size_t)n * D_LAT + k];
            s = fmaf(v, v, s);
            bf16 hi, lo; split_bf16(v, hi, lo);
            R[k] = hi; R[D_LAT + k] = hi; R[2 * D_LAT + k] = lo;
        }
        g_cnorm[b * N_CODES + n] = s;
    }
}

__global__ void finalize_k(float* __restrict__ out_loss) {
    double loss = g_loss[0] / ((double)B_ROWS * (double)D_IN)
                + 0.25 * ((g_loss[1] + g_loss[2]) / ((double)B_ROWS * (double)D_LAT));
    out_loss[0] = (float)loss;
}

// ---------------- universal split-bf16 HMMA GEMM (3-stage pipeline) ---------
// C[M,N] = A[M,kA] @ BT[N,K]^T, K-remap on A (wraps to hi segment for Bl part).
// NT = n-tiles per warp (8 -> HN=128, 7 -> HN=112).
// EPI 1: +bias, relu -> split pair [h|l] bf16, row stride ldc
// EPI 2: +bias, tanh -> f32 store + sum((v-X)^2) into lossAcc (NT=7, no bounds)
// EPI 3: +bias -> f32 (Cout, stride Nout) AND split pair (Cout2, 2*Nout)
// EPI 4: dv = aux[gn] - 2*acc; per-row argmin over CTA's 128 cols
#define HM 128
#define HK 64
#define PITCH 144
#define NSTAGE 3
#define TILE_B (HM * PITCH)                    // 18432
#define SMEM_HMMA (2 * NSTAGE * TILE_B)        // 110592

template <int EPI, int NT>
__global__ void __launch_bounds__(256)
hmma_k(const bf16* __restrict__ A, const bf16* __restrict__ BT,
       const float* __restrict__ aux, void* __restrict__ Cout,
       void* __restrict__ Cout2, int kA, int K, int Nout, int ldc,
       const float* __restrict__ X, double* __restrict__ lossAcc) {
    extern __shared__ char sm[];
    __shared__ float red[8];

    const int HN_T = 16 * NT;            // CTA n-tile width
    const int tid = threadIdx.x;
    const int wid = tid >> 5, lane = tid & 31;
    const int warp_m = wid >> 1, warp_n = wid & 1;
    const int m0 = blockIdx.y * HM, n0 = blockIdx.x * HN_T;
    const int NC = K / HK;

    const uint32_t smA = smem_u32(sm);
    const uint32_t smB = smA + NSTAGE * TILE_B;

    const int lrow = tid >> 3;           // 0..31
    const int lseg = (tid & 7) << 4;     // 0,16,...,112
    const size_t rsA = (size_t)kA * 2;
    const size_t rsB = (size_t)K * 2;
    const char* Ag = (const char*)(A + (size_t)m0 * kA) + (size_t)lrow * rsA + lseg;
    const char* Bg = (const char*)(BT + (size_t)n0 * K) + (size_t)lrow * rsB + lseg;
    const uint32_t stoff = lrow * PITCH + lseg;
    const int kAb = kA * 2;  // bytes

    const int a_row = (lane & 15);
    const int a_kb16 = (lane >> 4) << 4;
    const int b_row = (lane & 7) + ((lane >> 4) << 3);
    const int b_kb16 = ((lane >> 3) & 1) << 4;

    uint32_t a_sm[NSTAGE], b_sm[NSTAGE];
#pragma unroll
    for (int s = 0; s < NSTAGE; s++) {
        a_sm[s] = smA + s * TILE_B + (warp_m * 32 + a_row) * PITCH + a_kb16;
        b_sm[s] = smB + s * TILE_B + (warp_n * (NT * 8) + b_row) * PITCH + b_kb16;
    }

    float acc[2][NT][4];
#pragma unroll
    for (int i = 0; i < 2; i++)
#pragma unroll
        for (int j = 0; j < NT; j++)
#pragma unroll
            for (int t = 0; t < 4; t++) acc[i][j][t] = 0.f;

    // prefetch chunks 0 .. NSTAGE-2 (always load 128 B rows; extra rows are
    // in-bounds garbage for NT=7 and never consumed by ldsm)
#pragma unroll
    for (int s = 0; s < NSTAGE - 1; s++) {
        int koffB = s * (HK * 2);
        int koffA = (koffB < kAb) ? koffB : koffB - kAb;
        uint32_t ast = smA + s * TILE_B + stoff;
        uint32_t bst = smB + s * TILE_B + stoff;
#pragma unroll
        for (int j = 0; j < 4; j++) {
            CP16(ast + j * 32 * PITCH, Ag + (size_t)j * 32 * rsA + koffA);
            CP16(bst + j * 32 * PITCH, Bg + (size_t)j * 32 * rsB + koffB);
        }
        CP_COMMIT();
    }

    int pf = NSTAGE - 1;
    for (int i = 0; i < NC; i++) {
        CP_WAIT(NSTAGE - 2);
        __syncthreads();

        if (pf < NC) {
            int buf = pf % NSTAGE;
            int koffB = pf * (HK * 2);
            int koffA = (koffB < kAb) ? koffB : koffB - kAb;
            uint32_t ast = smA + buf * TILE_B + stoff;
            uint32_t bst = smB + buf * TILE_B + stoff;
#pragma unroll
            for (int j = 0; j < 4; j++) {
                CP16(ast + j * 32 * PITCH, Ag + (size_t)j * 32 * rsA + koffA);
                CP16(bst + j * 32 * PITCH, Bg + (size_t)j * 32 * rsB + koffB);
            }
        }
        CP_COMMIT();
        pf++;

        int buf = i % NSTAGE;
#pragma unroll
        for (int ks = 0; ks < 4; ks++) {
            uint32_t af[2][4];
#pragma unroll
            for (int im = 0; im < 2; im++)
                ldsm_x4(af[im], a_sm[buf] + im * 16 * PITCH + ks * 32);
            uint32_t bfr[(NT + 1) / 2][4];
#pragma unroll
            for (int jp = 0; jp < NT / 2; jp++)
                ldsm_x4(bfr[jp], b_sm[buf] + jp * 16 * PITCH + ks * 32);
            if (NT & 1)
                ldsm_x2(bfr[NT / 2], b_sm[buf] + (NT - 1) * 8 * PITCH + ks * 32);
#pragma unroll
            for (int im = 0; im < 2; im++)
#pragma unroll
                for (int jn = 0; jn < NT; jn++)
                    mma_bf16(acc[im][jn], af[im], &bfr[jn >> 1][(jn & 1) * 2]);
        }
    }

    // ---- epilogue
    const int qr = lane >> 2, qc = (lane & 3) * 2;

    if (EPI == 4) {
        __syncthreads();
        float2* sMin = (float2*)sm;
        const float* cn = aux;
#pragma unroll
        for (int im = 0; im < 2; im++) {
#pragma unroll
            for (int h = 0; h < 2; h++) {
                int row = warp_m * 32 + im * 16 + h * 8 + qr;
                float bv = 3.4e38f; int bi = 0x7fffffff;
#pragma unroll
                for (int jn = 0; jn < NT; jn++) {
#pragma unroll
                    for (int t = 0; t < 2; t++) {
                        int gn = n0 + warp_n * (NT * 8) + jn * 8 + qc + t;
                        float dv = fmaf(-2.f, acc[im][jn][h * 2 + t], __ldg(&cn[gn]));
                        if (dv < bv) { bv = dv; bi = gn; }
                    }
                }
#pragma unroll
                for (int off = 1; off < 4; off <<= 1) {
                    float ov = __shfl_xor_sync(0xffffffffu, bv, off);
                    int   oi = __shfl_xor_sync(0xffffffffu, bi, off);
                    if (ov < bv || (ov == bv && oi < bi)) { bv = ov; bi = oi; }
                }
                if ((lane & 3) == 0)
                    sMin[row * 2 + warp_n] = make_float2(bv, (float)bi);
            }
        }
        __syncthreads();
        if (tid < HM) {
            float2 c0 = sMin[tid * 2 + 0], c1 = sMin[tid * 2 + 1];
            float2 b = (c1.x < c0.x || (c1.x == c0.x && c1.y < c0.y)) ? c1 : c0;
            ((float2*)Cout)[(size_t)(m0 + tid) * gridDim.x + blockIdx.x] = b;
        }
        return;
    }

    float lsum = 0.f;
#pragma unroll
    for (int im = 0; im < 2; im++) {
#pragma unroll
        for (int h = 0; h < 2; h++) {
            int gm = m0 + warp_m * 32 + im * 16 + qr + h * 8;
#pragma unroll
            for (int jn = 0; jn < NT; jn++) {
                int gn = n0 + warp_n * (NT * 8) + jn * 8 + qc;
                float v0 = acc[im][jn][h * 2 + 0];
                float v1 = acc[im][jn][h * 2 + 1];
                if (EPI == 1) {
                    v0 = fmaxf(v0 + __ldg(&aux[gn]),     0.f);
                    v1 = fmaxf(v1 + __ldg(&aux[gn + 1]), 0.f);
                    bf16 h0, l0, h1, l1;
                    split_bf16(v0, h0, l0); split_bf16(v1, h1, l1);
                    bf16* Cr = (bf16*)Cout + (size_t)gm * ldc;
                    bf162 hp; hp.x = h0; hp.y = h1;
                    bf162 lp; lp.x = l0; lp.y = l1;
                    *(bf162*)(Cr + gn)        = hp;
                    *(bf162*)(Cr + Nout + gn) = lp;
                } else if (EPI == 2) {
                    v0 = tanhf(v0 + __ldg(&aux[gn]));
                    v1 = tanhf(v1 + __ldg(&aux[gn + 1]));
                    const float* Xr = X + (size_t)gm * Nout + gn;
                    float d0 = v0 - Xr[0], d1 = v1 - Xr[1];
                    lsum = fmaf(d0, d0, fmaf(d1, d1, lsum));
                    *(float2*)((float*)Cout + (size_t)gm * Nout + gn) =
                        make_float2(v0, v1);
                } else {  // EPI == 3
                    v0 += __ldg(&aux[gn]);
                    v1 += __ldg(&aux[gn + 1]);
                    *(float2*)((float*)Cout + (size_t)gm * Nout + gn) =
                        make_float2(v0, v1);
                    bf16 h0, l0, h1, l1;
                    split_bf16(v0, h0, l0); split_bf16(v1, h1, l1);
                    bf16* Cr = (bf16*)Cout2 + (size_t)gm * (2 * Nout);
                    bf162 hp; hp.x = h0; hp.y = h1;
                    bf162 lp; lp.x = l0; lp.y = l1;
                    *(bf162*)(Cr + gn)        = hp;
                    *(bf162*)(Cr + Nout + gn) = lp;
                }
            }
        }
    }

    if (EPI == 2) {
#pragma unroll
        for (int off = 16; off > 0; off >>= 1)
            lsum += __shfl_down_sync(0xffffffffu, lsum, off);
        if (lane == 0) red[wid] = lsum;
        __syncthreads();
        if (tid == 0) {
            float s = 0.f;
#pragma unroll
            for (int i = 0; i < 8; i++) s += red[i];
            atomicAdd(lossAcc, (double)s);
        }
    }
}

// ---------------- VQ: combine partial argmins + gather + residual ----------
__global__ void __launch_bounds__(256)
vq_pass_k(const float2* __restrict__ Sp, const float* __restrict__ cb,
          const float* __restrict__ rin, float* __restrict__ rout,
          const float* __restrict__ enc, bf16* __restrict__ tri, int tri_mode,
          float* __restrict__ idx_out, int pass, double* __restrict__ commitAcc) {
    int warp = threadIdx.x >> 5, lane = threadIdx.x & 31;
    __shared__ float wsum[8];
    float csum = 0.f;

    for (int r = 0; r < 8; r++) {
        int m = blockIdx.x * 64 + warp * 8 + r;
        float2 c0 = Sp[(size_t)m * 2 + 0];
        float2 c1 = Sp[(size_t)m * 2 + 1];
        float2 b = (c1.x < c0.x || (c1.x == c0.x && c1.y < c0.y)) ? c1 : c0;
        int bi = (int)b.y;
        if (lane == 0) idx_out[(size_t)m * 2 + pass] = (float)bi;

        const float4* rin4 = (const float4*)(rin + (size_t)m * D_LAT);
        float4*       rout4 = (float4*)(rout + (size_t)m * D_LAT);
        const float4* cb4 = (const float4*)(cb + (size_t)bi * D_LAT);
#pragma unroll
        for (int t = 0; t < 2; t++) {
            int e = t * 32 + lane;
            float4 rv = rin4[e], cv = cb4[e];
            float4 o;
            o.x = rv.x - cv.x; o.y = rv.y - cv.y;
            o.z = rv.z - cv.z; o.w = rv.w - cv.w;
            rout4[e] = o;
            csum += o.x * o.x + o.y * o.y + o.z * o.z + o.w * o.w;

            float q0, q1, q2, q3v;
            if (tri_mode) {
                const float4* enc4 = (const float4*)(enc + (size_t)m * D_LAT);
                float4 ev = enc4[e];
                q0 = ev.x - o.x; q1 = ev.y - o.y;
                q2 = ev.z - o.z; q3v = ev.w - o.w;
            } else {
                q0 = o.x; q1 = o.y; q2 = o.z; q3v = o.w;
            }
            bf16 h0, l0, h1, l1, h2, l2, h3, l3;
            split_bf16(q0, h0, l0); split_bf16(q1, h1, l1);
            split_bf16(q2, h2, l2); split_bf16(q3v, h3, l3);
            bf162* Qr = (bf162*)(tri + (size_t)m * KA_E);
            bf162 hp0; hp0.x = h0; hp0.y = h1;
            bf162 hp1; hp1.x = h2; hp1.y = h3;
            bf162 lp0; lp0.x = l0; lp0.y = l1;
            bf162 lp1; lp1.x = l2; lp1.y = l3;
            Qr[e * 2 + 0]       = hp0;  Qr[e * 2 + 1]       = hp1;
            Qr[128 + e * 2 + 0] = lp0;  Qr[128 + e * 2 + 1] = lp1;
        }
    }

#pragma unroll
    for (int off = 16; off > 0; off >>= 1)
        csum += __shfl_down_sync(0xffffffffu, csum, off);
    if (lane == 0) wsum[warp] = csum;
    __syncthreads();
    if (threadIdx.x == 0) {
        float s = 0.f;
        for (int i = 0; i < 8; i++) s += wsum[i];
        atomicAdd(commitAcc, (double)s);
    }
}

// ---------------- launch ----------------------------------------------------
extern "C" void kernel_launch(void* const* d_in, const int* in_sizes, int n_in,
                              void* d_out, int out_size) {
    const float* x   = (const float*)d_in[0];
    const float* We1 = (const float*)d_in[1];
    const float* be1 = (const float*)d_in[2];
    const float* We2 = (const float*)d_in[3];
    const float* be2 = (const float*)d_in[4];
    const float* cb0 = (const float*)d_in[5];
    const float* cb1 = (const float*)d_in[6];
    const float* Wd1 = (const float*)d_in[7];
    const float* bd1 = (const float*)d_in[8];
    const float* Wd2 = (const float*)d_in[9];
    const float* bd2 = (const float*)d_in[10];

    float* out       = (float*)d_out;
    float* out_recon = out;
    float* out_idx   = out + (size_t)B_ROWS * D_IN;
    float* out_loss  = out + (size_t)B_ROWS * D_IN + (size_t)B_ROWS * 2;

    bf16 *px3, *ph3, *pe3, *pq3, *pd3, *pWe1b, *pWe2b, *pcb3, *pW1b, *pW2b;
    float *penc, *pr, *pcn;
    float2* pSp;
    double* pl;
    cudaGetSymbolAddress((void**)&px3,   g_x3);
    cudaGetSymbolAddress((void**)&ph3,   g_h3);
    cudaGetSymbolAddress((void**)&penc,  g_enc);
    cudaGetSymbolAddress((void**)&pe3,   g_e3);
    cudaGetSymbolAddress((void**)&pr,    g_r);
    cudaGetSymbolAddress((void**)&pSp,   g_Sp);
    cudaGetSymbolAddress((void**)&pq3,   g_q3);
    cudaGetSymbolAddress((void**)&pd3,   g_d3);
    cudaGetSymbolAddress((void**)&pWe1b, g_We1b);
    cudaGetSymbolAddress((void**)&pWe2b, g_We2b);
    cudaGetSymbolAddress((void**)&pcb3,  g_cb3);
    cudaGetSymbolAddress((void**)&pW1b,  g_W1b);
    cudaGetSymbolAddress((void**)&pW2b,  g_W2b);
    cudaGetSymbolAddress((void**)&pcn,   g_cnorm);
    cudaGetSymbolAddress((void**)&pl,    g_loss);

    cudaFuncSetAttribute((const void*)hmma_k<1, 8>, cudaFuncAttributeMaxDynamicSharedMemorySize, SMEM_HMMA);
    cudaFuncSetAttribute((const void*)hmma_k<2, 7>, cudaFuncAttributeMaxDynamicSharedMemorySize, SMEM_HMMA);
    cudaFuncSetAttribute((const void*)hmma_k<3, 8>, cudaFuncAttributeMaxDynamicSharedMemorySize, SMEM_HMMA);
    cudaFuncSetAttribute((const void*)hmma_k<4, 8>, cudaFuncAttributeMaxDynamicSharedMemorySize, SMEM_HMMA);

    dim3 blk(256);

    // launches 0..3 (so launch index 5 = second GEMM for ncu -s 5)
    init_k<<<1, 32>>>();
    prep_x_k<<<(int)(((size_t)B_ROWS * (L_X / 4) + 255) / 256), 256>>>(x);
    prep_we1_k<<<(D_HID * L_X + 255) / 256, 256>>>(We1);
    prep_small_k<<<NB_WE2 + NB_WD1 + NB_WD2 + 2, 256>>>(We2, Wd1, Wd2, cb0, cb1);

    // encoder (launches 4, 5)
    hmma_k<1, 8><<<dim3(D_HID / 128, B_ROWS / HM), blk, SMEM_HMMA>>>(
        px3, pWe1b, be1, ph3, nullptr, KA_X, KB_X, D_HID, KA_H, nullptr, nullptr);
    hmma_k<3, 8><<<dim3(D_LAT / 128, B_ROWS / HM), blk, SMEM_HMMA>>>(
        ph3, pWe2b, be2, penc, pe3, KA_H, KB_H, D_LAT, 0, nullptr, nullptr);

    // VQ quantizer 0
    hmma_k<4, 8><<<dim3(N_CODES / 128, B_ROWS / HM), blk, SMEM_HMMA>>>(
        pe3, pcb3, pcn, pSp, nullptr, KA_E, KB_E, N_CODES, 0, nullptr, nullptr);
    vq_pass_k<<<B_ROWS / 64, 256>>>(pSp, cb0, penc, pr,
                                    nullptr, pe3, 0, out_idx, 0, pl + 1);
    // VQ quantizer 1
    hmma_k<4, 8><<<dim3(N_CODES / 128, B_ROWS / HM), blk, SMEM_HMMA>>>(
        pe3, pcb3 + (size_t)N_CODES * KB_E, pcn + N_CODES, pSp, nullptr,
        KA_E, KB_E, N_CODES, 0, nullptr, nullptr);
    vq_pass_k<<<B_ROWS / 64, 256>>>(pSp, cb1, pr, pr,
                                    penc, pq3, 1, out_idx, 1, pl + 2);

    // decoder (dec2 with exact N=784 via HN=112 tiles)
    hmma_k<1, 8><<<dim3(D_HID / 128, B_ROWS / HM), blk, SMEM_HMMA>>>(
        pq3, pW1b, bd1, pd3, nullptr, KA_E, KB_E, D_HID, KA_H, nullptr, nullptr);
    hmma_k<2, 7><<<dim3(D_IN / 112, B_ROWS / HM), blk, SMEM_HMMA>>>(
        pd3, pW2b, bd2, out_recon, nullptr, KA_H, KB_H, D_IN, 0, x, pl + 0);

    finalize_k<<<1, 1>>>(out_loss);
}

// round 9
// speedup vs baseline: 2.5258x; 1.1580x over previous
#include <cuda_runtime.h>
#include <cuda_bf16.h>
#include <cstdint>
#include <math.h>

#define B_ROWS 65536
#define D_IN   784
#define D_HID  512
#define D_LAT  256
#define N_CODES 256
#define N_PAD  896            // dec2 B rows allocated (tiles read up to row 799)
#define L_X    832            // D_IN padded to 13*64
#define KA_X   (2 * L_X)      // 1664 : GEMM1 A row ([xh|xl])
#define KB_X   (3 * L_X)      // 2496 : GEMM1 B row ([Wh|Wh|Wl])
#define KA_H   (2 * D_HID)    // 1024
#define KB_H   (3 * D_HID)    // 1536
#define KA_E   (2 * D_LAT)    // 512
#define KB_E   (3 * D_LAT)    // 768

typedef __nv_bfloat16 bf16;
typedef __nv_bfloat162 bf162;

// ---------------- scratch (device globals; no allocation allowed) ----------
__device__ bf16 g_x3 [(size_t)B_ROWS * KA_X];   // [xh|xl]
__device__ bf16 g_h3 [(size_t)B_ROWS * KA_H];   // [hh|hl]
__device__ float g_enc[(size_t)B_ROWS * D_LAT];
__device__ bf16 g_e3 [(size_t)B_ROWS * KA_E];   // [eh|el], reused for r pairs
__device__ float g_r  [(size_t)B_ROWS * D_LAT];
__device__ float2 g_Sp[(size_t)B_ROWS * 2];     // per-128-block (dv, idx)
__device__ bf16 g_q3 [(size_t)B_ROWS * KA_E];   // [qh|ql]
__device__ bf16 g_d3 [(size_t)B_ROWS * KA_H];   // [dh|dl]
__device__ bf16 g_We1b[(size_t)D_HID * KB_X];
__device__ bf16 g_We2b[(size_t)D_LAT * KB_H];
__device__ bf16 g_cb3 [2 * N_CODES * KB_E];
__device__ bf16 g_W1b [(size_t)D_HID * KB_E];
__device__ bf16 g_W2b [(size_t)N_PAD * KB_H];
__device__ float g_cnorm[2 * N_CODES];
__device__ double g_loss[3];                    // recon_sum, commit0, commit1

// ====================== PTX helpers ========================================
__device__ __forceinline__ uint32_t smem_u32(const void* p) {
    uint32_t a;
    asm("{ .reg .u64 t; cvta.to.shared.u64 t, %1; cvt.u32.u64 %0, t; }"
        : "=r"(a) : "l"(p));
    return a;
}
#define CP16(dst, src) \
    asm volatile("cp.async.cg.shared.global [%0], [%1], 16;" :: "r"(dst), "l"(src) : "memory")
#define CP_COMMIT() asm volatile("cp.async.commit_group;" ::: "memory")
#define CP_WAIT(n)  asm volatile("cp.async.wait_group %0;" :: "n"(n) : "memory")

__device__ __forceinline__ void ldsm_x4(uint32_t* r, uint32_t addr) {
    asm volatile("ldmatrix.sync.aligned.m8n8.x4.shared.b16 {%0,%1,%2,%3}, [%4];"
        : "=r"(r[0]), "=r"(r[1]), "=r"(r[2]), "=r"(r[3]) : "r"(addr));
}
__device__ __forceinline__ void ldsm_x2(uint32_t* r, uint32_t addr) {
    asm volatile("ldmatrix.sync.aligned.m8n8.x2.shared.b16 {%0,%1}, [%2];"
        : "=r"(r[0]), "=r"(r[1]) : "r"(addr));
}
__device__ __forceinline__ void mma_bf16(float* c, const uint32_t* a, const uint32_t* b) {
    asm volatile("mma.sync.aligned.m16n8k16.row.col.f32.bf16.bf16.f32 "
        "{%0,%1,%2,%3}, {%4,%5,%6,%7}, {%8,%9}, {%0,%1,%2,%3};"
        : "+f"(c[0]), "+f"(c[1]), "+f"(c[2]), "+f"(c[3])
        : "r"(a[0]), "r"(a[1]), "r"(a[2]), "r"(a[3]), "r"(b[0]), "r"(b[1]));
}
__device__ __forceinline__ void split_bf16(float v, bf16& hi, bf16& lo) {
    hi = __float2bfloat16_rn(v);
    lo = __float2bfloat16_rn(v - __bfloat162float(hi));
}

// ---------------- prep kernels ---------------------------------------------
__global__ void init_k() {
    if (threadIdx.x < 3) g_loss[threadIdx.x] = 0.0;
}

// x [B,784] f32 -> g_x3 [B,1664] = [xh(832)|xl(832)] with zero pad
__global__ void prep_x_k(const float* __restrict__ x) {
    size_t idx = (size_t)blockIdx.x * blockDim.x + threadIdx.x;
    if (idx >= (size_t)B_ROWS * (L_X / 4)) return;
    size_t m = idx / (L_X / 4);
    int c = (int)(idx % (L_X / 4)) * 4;
    bf162 hp0, hp1, lp0, lp1;
    if (c < D_IN) {
        float4 v = *(const float4*)(x + m * D_IN + c);
        bf16 h0, l0, h1, l1, h2, l2, h3, l3;
        split_bf16(v.x, h0, l0); split_bf16(v.y, h1, l1);
        split_bf16(v.z, h2, l2); split_bf16(v.w, h3, l3);
        hp0.x = h0; hp0.y = h1; hp1.x = h2; hp1.y = h3;
        lp0.x = l0; lp0.y = l1; lp1.x = l2; lp1.y = l3;
    } else {
        bf16 z = __float2bfloat16(0.f);
        hp0.x = z; hp0.y = z; hp1 = hp0; lp0 = hp0; lp1 = hp0;
    }
    bf162* R = (bf162*)(g_x3 + m * KA_X);
    R[c / 2] = hp0;             R[c / 2 + 1] = hp1;
    R[(L_X + c) / 2] = lp0;     R[(L_X + c) / 2 + 1] = lp1;
}

// We1 [784,512] -> g_We1b [512, 2496] rows [Wh|Wh|Wl] (zero pad k>=784)
__global__ void prep_we1_k(const float* __restrict__ We1) {
    int idx = blockIdx.x * blockDim.x + threadIdx.x;
    if (idx < D_HID * L_X) {
        int n = idx / L_X, k = idx % L_X;
        float v = (k < D_IN) ? We1[(size_t)k * D_HID + n] : 0.f;
        bf16 hi, lo; split_bf16(v, hi, lo);
        bf16* R = g_We1b + (size_t)n * KB_X;
        R[k] = hi; R[L_X + k] = hi; R[2 * L_X + k] = lo;
    }
}

// merged small weight preps: We2 (512 blocks) | Wd1 (512) | Wd2 (1792)
#define NB_WE2 (D_LAT * D_HID / 256)     // 512
#define NB_WD1 (D_HID * D_LAT / 256)     // 512
#define NB_WD2 (N_PAD * D_HID / 256)     // 1792
__global__ void prep_small_k(const float* __restrict__ We2,
                             const float* __restrict__ Wd1,
                             const float* __restrict__ Wd2) {
    int b = blockIdx.x;
    if (b < NB_WE2) {
        int idx = b * 256 + threadIdx.x;
        int n = idx / D_HID, k = idx % D_HID;
        bf16 hi, lo; split_bf16(We2[(size_t)k * D_LAT + n], hi, lo);
        bf16* R = g_We2b + (size_t)n * KB_H;
        R[k] = hi; R[D_HID + k] = hi; R[2 * D_HID + k] = lo;
        return;
    }
    b -= NB_WE2;
    if (b < NB_WD1) {
        int idx = b * 256 + threadIdx.x;
        int n = idx / D_LAT, k = idx % D_LAT;
        bf16 hi, lo; split_bf16(Wd1[(size_t)k * D_HID + n], hi, lo);
        bf16* R = g_W1b + (size_t)n * KB_E;
        R[k] = hi; R[D_LAT + k] = hi; R[2 * D_LAT + k] = lo;
        return;
    }
    b -= NB_WD1;
    {
        int idx = b * 256 + threadIdx.x;
        int n = idx / D_HID, k = idx % D_HID;
        bf16 hi, lo;
        if (n < D_IN) split_bf16(Wd2[(size_t)k * D_IN + n], hi, lo);
        else { hi = __float2bfloat16(0.f); lo = hi; }
        bf16* R = g_W2b + (size_t)n * KB_H;
        R[k] = hi; R[D_HID + k] = hi; R[2 * D_HID + k] = lo;
    }
}

// codebooks: one block per (codebook, code); coalesced loads/stores + reduce
__global__ void prep_cb_k(const float* __restrict__ cb0,
                          const float* __restrict__ cb1) {
    __shared__ float red[8];
    int c = blockIdx.x >> 8;            // codebook 0/1
    int n = blockIdx.x & 255;           // code index
    int k = threadIdx.x;                // 0..255
    const float* cb = c ? cb1 : cb0;
    float v = cb[(size_t)n * D_LAT + k];
    bf16 hi, lo; split_bf16(v, hi, lo);
    bf16* R = g_cb3 + ((size_t)c * N_CODES + n) * KB_E;
    R[k] = hi; R[D_LAT + k] = hi; R[2 * D_LAT + k] = lo;

    float s = v * v;
    int lane = k & 31, warp = k >> 5;
#pragma unroll
    for (int off = 16; off > 0; off >>= 1)
        s += __shfl_down_sync(0xffffffffu, s, off);
    if (lane == 0) red[warp] = s;
    __syncthreads();
    if (k == 0) {
        float t = 0.f;
#pragma unroll
        for (int i = 0; i < 8; i++) t += red[i];
        g_cnorm[c * N_CODES + n] = t;
    }
}

__global__ void finalize_k(float* __restrict__ out_loss) {
    double loss = g_loss[0] / ((double)B_ROWS * (double)D_IN)
                + 0.25 * ((g_loss[1] + g_loss[2]) / ((double)B_ROWS * (double)D_LAT));
    out_loss[0] = (float)loss;
}

// ---------------- universal split-bf16 HMMA GEMM (3-stage pipeline) ---------
// C[M,N] = A[M,kA] @ BT[N,K]^T, K-remap on A (wraps to hi segment for Bl part).
// NT = n-tiles per warp (8 -> HN=128, 7 -> HN=112).
// EPI 1: +bias, relu -> split pair [h|l] bf16, row stride ldc
// EPI 2: +bias, tanh -> f32 store + sum((v-X)^2) into lossAcc (NT=7, no bounds)
// EPI 3: +bias -> f32 (Cout, stride Nout) AND split pair (Cout2, 2*Nout)
// EPI 4: dv = aux[gn] - 2*acc; per-row argmin over CTA's 128 cols
#define HM 128
#define HK 64
#define PITCH 144
#define NSTAGE 3
#define TILE_B (HM * PITCH)                    // 18432
#define SMEM_HMMA (2 * NSTAGE * TILE_B)        // 110592

template <int EPI, int NT>
__global__ void __launch_bounds__(256)
hmma_k(const bf16* __restrict__ A, const bf16* __restrict__ BT,
       const float* __restrict__ aux, void* __restrict__ Cout,
       void* __restrict__ Cout2, int kA, int K, int Nout, int ldc,
       const float* __restrict__ X, double* __restrict__ lossAcc) {
    extern __shared__ char sm[];
    __shared__ float red[8];

    const int HN_T = 16 * NT;            // CTA n-tile width
    const int tid = threadIdx.x;
    const int wid = tid >> 5, lane = tid & 31;
    const int warp_m = wid >> 1, warp_n = wid & 1;
    const int m0 = blockIdx.y * HM, n0 = blockIdx.x * HN_T;
    const int NC = K / HK;

    const uint32_t smA = smem_u32(sm);
    const uint32_t smB = smA + NSTAGE * TILE_B;

    const int lrow = tid >> 3;           // 0..31
    const int lseg = (tid & 7) << 4;     // 0,16,...,112
    const size_t rsA = (size_t)kA * 2;
    const size_t rsB = (size_t)K * 2;
    const char* Ag = (const char*)(A + (size_t)m0 * kA) + (size_t)lrow * rsA + lseg;
    const char* Bg = (const char*)(BT + (size_t)n0 * K) + (size_t)lrow * rsB + lseg;
    const uint32_t stoff = lrow * PITCH + lseg;
    const int kAb = kA * 2;  // bytes

    const int a_row = (lane & 15);
    const int a_kb16 = (lane >> 4) << 4;
    const int b_row = (lane & 7) + ((lane >> 4) << 3);
    const int b_kb16 = ((lane >> 3) & 1) << 4;

    uint32_t a_sm[NSTAGE], b_sm[NSTAGE];
#pragma unroll
    for (int s = 0; s < NSTAGE; s++) {
        a_sm[s] = smA + s * TILE_B + (warp_m * 32 + a_row) * PITCH + a_kb16;
        b_sm[s] = smB + s * TILE_B + (warp_n * (NT * 8) + b_row) * PITCH + b_kb16;
    }

    float acc[2][NT][4];
#pragma unroll
    for (int i = 0; i < 2; i++)
#pragma unroll
        for (int j = 0; j < NT; j++)
#pragma unroll
            for (int t = 0; t < 4; t++) acc[i][j][t] = 0.f;

    // prefetch chunks 0 .. NSTAGE-2
#pragma unroll
    for (int s = 0; s < NSTAGE - 1; s++) {
        int koffB = s * (HK * 2);
        int koffA = (koffB < kAb) ? koffB : koffB - kAb;
        uint32_t ast = smA + s * TILE_B + stoff;
        uint32_t bst = smB + s * TILE_B + stoff;
#pragma unroll
        for (int j = 0; j < 4; j++) {
            CP16(ast + j * 32 * PITCH, Ag + (size_t)j * 32 * rsA + koffA);
            CP16(bst + j * 32 * PITCH, Bg + (size_t)j * 32 * rsB + koffB);
        }
        CP_COMMIT();
    }

    int pf = NSTAGE - 1;
    for (int i = 0; i < NC; i++) {
        CP_WAIT(NSTAGE - 2);
        __syncthreads();

        if (pf < NC) {
            int buf = pf % NSTAGE;
            int koffB = pf * (HK * 2);
            int koffA = (koffB < kAb) ? koffB : koffB - kAb;
            uint32_t ast = smA + buf * TILE_B + stoff;
            uint32_t bst = smB + buf * TILE_B + stoff;
#pragma unroll
            for (int j = 0; j < 4; j++) {
                CP16(ast + j * 32 * PITCH, Ag + (size_t)j * 32 * rsA + koffA);
                CP16(bst + j * 32 * PITCH, Bg + (size_t)j * 32 * rsB + koffB);
            }
        }
        CP_COMMIT();
        pf++;

        int buf = i % NSTAGE;
#pragma unroll
        for (int ks = 0; ks < 4; ks++) {
            uint32_t af[2][4];
#pragma unroll
            for (int im = 0; im < 2; im++)
                ldsm_x4(af[im], a_sm[buf] + im * 16 * PITCH + ks * 32);
            uint32_t bfr[(NT + 1) / 2][4];
#pragma unroll
            for (int jp = 0; jp < NT / 2; jp++)
                ldsm_x4(bfr[jp], b_sm[buf] + jp * 16 * PITCH + ks * 32);
            if (NT & 1)
                ldsm_x2(bfr[NT / 2], b_sm[buf] + (NT - 1) * 8 * PITCH + ks * 32);
#pragma unroll
            for (int im = 0; im < 2; im++)
#pragma unroll
                for (int jn = 0; jn < NT; jn++)
                    mma_bf16(acc[im][jn], af[im], &bfr[jn >> 1][(jn & 1) * 2]);
        }
    }

    // ---- epilogue
    const int qr = lane >> 2, qc = (lane & 3) * 2;

    if (EPI == 4) {
        __syncthreads();
        float2* sMin = (float2*)sm;
        const float* cn = aux;
#pragma unroll
        for (int im = 0; im < 2; im++) {
#pragma unroll
            for (int h = 0; h < 2; h++) {
                int row = warp_m * 32 + im * 16 + h * 8 + qr;
                float bv = 3.4e38f; int bi = 0x7fffffff;
#pragma unroll
                for (int jn = 0; jn < NT; jn++) {
#pragma unroll
                    for (int t = 0; t < 2; t++) {
                        int gn = n0 + warp_n * (NT * 8) + jn * 8 + qc + t;
                        float dv = fmaf(-2.f, acc[im][jn][h * 2 + t], __ldg(&cn[gn]));
                        if (dv < bv) { bv = dv; bi = gn; }
                    }
                }
#pragma unroll
                for (int off = 1; off < 4; off <<= 1) {
                    float ov = __shfl_xor_sync(0xffffffffu, bv, off);
                    int   oi = __shfl_xor_sync(0xffffffffu, bi, off);
                    if (ov < bv || (ov == bv && oi < bi)) { bv = ov; bi = oi; }
                }
                if ((lane & 3) == 0)
                    sMin[row * 2 + warp_n] = make_float2(bv, (float)bi);
            }
        }
        __syncthreads();
        if (tid < HM) {
            float2 c0 = sMin[tid * 2 + 0], c1 = sMin[tid * 2 + 1];
            float2 b = (c1.x < c0.x || (c1.x == c0.x && c1.y < c0.y)) ? c1 : c0;
            ((float2*)Cout)[(size_t)(m0 + tid) * gridDim.x + blockIdx.x] = b;
        }
        return;
    }

    float lsum = 0.f;
#pragma unroll
    for (int im = 0; im < 2; im++) {
#pragma unroll
        for (int h = 0; h < 2; h++) {
            int gm = m0 + warp_m * 32 + im * 16 + qr + h * 8;
#pragma unroll
            for (int jn = 0; jn < NT; jn++) {
                int gn = n0 + warp_n * (NT * 8) + jn * 8 + qc;
                float v0 = acc[im][jn][h * 2 + 0];
                float v1 = acc[im][jn][h * 2 + 1];
                if (EPI == 1) {
                    v0 = fmaxf(v0 + __ldg(&aux[gn]),     0.f);
                    v1 = fmaxf(v1 + __ldg(&aux[gn + 1]), 0.f);
                    bf16 h0, l0, h1, l1;
                    split_bf16(v0, h0, l0); split_bf16(v1, h1, l1);
                    bf16* Cr = (bf16*)Cout + (size_t)gm * ldc;
                    bf162 hp; hp.x = h0; hp.y = h1;
                    bf162 lp; lp.x = l0; lp.y = l1;
                    *(bf162*)(Cr + gn)        = hp;
                    *(bf162*)(Cr + Nout + gn) = lp;
                } else if (EPI == 2) {
                    v0 = tanhf(v0 + __ldg(&aux[gn]));
                    v1 = tanhf(v1 + __ldg(&aux[gn + 1]));
                    const float* Xr = X + (size_t)gm * Nout + gn;
                    float d0 = v0 - Xr[0], d1 = v1 - Xr[1];
                    lsum = fmaf(d0, d0, fmaf(d1, d1, lsum));
                    *(float2*)((float*)Cout + (size_t)gm * Nout + gn) =
                        make_float2(v0, v1);
                } else {  // EPI == 3
                    v0 += __ldg(&aux[gn]);
                    v1 += __ldg(&aux[gn + 1]);
                    *(float2*)((float*)Cout + (size_t)gm * Nout + gn) =
                        make_float2(v0, v1);
                    bf16 h0, l0, h1, l1;
                    split_bf16(v0, h0, l0); split_bf16(v1, h1, l1);
                    bf16* Cr = (bf16*)Cout2 + (size_t)gm * (2 * Nout);
                    bf162 hp; hp.x = h0; hp.y = h1;
                    bf162 lp; lp.x = l0; lp.y = l1;
                    *(bf162*)(Cr + gn)        = hp;
                    *(bf162*)(Cr + Nout + gn) = lp;
                }
            }
        }
    }

    if (EPI == 2) {
#pragma unroll
        for (int off = 16; off > 0; off >>= 1)
            lsum += __shfl_down_sync(0xffffffffu, lsum, off);
        if (lane == 0) red[wid] = lsum;
        __syncthreads();
        if (tid == 0) {
            float s = 0.f;
#pragma unroll
            for (int i = 0; i < 8; i++) s += red[i];
            atomicAdd(lossAcc, (double)s);
        }
    }
}

// ---------------- VQ: combine partial argmins + gather + residual ----------
__global__ void __launch_bounds__(256)
vq_pass_k(const float2* __restrict__ Sp, const float* __restrict__ cb,
          const float* __restrict__ rin, float* __restrict__ rout,
          const float* __restrict__ enc, bf16* __restrict__ tri, int tri_mode,
          float* __restrict__ idx_out, int pass, double* __restrict__ commitAcc) {
    int warp = threadIdx.x >> 5, lane = threadIdx.x & 31;
    __shared__ float wsum[8];
    float csum = 0.f;

    for (int r = 0; r < 8; r++) {
        int m = blockIdx.x * 64 + warp * 8 + r;
        float2 c0 = Sp[(size_t)m * 2 + 0];
        float2 c1 = Sp[(size_t)m * 2 + 1];
        float2 b = (c1.x < c0.x || (c1.x == c0.x && c1.y < c0.y)) ? c1 : c0;
        int bi = (int)b.y;
        if (lane == 0) idx_out[(size_t)m * 2 + pass] = (float)bi;

        const float4* rin4 = (const float4*)(rin + (size_t)m * D_LAT);
        float4*       rout4 = (float4*)(rout + (size_t)m * D_LAT);
        const float4* cb4 = (const float4*)(cb + (size_t)bi * D_LAT);
#pragma unroll
        for (int t = 0; t < 2; t++) {
            int e = t * 32 + lane;
            float4 rv = rin4[e], cv = cb4[e];
            float4 o;
            o.x = rv.x - cv.x; o.y = rv.y - cv.y;
            o.z = rv.z - cv.z; o.w = rv.w - cv.w;
            rout4[e] = o;
            csum += o.x * o.x + o.y * o.y + o.z * o.z + o.w * o.w;

            float q0, q1, q2, q3v;
            if (tri_mode) {
                const float4* enc4 = (const float4*)(enc + (size_t)m * D_LAT);
                float4 ev = enc4[e];
                q0 = ev.x - o.x; q1 = ev.y - o.y;
                q2 = ev.z - o.z; q3v = ev.w - o.w;
            } else {
                q0 = o.x; q1 = o.y; q2 = o.z; q3v = o.w;
            }
            bf16 h0, l0, h1, l1, h2, l2, h3, l3;
            split_bf16(q0, h0, l0); split_bf16(q1, h1, l1);
            split_bf16(q2, h2, l2); split_bf16(q3v, h3, l3);
            bf162* Qr = (bf162*)(tri + (size_t)m * KA_E);
            bf162 hp0; hp0.x = h0; hp0.y = h1;
            bf162 hp1; hp1.x = h2; hp1.y = h3;
            bf162 lp0; lp0.x = l0; lp0.y = l1;
            bf162 lp1; lp1.x = l2; lp1.y = l3;
            Qr[e * 2 + 0]       = hp0;  Qr[e * 2 + 1]       = hp1;
            Qr[128 + e * 2 + 0] = lp0;  Qr[128 + e * 2 + 1] = lp1;
        }
    }

#pragma unroll
    for (int off = 16; off > 0; off >>= 1)
        csum += __shfl_down_sync(0xffffffffu, csum, off);
    if (lane == 0) wsum[warp] = csum;
    __syncthreads();
    if (threadIdx.x == 0) {
        float s = 0.f;
        for (int i = 0; i < 8; i++) s += wsum[i];
        atomicAdd(commitAcc, (double)s);
    }
}

// ---------------- launch ----------------------------------------------------
extern "C" void kernel_launch(void* const* d_in, const int* in_sizes, int n_in,
                              void* d_out, int out_size) {
    const float* x   = (const float*)d_in[0];
    const float* We1 = (const float*)d_in[1];
    const float* be1 = (const float*)d_in[2];
    const float* We2 = (const float*)d_in[3];
    const float* be2 = (const float*)d_in[4];
    const float* cb0 = (const float*)d_in[5];
    const float* cb1 = (const float*)d_in[6];
    const float* Wd1 = (const float*)d_in[7];
    const float* bd1 = (const float*)d_in[8];
    const float* Wd2 = (const float*)d_in[9];
    const float* bd2 = (const float*)d_in[10];

    float* out       = (float*)d_out;
    float* out_recon = out;
    float* out_idx   = out + (size_t)B_ROWS * D_IN;
    float* out_loss  = out + (size_t)B_ROWS * D_IN + (size_t)B_ROWS * 2;

    bf16 *px3, *ph3, *pe3, *pq3, *pd3, *pWe1b, *pWe2b, *pcb3, *pW1b, *pW2b;
    float *penc, *pr, *pcn;
    float2* pSp;
    double* pl;
    cudaGetSymbolAddress((void**)&px3,   g_x3);
    cudaGetSymbolAddress((void**)&ph3,   g_h3);
    cudaGetSymbolAddress((void**)&penc,  g_enc);
    cudaGetSymbolAddress((void**)&pe3,   g_e3);
    cudaGetSymbolAddress((void**)&pr,    g_r);
    cudaGetSymbolAddress((void**)&pSp,   g_Sp);
    cudaGetSymbolAddress((void**)&pq3,   g_q3);
    cudaGetSymbolAddress((void**)&pd3,   g_d3);
    cudaGetSymbolAddress((void**)&pWe1b, g_We1b);
    cudaGetSymbolAddress((void**)&pWe2b, g_We2b);
    cudaGetSymbolAddress((void**)&pcb3,  g_cb3);
    cudaGetSymbolAddress((void**)&pW1b,  g_W1b);
    cudaGetSymbolAddress((void**)&pW2b,  g_W2b);
    cudaGetSymbolAddress((void**)&pcn,   g_cnorm);
    cudaGetSymbolAddress((void**)&pl,    g_loss);

    cudaFuncSetAttribute((const void*)hmma_k<1, 8>, cudaFuncAttributeMaxDynamicSharedMemorySize, SMEM_HMMA);
    cudaFuncSetAttribute((const void*)hmma_k<2, 7>, cudaFuncAttributeMaxDynamicSharedMemorySize, SMEM_HMMA);
    cudaFuncSetAttribute((const void*)hmma_k<3, 8>, cudaFuncAttributeMaxDynamicSharedMemorySize, SMEM_HMMA);
    cudaFuncSetAttribute((const void*)hmma_k<4, 8>, cudaFuncAttributeMaxDynamicSharedMemorySize, SMEM_HMMA);

    dim3 blk(256);

    init_k<<<1, 32>>>();
    prep_x_k<<<(int)(((size_t)B_ROWS * (L_X / 4) + 255) / 256), 256>>>(x);
    prep_we1_k<<<(D_HID * L_X + 255) / 256, 256>>>(We1);
    prep_small_k<<<NB_WE2 + NB_WD1 + NB_WD2, 256>>>(We2, Wd1, Wd2);
    prep_cb_k<<<512, 256>>>(cb0, cb1);

    // encoder
    hmma_k<1, 8><<<dim3(D_HID / 128, B_ROWS / HM), blk, SMEM_HMMA>>>(
        px3, pWe1b, be1, ph3, nullptr, KA_X, KB_X, D_HID, KA_H, nullptr, nullptr);
    hmma_k<3, 8><<<dim3(D_LAT / 128, B_ROWS / HM), blk, SMEM_HMMA>>>(
        ph3, pWe2b, be2, penc, pe3, KA_H, KB_H, D_LAT, 0, nullptr, nullptr);

    // VQ quantizer 0
    hmma_k<4, 8><<<dim3(N_CODES / 128, B_ROWS / HM), blk, SMEM_HMMA>>>(
        pe3, pcb3, pcn, pSp, nullptr, KA_E, KB_E, N_CODES, 0, nullptr, nullptr);
    vq_pass_k<<<B_ROWS / 64, 256>>>(pSp, cb0, penc, pr,
                                    nullptr, pe3, 0, out_idx, 0, pl + 1);
    // VQ quantizer 1
    hmma_k<4, 8><<<dim3(N_CODES / 128, B_ROWS / HM), blk, SMEM_HMMA>>>(
        pe3, pcb3 + (size_t)N_CODES * KB_E, pcn + N_CODES, pSp, nullptr,
        KA_E, KB_E, N_CODES, 0, nullptr, nullptr);
    vq_pass_k<<<B_ROWS / 64, 256>>>(pSp, cb1, pr, pr,
                                    penc, pq3, 1, out_idx, 1, pl + 2);

    // decoder (dec2 with exact N=784 via HN=112 tiles)
    hmma_k<1, 8><<<dim3(D_HID / 128, B_ROWS / HM), blk, SMEM_HMMA>>>(
        pq3, pW1b, bd1, pd3, nullptr, KA_E, KB_E, D_HID, KA_H, nullptr, nullptr);
    hmma_k<2, 7><<<dim3(D_IN / 112, B_ROWS / HM), blk, SMEM_HMMA>>>(
        pd3, pW2b, bd2, out_recon, nullptr, KA_H, KB_H, D_IN, 0, x, pl + 0);

    finalize_k<<<1, 1>>>(out_loss);
}

// round 10
// speedup vs baseline: 2.8516x; 1.1290x over previous
#include <cuda_runtime.h>
#include <cuda_bf16.h>
#include <cuda_fp16.h>
#include <cstdint>
#include <math.h>

#define B_ROWS 65536
#define D_IN   784
#define D_HID  512
#define D_LAT  256
#define N_CODES 256
#define N_PAD  896            // dec2 B rows allocated (tiles read up to row 799)
#define L_X    832            // D_IN padded to 13*64
#define KA_X   (2 * L_X)      // 1664 : GEMM1 A row ([xh|xl])
#define KB_X   (3 * L_X)      // 2496 : GEMM1 B row ([Wh|Wh|Wl])
#define KA_H   (2 * D_HID)    // 1024
#define KB_H   (3 * D_HID)    // 1536
#define KA_E   (2 * D_LAT)    // 512
#define KB_E   (3 * D_LAT)    // 768

typedef __nv_bfloat16 bf16;
typedef __nv_bfloat162 bf162;

// ---------------- scratch (device globals; no allocation allowed) ----------
__device__ bf16 g_x3 [(size_t)B_ROWS * KA_X];   // [xh|xl]
__device__ bf16 g_h3 [(size_t)B_ROWS * KA_H];   // [hh|hl] bf16
__device__ float g_enc[(size_t)B_ROWS * D_LAT];
__device__ bf16 g_e3 [(size_t)B_ROWS * KA_E];   // [eh|el] bf16 (r pairs too)
__device__ float g_r  [(size_t)B_ROWS * D_LAT];
__device__ float2 g_Sp[(size_t)B_ROWS * 2];     // per-128-block (dv, idx)
__device__ __half g_q3 [(size_t)B_ROWS * KA_E]; // [qh|ql] fp16
__device__ __half g_d3 [(size_t)B_ROWS * KA_H]; // [dh|dl] fp16
__device__ bf16 g_We1b[(size_t)D_HID * KB_X];
__device__ bf16 g_We2b[(size_t)D_LAT * KB_H];
__device__ bf16 g_cb3 [2 * N_CODES * KB_E];
__device__ __half g_W1b [(size_t)D_HID * KA_E]; // [Wh|Wh] fp16 (K=512)
__device__ __half g_W2b [(size_t)N_PAD * KA_H]; // [Wh|Wh] fp16 (K=1024)
__device__ float g_cnorm[2 * N_CODES];
__device__ double g_loss[3];                    // recon_sum, commit0, commit1

// ====================== PTX helpers ========================================
__device__ __forceinline__ uint32_t smem_u32(const void* p) {
    uint32_t a;
    asm("{ .reg .u64 t; cvta.to.shared.u64 t, %1; cvt.u32.u64 %0, t; }"
        : "=r"(a) : "l"(p));
    return a;
}
#define CP16(dst, src) \
    asm volatile("cp.async.cg.shared.global [%0], [%1], 16;" :: "r"(dst), "l"(src) : "memory")
#define CP_COMMIT() asm volatile("cp.async.commit_group;" ::: "memory")
#define CP_WAIT(n)  asm volatile("cp.async.wait_group %0;" :: "n"(n) : "memory")

__device__ __forceinline__ void ldsm_x4(uint32_t* r, uint32_t addr) {
    asm volatile("ldmatrix.sync.aligned.m8n8.x4.shared.b16 {%0,%1,%2,%3}, [%4];"
        : "=r"(r[0]), "=r"(r[1]), "=r"(r[2]), "=r"(r[3]) : "r"(addr));
}
__device__ __forceinline__ void ldsm_x2(uint32_t* r, uint32_t addr) {
    asm volatile("ldmatrix.sync.aligned.m8n8.x2.shared.b16 {%0,%1}, [%2];"
        : "=r"(r[0]), "=r"(r[1]) : "r"(addr));
}
__device__ __forceinline__ void mma_bf16(float* c, const uint32_t* a, const uint32_t* b) {
    asm volatile("mma.sync.aligned.m16n8k16.row.col.f32.bf16.bf16.f32 "
        "{%0,%1,%2,%3}, {%4,%5,%6,%7}, {%8,%9}, {%0,%1,%2,%3};"
        : "+f"(c[0]), "+f"(c[1]), "+f"(c[2]), "+f"(c[3])
        : "r"(a[0]), "r"(a[1]), "r"(a[2]), "r"(a[3]), "r"(b[0]), "r"(b[1]));
}
__device__ __forceinline__ void mma_f16(float* c, const uint32_t* a, const uint32_t* b) {
    asm volatile("mma.sync.aligned.m16n8k16.row.col.f32.f16.f16.f32 "
        "{%0,%1,%2,%3}, {%4,%5,%6,%7}, {%8,%9}, {%0,%1,%2,%3};"
        : "+f"(c[0]), "+f"(c[1]), "+f"(c[2]), "+f"(c[3])
        : "r"(a[0]), "r"(a[1]), "r"(a[2]), "r"(a[3]), "r"(b[0]), "r"(b[1]));
}
__device__ __forceinline__ void split_bf16(float v, bf16& hi, bf16& lo) {
    hi = __float2bfloat16_rn(v);
    lo = __float2bfloat16_rn(v - __bfloat162float(hi));
}
__device__ __forceinline__ void split_f16(float v, __half& hi, __half& lo) {
    hi = __float2half_rn(v);
    lo = __float2half_rn(v - __half2float(hi));
}

// ---------------- prep kernels ---------------------------------------------
__global__ void init_k() {
    if (threadIdx.x < 3) g_loss[threadIdx.x] = 0.0;
}

// x [B,784] f32 -> g_x3 [B,1664] = [xh(832)|xl(832)] with zero pad
__global__ void prep_x_k(const float* __restrict__ x) {
    size_t idx = (size_t)blockIdx.x * blockDim.x + threadIdx.x;
    if (idx >= (size_t)B_ROWS * (L_X / 4)) return;
    size_t m = idx / (L_X / 4);
    int c = (int)(idx % (L_X / 4)) * 4;
    bf162 hp0, hp1, lp0, lp1;
    if (c < D_IN) {
        float4 v = *(const float4*)(x + m * D_IN + c);
        bf16 h0, l0, h1, l1, h2, l2, h3, l3;
        split_bf16(v.x, h0, l0); split_bf16(v.y, h1, l1);
        split_bf16(v.z, h2, l2); split_bf16(v.w, h3, l3);
        hp0.x = h0; hp0.y = h1; hp1.x = h2; hp1.y = h3;
        lp0.x = l0; lp0.y = l1; lp1.x = l2; lp1.y = l3;
    } else {
        bf16 z = __float2bfloat16(0.f);
        hp0.x = z; hp0.y = z; hp1 = hp0; lp0 = hp0; lp1 = hp0;
    }
    bf162* R = (bf162*)(g_x3 + m * KA_X);
    R[c / 2] = hp0;             R[c / 2 + 1] = hp1;
    R[(L_X + c) / 2] = lp0;     R[(L_X + c) / 2 + 1] = lp1;
}

// We1 [784,512] -> g_We1b [512, 2496] rows [Wh|Wh|Wl] (zero pad k>=784)
__global__ void prep_we1_k(const float* __restrict__ We1) {
    int idx = blockIdx.x * blockDim.x + threadIdx.x;
    if (idx < D_HID * L_X) {
        int n = idx / L_X, k = idx % L_X;
        float v = (k < D_IN) ? We1[(size_t)k * D_HID + n] : 0.f;
        bf16 hi, lo; split_bf16(v, hi, lo);
        bf16* R = g_We1b + (size_t)n * KB_X;
        R[k] = hi; R[L_X + k] = hi; R[2 * L_X + k] = lo;
    }
}

// merged small weight preps: We2 bf16-3 | Wd1 fp16-2 | Wd2 fp16-2
#define NB_WE2 (D_LAT * D_HID / 256)     // 512
#define NB_WD1 (D_HID * D_LAT / 256)     // 512
#define NB_WD2 (N_PAD * D_HID / 256)     // 1792
__global__ void prep_small_k(const float* __restrict__ We2,
                             const float* __restrict__ Wd1,
                             const float* __restrict__ Wd2) {
    int b = blockIdx.x;
    if (b < NB_WE2) {
        int idx = b * 256 + threadIdx.x;
        int n = idx / D_HID, k = idx % D_HID;
        bf16 hi, lo; split_bf16(We2[(size_t)k * D_LAT + n], hi, lo);
        bf16* R = g_We2b + (size_t)n * KB_H;
        R[k] = hi; R[D_HID + k] = hi; R[2 * D_HID + k] = lo;
        return;
    }
    b -= NB_WE2;
    if (b < NB_WD1) {
        int idx = b * 256 + threadIdx.x;
        int n = idx / D_LAT, k = idx % D_LAT;
        __half h = __float2half_rn(Wd1[(size_t)k * D_HID + n]);
        __half* R = g_W1b + (size_t)n * KA_E;
        R[k] = h; R[D_LAT + k] = h;
        return;
    }
    b -= NB_WD1;
    {
        int idx = b * 256 + threadIdx.x;
        int n = idx / D_HID, k = idx % D_HID;
        __half h = (n < D_IN) ? __float2half_rn(Wd2[(size_t)k * D_IN + n])
                              : __float2half_rn(0.f);
        __half* R = g_W2b + (size_t)n * KA_H;
        R[k] = h; R[D_HID + k] = h;
    }
}

// codebooks: one block per (codebook, code); coalesced loads/stores + reduce
__global__ void prep_cb_k(const float* __restrict__ cb0,
                          const float* __restrict__ cb1) {
    __shared__ float red[8];
    int c = blockIdx.x >> 8;
    int n = blockIdx.x & 255;
    int k = threadIdx.x;
    const float* cb = c ? cb1 : cb0;
    float v = cb[(size_t)n * D_LAT + k];
    bf16 hi, lo; split_bf16(v, hi, lo);
    bf16* R = g_cb3 + ((size_t)c * N_CODES + n) * KB_E;
    R[k] = hi; R[D_LAT + k] = hi; R[2 * D_LAT + k] = lo;

    float s = v * v;
    int lane = k & 31, warp = k >> 5;
#pragma unroll
    for (int off = 16; off > 0; off >>= 1)
        s += __shfl_down_sync(0xffffffffu, s, off);
    if (lane == 0) red[warp] = s;
    __syncthreads();
    if (k == 0) {
        float t = 0.f;
#pragma unroll
        for (int i = 0; i < 8; i++) t += red[i];
        g_cnorm[c * N_CODES + n] = t;
    }
}

__global__ void finalize_k(float* __restrict__ out_loss) {
    double loss = g_loss[0] / ((double)B_ROWS * (double)D_IN)
                + 0.25 * ((g_loss[1] + g_loss[2]) / ((double)B_ROWS * (double)D_LAT));
    out_loss[0] = (float)loss;
}

// ---------------- universal split HMMA GEMM (3-stage pipeline) --------------
// C[M,N] = A[M,kA] @ BT[N,K]^T, K-remap on A (wraps when K > kA).
// DT: 0 = bf16 mma, 1 = fp16 mma. NT: n-tiles per warp (8->HN128, 7->HN112).
// EPI 1: +bias, relu -> split pair [h|l] (type per DT), row stride ldc
// EPI 2: +bias, tanh -> f32 store + sum((v-X)^2) into lossAcc
// EPI 3: +bias -> f32 (Cout, stride Nout) AND bf16 split pair (Cout2, 2*Nout)
// EPI 4: dv = aux[gn] - 2*acc; per-row argmin over CTA's 128 cols
#define HM 128
#define HK 64
#define PITCH 144
#define NSTAGE 3
#define TILE_B (HM * PITCH)                    // 18432
#define SMEM_HMMA (2 * NSTAGE * TILE_B)        // 110592

template <int EPI, int NT, int DT>
__global__ void __launch_bounds__(256)
hmma_k(const void* __restrict__ Av, const void* __restrict__ BTv,
       const float* __restrict__ aux, void* __restrict__ Cout,
       void* __restrict__ Cout2, int kA, int K, int Nout, int ldc,
       const float* __restrict__ X, double* __restrict__ lossAcc) {
    extern __shared__ char sm[];
    __shared__ float red[8];

    const int HN_T = 16 * NT;
    const int tid = threadIdx.x;
    const int wid = tid >> 5, lane = tid & 31;
    const int warp_m = wid >> 1, warp_n = wid & 1;
    const int m0 = blockIdx.y * HM, n0 = blockIdx.x * HN_T;
    const int NC = K / HK;

    const uint32_t smA = smem_u32(sm);
    const uint32_t smB = smA + NSTAGE * TILE_B;

    const int lrow = tid >> 3;
    const int lseg = (tid & 7) << 4;
    const size_t rsA = (size_t)kA * 2;
    const size_t rsB = (size_t)K * 2;
    const char* Ag = (const char*)Av + (size_t)m0 * rsA + (size_t)lrow * rsA + lseg;
    const char* Bg = (const char*)BTv + (size_t)n0 * rsB + (size_t)lrow * rsB + lseg;
    const uint32_t stoff = lrow * PITCH + lseg;
    const int kAb = kA * 2;

    const int a_row = (lane & 15);
    const int a_kb16 = (lane >> 4) << 4;
    const int b_row = (lane & 7) + ((lane >> 4) << 3);
    const int b_kb16 = ((lane >> 3) & 1) << 4;

    uint32_t a_sm[NSTAGE], b_sm[NSTAGE];
#pragma unroll
    for (int s = 0; s < NSTAGE; s++) {
        a_sm[s] = smA + s * TILE_B + (warp_m * 32 + a_row) * PITCH + a_kb16;
        b_sm[s] = smB + s * TILE_B + (warp_n * (NT * 8) + b_row) * PITCH + b_kb16;
    }

    float acc[2][NT][4];
#pragma unroll
    for (int i = 0; i < 2; i++)
#pragma unroll
        for (int j = 0; j < NT; j++)
#pragma unroll
            for (int t = 0; t < 4; t++) acc[i][j][t] = 0.f;

#pragma unroll
    for (int s = 0; s < NSTAGE - 1; s++) {
        int koffB = s * (HK * 2);
        int koffA = (koffB < kAb) ? koffB : koffB - kAb;
        uint32_t ast = smA + s * TILE_B + stoff;
        uint32_t bst = smB + s * TILE_B + stoff;
#pragma unroll
        for (int j = 0; j < 4; j++) {
            CP16(ast + j * 32 * PITCH, Ag + (size_t)j * 32 * rsA + koffA);
            CP16(bst + j * 32 * PITCH, Bg + (size_t)j * 32 * rsB + koffB);
        }
        CP_COMMIT();
    }

    int pf = NSTAGE - 1;
    for (int i = 0; i < NC; i++) {
        CP_WAIT(NSTAGE - 2);
        __syncthreads();

        if (pf < NC) {
            int buf = pf % NSTAGE;
            int koffB = pf * (HK * 2);
            int koffA = (koffB < kAb) ? koffB : koffB - kAb;
            uint32_t ast = smA + buf * TILE_B + stoff;
            uint32_t bst = smB + buf * TILE_B + stoff;
#pragma unroll
            for (int j = 0; j < 4; j++) {
                CP16(ast + j * 32 * PITCH, Ag + (size_t)j * 32 * rsA + koffA);
                CP16(bst + j * 32 * PITCH, Bg + (size_t)j * 32 * rsB + koffB);
            }
        }
        CP_COMMIT();
        pf++;

        int buf = i % NSTAGE;
#pragma unroll
        for (int ks = 0; ks < 4; ks++) {
            uint32_t af[2][4];
#pragma unroll
            for (int im = 0; im < 2; im++)
                ldsm_x4(af[im], a_sm[buf] + im * 16 * PITCH + ks * 32);
            uint32_t bfr[(NT + 1) / 2][4];
#pragma unroll
            for (int jp = 0; jp < NT / 2; jp++)
                ldsm_x4(bfr[jp], b_sm[buf] + jp * 16 * PITCH + ks * 32);
            if (NT & 1)
                ldsm_x2(bfr[NT / 2], b_sm[buf] + (NT - 1) * 8 * PITCH + ks * 32);
#pragma unroll
            for (int im = 0; im < 2; im++)
#pragma unroll
                for (int jn = 0; jn < NT; jn++) {
                    if (DT == 0)
                        mma_bf16(acc[im][jn], af[im], &bfr[jn >> 1][(jn & 1) * 2]);
                    else
                        mma_f16(acc[im][jn], af[im], &bfr[jn >> 1][(jn & 1) * 2]);
                }
        }
    }

    // ---- epilogue
    const int qr = lane >> 2, qc = (lane & 3) * 2;

    if (EPI == 4) {
        __syncthreads();
        float2* sMin = (float2*)sm;
        const float* cn = aux;
#pragma unroll
        for (int im = 0; im < 2; im++) {
#pragma unroll
            for (int h = 0; h < 2; h++) {
                int row = warp_m * 32 + im * 16 + h * 8 + qr;
                float bv = 3.4e38f; int bi = 0x7fffffff;
#pragma unroll
                for (int jn = 0; jn < NT; jn++) {
#pragma unroll
                    for (int t = 0; t < 2; t++) {
                        int gn = n0 + warp_n * (NT * 8) + jn * 8 + qc + t;
                        float dv = fmaf(-2.f, acc[im][jn][h * 2 + t], __ldg(&cn[gn]));
                        if (dv < bv) { bv = dv; bi = gn; }
                    }
                }
#pragma unroll
                for (int off = 1; off < 4; off <<= 1) {
                    float ov = __shfl_xor_sync(0xffffffffu, bv, off);
                    int   oi = __shfl_xor_sync(0xffffffffu, bi, off);
                    if (ov < bv || (ov == bv && oi < bi)) { bv = ov; bi = oi; }
                }
                if ((lane & 3) == 0)
                    sMin[row * 2 + warp_n] = make_float2(bv, (float)bi);
            }
        }
        __syncthreads();
        if (tid < HM) {
            float2 c0 = sMin[tid * 2 + 0], c1 = sMin[tid * 2 + 1];
            float2 b = (c1.x < c0.x || (c1.x == c0.x && c1.y < c0.y)) ? c1 : c0;
            ((float2*)Cout)[(size_t)(m0 + tid) * gridDim.x + blockIdx.x] = b;
        }
        return;
    }

    float lsum = 0.f;
#pragma unroll
    for (int im = 0; im < 2; im++) {
#pragma unroll
        for (int h = 0; h < 2; h++) {
            int gm = m0 + warp_m * 32 + im * 16 + qr + h * 8;
#pragma unroll
            for (int jn = 0; jn < NT; jn++) {
                int gn = n0 + warp_n * (NT * 8) + jn * 8 + qc;
                float v0 = acc[im][jn][h * 2 + 0];
                float v1 = acc[im][jn][h * 2 + 1];
                if (EPI == 1) {
                    v0 = fmaxf(v0 + __ldg(&aux[gn]),     0.f);
                    v1 = fmaxf(v1 + __ldg(&aux[gn + 1]), 0.f);
                    if (DT == 0) {
                        bf16 h0, l0, h1, l1;
                        split_bf16(v0, h0, l0); split_bf16(v1, h1, l1);
                        bf16* Cr = (bf16*)Cout + (size_t)gm * ldc;
                        bf162 hp; hp.x = h0; hp.y = h1;
                        bf162 lp; lp.x = l0; lp.y = l1;
                        *(bf162*)(Cr + gn)        = hp;
                        *(bf162*)(Cr + Nout + gn) = lp;
                    } else {
                        __half h0, l0, h1, l1;
                        split_f16(v0, h0, l0); split_f16(v1, h1, l1);
                        __half* Cr = (__half*)Cout + (size_t)gm * ldc;
                        __half2 hp; hp.x = h0; hp.y = h1;
                        __half2 lp; lp.x = l0; lp.y = l1;
                        *(__half2*)(Cr + gn)        = hp;
                        *(__half2*)(Cr + Nout + gn) = lp;
                    }
                } else if (EPI == 2) {
                    v0 = tanhf(v0 + __ldg(&aux[gn]));
                    v1 = tanhf(v1 + __ldg(&aux[gn + 1]));
                    const float* Xr = X + (size_t)gm * Nout + gn;
                    float d0 = v0 - Xr[0], d1 = v1 - Xr[1];
                    lsum = fmaf(d0, d0, fmaf(d1, d1, lsum));
                    *(float2*)((float*)Cout + (size_t)gm * Nout + gn) =
                        make_float2(v0, v1);
                } else {  // EPI == 3
                    v0 += __ldg(&aux[gn]);
                    v1 += __ldg(&aux[gn + 1]);
                    *(float2*)((float*)Cout + (size_t)gm * Nout + gn) =
                        make_float2(v0, v1);
                    bf16 h0, l0, h1, l1;
                    split_bf16(v0, h0, l0); split_bf16(v1, h1, l1);
                    bf16* Cr = (bf16*)Cout2 + (size_t)gm * (2 * Nout);
                    bf162 hp; hp.x = h0; hp.y = h1;
                    bf162 lp; lp.x = l0; lp.y = l1;
                    *(bf162*)(Cr + gn)        = hp;
                    *(bf162*)(Cr + Nout + gn) = lp;
                }
            }
        }
    }

    if (EPI == 2) {
#pragma unroll
        for (int off = 16; off > 0; off >>= 1)
            lsum += __shfl_down_sync(0xffffffffu, lsum, off);
        if (lane == 0) red[wid] = lsum;
        __syncthreads();
        if (tid == 0) {
            float s = 0.f;
#pragma unroll
            for (int i = 0; i < 8; i++) s += red[i];
            atomicAdd(lossAcc, (double)s);
        }
    }
}

// ---------------- VQ: combine partial argmins + gather + residual ----------
// OUTF 0: tri <- bf16 split(residual_new) ; OUTF 1: tri <- fp16 split(enc - r)
template <int OUTF>
__global__ void __launch_bounds__(256)
vq_pass_k(const float2* __restrict__ Sp, const float* __restrict__ cb,
          const float* __restrict__ rin, float* __restrict__ rout,
          const float* __restrict__ enc, void* __restrict__ tri,
          float* __restrict__ idx_out, int pass, double* __restrict__ commitAcc) {
    int warp = threadIdx.x >> 5, lane = threadIdx.x & 31;
    __shared__ float wsum[8];
    float csum = 0.f;

    for (int r = 0; r < 8; r++) {
        int m = blockIdx.x * 64 + warp * 8 + r;
        float2 c0 = Sp[(size_t)m * 2 + 0];
        float2 c1 = Sp[(size_t)m * 2 + 1];
        float2 b = (c1.x < c0.x || (c1.x == c0.x && c1.y < c0.y)) ? c1 : c0;
        int bi = (int)b.y;
        if (lane == 0) idx_out[(size_t)m * 2 + pass] = (float)bi;

        const float4* rin4 = (const float4*)(rin + (size_t)m * D_LAT);
        float4*       rout4 = (float4*)(rout + (size_t)m * D_LAT);
        const float4* cb4 = (const float4*)(cb + (size_t)bi * D_LAT);
#pragma unroll
        for (int t = 0; t < 2; t++) {
            int e = t * 32 + lane;
            float4 rv = rin4[e], cv = cb4[e];
            float4 o;
            o.x = rv.x - cv.x; o.y = rv.y - cv.y;
            o.z = rv.z - cv.z; o.w = rv.w - cv.w;
            rout4[e] = o;
            csum += o.x * o.x + o.y * o.y + o.z * o.z + o.w * o.w;

            if (OUTF == 0) {
                bf16 h0, l0, h1, l1, h2, l2, h3, l3;
                split_bf16(o.x, h0, l0); split_bf16(o.y, h1, l1);
                split_bf16(o.z, h2, l2); split_bf16(o.w, h3, l3);
                bf162* Qr = (bf162*)((bf16*)tri + (size_t)m * KA_E);
                bf162 hp0; hp0.x = h0; hp0.y = h1;
                bf162 hp1; hp1.x = h2; hp1.y = h3;
                bf162 lp0; lp0.x = l0; lp0.y = l1;
                bf162 lp1; lp1.x = l2; lp1.y = l3;
                Qr[e * 2 + 0]       = hp0;  Qr[e * 2 + 1]       = hp1;
                Qr[128 + e * 2 + 0] = lp0;  Qr[128 + e * 2 + 1] = lp1;
            } else {
                const float4* enc4 = (const float4*)(enc + (size_t)m * D_LAT);
                float4 ev = enc4[e];
                float q0 = ev.x - o.x, q1 = ev.y - o.y;
                float q2 = ev.z - o.z, q3v = ev.w - o.w;
                __half h0, l0, h1, l1, h2, l2, h3, l3;
                split_f16(q0, h0, l0); split_f16(q1, h1, l1);
                split_f16(q2, h2, l2); split_f16(q3v, h3, l3);
                __half2* Qr = (__half2*)((__half*)tri + (size_t)m * KA_E);
                __half2 hp0; hp0.x = h0; hp0.y = h1;
                __half2 hp1; hp1.x = h2; hp1.y = h3;
                __half2 lp0; lp0.x = l0; lp0.y = l1;
                __half2 lp1; lp1.x = l2; lp1.y = l3;
                Qr[e * 2 + 0]       = hp0;  Qr[e * 2 + 1]       = hp1;
                Qr[128 + e * 2 + 0] = lp0;  Qr[128 + e * 2 + 1] = lp1;
            }
        }
    }

#pragma unroll
    for (int off = 16; off > 0; off >>= 1)
        csum += __shfl_down_sync(0xffffffffu, csum, off);
    if (lane == 0) wsum[warp] = csum;
    __syncthreads();
    if (threadIdx.x == 0) {
        float s = 0.f;
        for (int i = 0; i < 8; i++) s += wsum[i];
        atomicAdd(commitAcc, (double)s);
    }
}

// ---------------- launch ----------------------------------------------------
extern "C" void kernel_launch(void* const* d_in, const int* in_sizes, int n_in,
                              void* d_out, int out_size) {
    const float* x   = (const float*)d_in[0];
    const float* We1 = (const float*)d_in[1];
    const float* be1 = (const float*)d_in[2];
    const float* We2 = (const float*)d_in[3];
    const float* be2 = (const float*)d_in[4];
    const float* cb0 = (const float*)d_in[5];
    const float* cb1 = (const float*)d_in[6];
    const float* Wd1 = (const float*)d_in[7];
    const float* bd1 = (const float*)d_in[8];
    const float* Wd2 = (const float*)d_in[9];
    const float* bd2 = (const float*)d_in[10];

    float* out       = (float*)d_out;
    float* out_recon = out;
    float* out_idx   = out + (size_t)B_ROWS * D_IN;
    float* out_loss  = out + (size_t)B_ROWS * D_IN + (size_t)B_ROWS * 2;

    bf16 *px3, *ph3, *pe3, *pWe1b, *pWe2b, *pcb3;
    __half *pq3, *pd3, *pW1b, *pW2b;
    float *penc, *pr, *pcn;
    float2* pSp;
    double* pl;
    cudaGetSymbolAddress((void**)&px3,   g_x3);
    cudaGetSymbolAddress((void**)&ph3,   g_h3);
    cudaGetSymbolAddress((void**)&penc,  g_enc);
    cudaGetSymbolAddress((void**)&pe3,   g_e3);
    cudaGetSymbolAddress((void**)&pr,    g_r);
    cudaGetSymbolAddress((void**)&pSp,   g_Sp);
    cudaGetSymbolAddress((void**)&pq3,   g_q3);
    cudaGetSymbolAddress((void**)&pd3,   g_d3);
    cudaGetSymbolAddress((void**)&pWe1b, g_We1b);
    cudaGetSymbolAddress((void**)&pWe2b, g_We2b);
    cudaGetSymbolAddress((void**)&pcb3,  g_cb3);
    cudaGetSymbolAddress((void**)&pW1b,  g_W1b);
    cudaGetSymbolAddress((void**)&pW2b,  g_W2b);
    cudaGetSymbolAddress((void**)&pcn,   g_cnorm);
    cudaGetSymbolAddress((void**)&pl,    g_loss);

    cudaFuncSetAttribute((const void*)hmma_k<1, 8, 0>, cudaFuncAttributeMaxDynamicSharedMemorySize, SMEM_HMMA);
    cudaFuncSetAttribute((const void*)hmma_k<3, 8, 0>, cudaFuncAttributeMaxDynamicSharedMemorySize, SMEM_HMMA);
    cudaFuncSetAttribute((const void*)hmma_k<4, 8, 0>, cudaFuncAttributeMaxDynamicSharedMemorySize, SMEM_HMMA);
    cudaFuncSetAttribute((const void*)hmma_k<1, 8, 1>, cudaFuncAttributeMaxDynamicSharedMemorySize, SMEM_HMMA);
    cudaFuncSetAttribute((const void*)hmma_k<2, 7, 1>, cudaFuncAttributeMaxDynamicSharedMemorySize, SMEM_HMMA);

    dim3 blk(256);

    init_k<<<1, 32>>>();
    prep_x_k<<<(int)(((size_t)B_ROWS * (L_X / 4) + 255) / 256), 256>>>(x);
    prep_we1_k<<<(D_HID * L_X + 255) / 256, 256>>>(We1);
    prep_small_k<<<NB_WE2 + NB_WD1 + NB_WD2, 256>>>(We2, Wd1, Wd2);
    prep_cb_k<<<512, 256>>>(cb0, cb1);

    // encoder (bf16 3-term, bit-identical to R9 -> indices protected)
    hmma_k<1, 8, 0><<<dim3(D_HID / 128, B_ROWS / HM), blk, SMEM_HMMA>>>(
        px3, pWe1b, be1, ph3, nullptr, KA_X, KB_X, D_HID, KA_H, nullptr, nullptr);
    hmma_k<3, 8, 0><<<dim3(D_LAT / 128, B_ROWS / HM), blk, SMEM_HMMA>>>(
        ph3, pWe2b, be2, penc, pe3, KA_H, KB_H, D_LAT, 0, nullptr, nullptr);

    // VQ quantizer 0
    hmma_k<4, 8, 0><<<dim3(N_CODES / 128, B_ROWS / HM), blk, SMEM_HMMA>>>(
        pe3, pcb3, pcn, pSp, nullptr, KA_E, KB_E, N_CODES, 0, nullptr, nullptr);
    vq_pass_k<0><<<B_ROWS / 64, 256>>>(pSp, cb0, penc, pr,
                                       nullptr, pe3, out_idx, 0, pl + 1);
    // VQ quantizer 1 (emits fp16 split q)
    hmma_k<4, 8, 0><<<dim3(N_CODES / 128, B_ROWS / HM), blk, SMEM_HMMA>>>(
        pe3, pcb3 + (size_t)N_CODES * KB_E, pcn + N_CODES, pSp, nullptr,
        KA_E, KB_E, N_CODES, 0, nullptr, nullptr);
    vq_pass_k<1><<<B_ROWS / 64, 256>>>(pSp, cb1, pr, pr,
                                       penc, pq3, out_idx, 1, pl + 2);

    // decoder (fp16 2-term: K inflation 2x)
    hmma_k<1, 8, 1><<<dim3(D_HID / 128, B_ROWS / HM), blk, SMEM_HMMA>>>(
        pq3, pW1b, bd1, pd3, nullptr, KA_E, KA_E, D_HID, KA_H, nullptr, nullptr);
    hmma_k<2, 7, 1><<<dim3(D_IN / 112, B_ROWS / HM), blk, SMEM_HMMA>>>(
        pd3, pW2b, bd2, out_recon, nullptr, KA_H, KA_H, D_IN, 0, x, pl + 0);

    finalize_k<<<1, 1>>>(out_loss);
}

// round 11
// speedup vs baseline: 3.3181x; 1.1636x over previous
#include <cuda_runtime.h>
#include <cuda_bf16.h>
#include <cuda_fp16.h>
#include <cstdint>
#include <math.h>

#define B_ROWS 65536
#define D_IN   784
#define D_HID  512
#define D_LAT  256
#define N_CODES 256
#define N_PAD  896            // dec2 B rows allocated (tiles read up to row 799)
#define L_X    832            // D_IN padded to 13*64
#define KA_X   (2 * L_X)      // 1664 : GEMM1 A row ([xh|xl])
#define KB_X   (3 * L_X)      // 2496 : GEMM1 B row ([Wh|Wh|Wl])
#define KA_H   (2 * D_HID)    // 1024
#define KB_H   (3 * D_HID)    // 1536
#define KA_E   (2 * D_LAT)    // 512
#define KB_E   (3 * D_LAT)    // 768

typedef __nv_bfloat16 bf16;
typedef __nv_bfloat162 bf162;

// ---------------- scratch (device globals; no allocation allowed) ----------
__device__ bf16 g_x3 [(size_t)B_ROWS * KA_X];   // [xh|xl]
__device__ bf16 g_h3 [(size_t)B_ROWS * KA_H];   // [hh|hl] bf16
__device__ float g_enc[(size_t)B_ROWS * D_LAT];
__device__ bf16 g_e3 [(size_t)B_ROWS * KA_E];   // [eh|el] bf16 (r pairs too)
__device__ float g_r  [(size_t)B_ROWS * D_LAT];
__device__ float2 g_Sp[(size_t)B_ROWS * 2];     // per-128-block (dv, idx)
__device__ __half g_q1 [(size_t)B_ROWS * D_LAT]; // q fp16 (1-term)
__device__ __half g_d1 [(size_t)B_ROWS * D_HID]; // d fp16 (1-term)
__device__ bf16 g_We1b[(size_t)D_HID * KB_X];
__device__ bf16 g_We2b[(size_t)D_LAT * KB_H];
__device__ bf16 g_cb3 [2 * N_CODES * KB_E];
__device__ __half g_W1b [(size_t)D_HID * D_LAT]; // Wd1^T fp16 (K=256)
__device__ __half g_W2b [(size_t)N_PAD * D_HID]; // Wd2^T fp16 (K=512)
__device__ float g_cnorm[2 * N_CODES];
__device__ double g_loss[3];                    // recon_sum, commit0, commit1

// ====================== PTX helpers ========================================
__device__ __forceinline__ uint32_t smem_u32(const void* p) {
    uint32_t a;
    asm("{ .reg .u64 t; cvta.to.shared.u64 t, %1; cvt.u32.u64 %0, t; }"
        : "=r"(a) : "l"(p));
    return a;
}
#define CP16(dst, src) \
    asm volatile("cp.async.cg.shared.global [%0], [%1], 16;" :: "r"(dst), "l"(src) : "memory")
#define CP_COMMIT() asm volatile("cp.async.commit_group;" ::: "memory")
#define CP_WAIT(n)  asm volatile("cp.async.wait_group %0;" :: "n"(n) : "memory")

__device__ __forceinline__ void ldsm_x4(uint32_t* r, uint32_t addr) {
    asm volatile("ldmatrix.sync.aligned.m8n8.x4.shared.b16 {%0,%1,%2,%3}, [%4];"
        : "=r"(r[0]), "=r"(r[1]), "=r"(r[2]), "=r"(r[3]) : "r"(addr));
}
__device__ __forceinline__ void ldsm_x2(uint32_t* r, uint32_t addr) {
    asm volatile("ldmatrix.sync.aligned.m8n8.x2.shared.b16 {%0,%1}, [%2];"
        : "=r"(r[0]), "=r"(r[1]) : "r"(addr));
}
__device__ __forceinline__ void mma_bf16(float* c, const uint32_t* a, const uint32_t* b) {
    asm volatile("mma.sync.aligned.m16n8k16.row.col.f32.bf16.bf16.f32 "
        "{%0,%1,%2,%3}, {%4,%5,%6,%7}, {%8,%9}, {%0,%1,%2,%3};"
        : "+f"(c[0]), "+f"(c[1]), "+f"(c[2]), "+f"(c[3])
        : "r"(a[0]), "r"(a[1]), "r"(a[2]), "r"(a[3]), "r"(b[0]), "r"(b[1]));
}
__device__ __forceinline__ void mma_f16(float* c, const uint32_t* a, const uint32_t* b) {
    asm volatile("mma.sync.aligned.m16n8k16.row.col.f32.f16.f16.f32 "
        "{%0,%1,%2,%3}, {%4,%5,%6,%7}, {%8,%9}, {%0,%1,%2,%3};"
        : "+f"(c[0]), "+f"(c[1]), "+f"(c[2]), "+f"(c[3])
        : "r"(a[0]), "r"(a[1]), "r"(a[2]), "r"(a[3]), "r"(b[0]), "r"(b[1]));
}
__device__ __forceinline__ void split_bf16(float v, bf16& hi, bf16& lo) {
    hi = __float2bfloat16_rn(v);
    lo = __float2bfloat16_rn(v - __bfloat162float(hi));
}

// ---------------- prep kernels ---------------------------------------------
__global__ void init_k() {
    if (threadIdx.x < 3) g_loss[threadIdx.x] = 0.0;
}

// x [B,784] f32 -> g_x3 [B,1664] = [xh(832)|xl(832)] with zero pad
__global__ void prep_x_k(const float* __restrict__ x) {
    size_t idx = (size_t)blockIdx.x * blockDim.x + threadIdx.x;
    if (idx >= (size_t)B_ROWS * (L_X / 4)) return;
    size_t m = idx / (L_X / 4);
    int c = (int)(idx % (L_X / 4)) * 4;
    bf162 hp0, hp1, lp0, lp1;
    if (c < D_IN) {
        float4 v = *(const float4*)(x + m * D_IN + c);
        bf16 h0, l0, h1, l1, h2, l2, h3, l3;
        split_bf16(v.x, h0, l0); split_bf16(v.y, h1, l1);
        split_bf16(v.z, h2, l2); split_bf16(v.w, h3, l3);
        hp0.x = h0; hp0.y = h1; hp1.x = h2; hp1.y = h3;
        lp0.x = l0; lp0.y = l1; lp1.x = l2; lp1.y = l3;
    } else {
        bf16 z = __float2bfloat16(0.f);
        hp0.x = z; hp0.y = z; hp1 = hp0; lp0 = hp0; lp1 = hp0;
    }
    bf162* R = (bf162*)(g_x3 + m * KA_X);
    R[c / 2] = hp0;             R[c / 2 + 1] = hp1;
    R[(L_X + c) / 2] = lp0;     R[(L_X + c) / 2 + 1] = lp1;
}

// We1 [784,512] -> g_We1b [512, 2496] rows [Wh|Wh|Wl] (zero pad k>=784)
__global__ void prep_we1_k(const float* __restrict__ We1) {
    int idx = blockIdx.x * blockDim.x + threadIdx.x;
    if (idx < D_HID * L_X) {
        int n = idx / L_X, k = idx % L_X;
        float v = (k < D_IN) ? We1[(size_t)k * D_HID + n] : 0.f;
        bf16 hi, lo; split_bf16(v, hi, lo);
        bf16* R = g_We1b + (size_t)n * KB_X;
        R[k] = hi; R[L_X + k] = hi; R[2 * L_X + k] = lo;
    }
}

// merged small weight preps: We2 bf16-3 | Wd1 fp16-1 | Wd2 fp16-1
#define NB_WE2 (D_LAT * D_HID / 256)     // 512
#define NB_WD1 (D_HID * D_LAT / 256)     // 512
#define NB_WD2 (N_PAD * D_HID / 256)     // 1792
__global__ void prep_small_k(const float* __restrict__ We2,
                             const float* __restrict__ Wd1,
                             const float* __restrict__ Wd2) {
    int b = blockIdx.x;
    if (b < NB_WE2) {
        int idx = b * 256 + threadIdx.x;
        int n = idx / D_HID, k = idx % D_HID;
        bf16 hi, lo; split_bf16(We2[(size_t)k * D_LAT + n], hi, lo);
        bf16* R = g_We2b + (size_t)n * KB_H;
        R[k] = hi; R[D_HID + k] = hi; R[2 * D_HID + k] = lo;
        return;
    }
    b -= NB_WE2;
    if (b < NB_WD1) {
        int idx = b * 256 + threadIdx.x;
        int n = idx / D_LAT, k = idx % D_LAT;
        g_W1b[(size_t)n * D_LAT + k] = __float2half_rn(Wd1[(size_t)k * D_HID + n]);
        return;
    }
    b -= NB_WD1;
    {
        int idx = b * 256 + threadIdx.x;
        int n = idx / D_HID, k = idx % D_HID;
        g_W2b[(size_t)n * D_HID + k] =
            (n < D_IN) ? __float2half_rn(Wd2[(size_t)k * D_IN + n])
                       : __float2half_rn(0.f);
    }
}

// codebooks: one block per (codebook, code); coalesced loads/stores + reduce
__global__ void prep_cb_k(const float* __restrict__ cb0,
                          const float* __restrict__ cb1) {
    __shared__ float red[8];
    int c = blockIdx.x >> 8;
    int n = blockIdx.x & 255;
    int k = threadIdx.x;
    const float* cb = c ? cb1 : cb0;
    float v = cb[(size_t)n * D_LAT + k];
    bf16 hi, lo; split_bf16(v, hi, lo);
    bf16* R = g_cb3 + ((size_t)c * N_CODES + n) * KB_E;
    R[k] = hi; R[D_LAT + k] = hi; R[2 * D_LAT + k] = lo;

    float s = v * v;
    int lane = k & 31, warp = k >> 5;
#pragma unroll
    for (int off = 16; off > 0; off >>= 1)
        s += __shfl_down_sync(0xffffffffu, s, off);
    if (lane == 0) red[warp] = s;
    __syncthreads();
    if (k == 0) {
        float t = 0.f;
#pragma unroll
        for (int i = 0; i < 8; i++) t += red[i];
        g_cnorm[c * N_CODES + n] = t;
    }
}

__global__ void finalize_k(float* __restrict__ out_loss) {
    double loss = g_loss[0] / ((double)B_ROWS * (double)D_IN)
                + 0.25 * ((g_loss[1] + g_loss[2]) / ((double)B_ROWS * (double)D_LAT));
    out_loss[0] = (float)loss;
}

// ---------------- universal split HMMA GEMM (3-stage pipeline) --------------
// C[M,N] = A[M,kA] @ BT[N,K]^T, K-remap on A (wraps when K > kA).
// DT: 0 = bf16 mma, 1 = fp16 mma. NT: n-tiles per warp (8->HN128, 7->HN112).
// EPI 1: +bias, relu -> DT==0: bf16 split pair [h|l]; DT==1: single fp16
// EPI 2: +bias, tanh -> f32 store + sum((v-X)^2) into lossAcc
// EPI 3: +bias -> f32 (Cout, stride Nout) AND bf16 split pair (Cout2, 2*Nout)
// EPI 4: dv = aux[gn] - 2*acc; per-row argmin over CTA's 128 cols
#define HM 128
#define HK 64
#define PITCH 144
#define NSTAGE 3
#define TILE_B (HM * PITCH)                    // 18432
#define SMEM_HMMA (2 * NSTAGE * TILE_B)        // 110592

template <int EPI, int NT, int DT>
__global__ void __launch_bounds__(256)
hmma_k(const void* __restrict__ Av, const void* __restrict__ BTv,
       const float* __restrict__ aux, void* __restrict__ Cout,
       void* __restrict__ Cout2, int kA, int K, int Nout, int ldc,
       const float* __restrict__ X, double* __restrict__ lossAcc) {
    extern __shared__ char sm[];
    __shared__ float red[8];

    const int HN_T = 16 * NT;
    const int tid = threadIdx.x;
    const int wid = tid >> 5, lane = tid & 31;
    const int warp_m = wid >> 1, warp_n = wid & 1;
    const int m0 = blockIdx.y * HM, n0 = blockIdx.x * HN_T;
    const int NC = K / HK;

    const uint32_t smA = smem_u32(sm);
    const uint32_t smB = smA + NSTAGE * TILE_B;

    const int lrow = tid >> 3;
    const int lseg = (tid & 7) << 4;
    const size_t rsA = (size_t)kA * 2;
    const size_t rsB = (size_t)K * 2;
    const char* Ag = (const char*)Av + (size_t)m0 * rsA + (size_t)lrow * rsA + lseg;
    const char* Bg = (const char*)BTv + (size_t)n0 * rsB + (size_t)lrow * rsB + lseg;
    const uint32_t stoff = lrow * PITCH + lseg;
    const int kAb = kA * 2;

    const int a_row = (lane & 15);
    const int a_kb16 = (lane >> 4) << 4;
    const int b_row = (lane & 7) + ((lane >> 4) << 3);
    const int b_kb16 = ((lane >> 3) & 1) << 4;

    uint32_t a_sm[NSTAGE], b_sm[NSTAGE];
#pragma unroll
    for (int s = 0; s < NSTAGE; s++) {
        a_sm[s] = smA + s * TILE_B + (warp_m * 32 + a_row) * PITCH + a_kb16;
        b_sm[s] = smB + s * TILE_B + (warp_n * (NT * 8) + b_row) * PITCH + b_kb16;
    }

    float acc[2][NT][4];
#pragma unroll
    for (int i = 0; i < 2; i++)
#pragma unroll
        for (int j = 0; j < NT; j++)
#pragma unroll
            for (int t = 0; t < 4; t++) acc[i][j][t] = 0.f;

#pragma unroll
    for (int s = 0; s < NSTAGE - 1; s++) {
        int koffB = s * (HK * 2);
        int koffA = (koffB < kAb) ? koffB : koffB - kAb;
        uint32_t ast = smA + s * TILE_B + stoff;
        uint32_t bst = smB + s * TILE_B + stoff;
#pragma unroll
        for (int j = 0; j < 4; j++) {
            CP16(ast + j * 32 * PITCH, Ag + (size_t)j * 32 * rsA + koffA);
            CP16(bst + j * 32 * PITCH, Bg + (size_t)j * 32 * rsB + koffB);
        }
        CP_COMMIT();
    }

    int pf = NSTAGE - 1;
    for (int i = 0; i < NC; i++) {
        CP_WAIT(NSTAGE - 2);
        __syncthreads();

        if (pf < NC) {
            int buf = pf % NSTAGE;
            int koffB = pf * (HK * 2);
            int koffA = (koffB < kAb) ? koffB : koffB - kAb;
            uint32_t ast = smA + buf * TILE_B + stoff;
            uint32_t bst = smB + buf * TILE_B + stoff;
#pragma unroll
            for (int j = 0; j < 4; j++) {
                CP16(ast + j * 32 * PITCH, Ag + (size_t)j * 32 * rsA + koffA);
                CP16(bst + j * 32 * PITCH, Bg + (size_t)j * 32 * rsB + koffB);
            }
        }
        CP_COMMIT();
        pf++;

        int buf = i % NSTAGE;
#pragma unroll
        for (int ks = 0; ks < 4; ks++) {
            uint32_t af[2][4];
#pragma unroll
            for (int im = 0; im < 2; im++)
                ldsm_x4(af[im], a_sm[buf] + im * 16 * PITCH + ks * 32);
            uint32_t bfr[(NT + 1) / 2][4];
#pragma unroll
            for (int jp = 0; jp < NT / 2; jp++)
                ldsm_x4(bfr[jp], b_sm[buf] + jp * 16 * PITCH + ks * 32);
            if (NT & 1)
                ldsm_x2(bfr[NT / 2], b_sm[buf] + (NT - 1) * 8 * PITCH + ks * 32);
#pragma unroll
            for (int im = 0; im < 2; im++)
#pragma unroll
                for (int jn = 0; jn < NT; jn++) {
                    if (DT == 0)
                        mma_bf16(acc[im][jn], af[im], &bfr[jn >> 1][(jn & 1) * 2]);
                    else
                        mma_f16(acc[im][jn], af[im], &bfr[jn >> 1][(jn & 1) * 2]);
                }
        }
    }

    // ---- epilogue
    const int qr = lane >> 2, qc = (lane & 3) * 2;

    if (EPI == 4) {
        __syncthreads();
        float2* sMin = (float2*)sm;
        const float* cn = aux;
#pragma unroll
        for (int im = 0; im < 2; im++) {
#pragma unroll
            for (int h = 0; h < 2; h++) {
                int row = warp_m * 32 + im * 16 + h * 8 + qr;
                float bv = 3.4e38f; int bi = 0x7fffffff;
#pragma unroll
                for (int jn = 0; jn < NT; jn++) {
#pragma unroll
                    for (int t = 0; t < 2; t++) {
                        int gn = n0 + warp_n * (NT * 8) + jn * 8 + qc + t;
                        float dv = fmaf(-2.f, acc[im][jn][h * 2 + t], __ldg(&cn[gn]));
                        if (dv < bv) { bv = dv; bi = gn; }
                    }
                }
#pragma unroll
                for (int off = 1; off < 4; off <<= 1) {
                    float ov = __shfl_xor_sync(0xffffffffu, bv, off);
                    int   oi = __shfl_xor_sync(0xffffffffu, bi, off);
                    if (ov < bv || (ov == bv && oi < bi)) { bv = ov; bi = oi; }
                }
                if ((lane & 3) == 0)
                    sMin[row * 2 + warp_n] = make_float2(bv, (float)bi);
            }
        }
        __syncthreads();
        if (tid < HM) {
            float2 c0 = sMin[tid * 2 + 0], c1 = sMin[tid * 2 + 1];
            float2 b = (c1.x < c0.x || (c1.x == c0.x && c1.y < c0.y)) ? c1 : c0;
            ((float2*)Cout)[(size_t)(m0 + tid) * gridDim.x + blockIdx.x] = b;
        }
        return;
    }

    float lsum = 0.f;
#pragma unroll
    for (int im = 0; im < 2; im++) {
#pragma unroll
        for (int h = 0; h < 2; h++) {
            int gm = m0 + warp_m * 32 + im * 16 + qr + h * 8;
#pragma unroll
            for (int jn = 0; jn < NT; jn++) {
                int gn = n0 + warp_n * (NT * 8) + jn * 8 + qc;
                float v0 = acc[im][jn][h * 2 + 0];
                float v1 = acc[im][jn][h * 2 + 1];
                if (EPI == 1) {
                    v0 = fmaxf(v0 + __ldg(&aux[gn]),     0.f);
                    v1 = fmaxf(v1 + __ldg(&aux[gn + 1]), 0.f);
                    if (DT == 0) {
                        bf16 h0, l0, h1, l1;
                        split_bf16(v0, h0, l0); split_bf16(v1, h1, l1);
                        bf16* Cr = (bf16*)Cout + (size_t)gm * ldc;
                        bf162 hp; hp.x = h0; hp.y = h1;
                        bf162 lp; lp.x = l0; lp.y = l1;
                        *(bf162*)(Cr + gn)        = hp;
                        *(bf162*)(Cr + Nout + gn) = lp;
                    } else {
                        __half2 hp;
                        hp.x = __float2half_rn(v0);
                        hp.y = __float2half_rn(v1);
                        *(__half2*)((__half*)Cout + (size_t)gm * ldc + gn) = hp;
                    }
                } else if (EPI == 2) {
                    v0 = tanhf(v0 + __ldg(&aux[gn]));
                    v1 = tanhf(v1 + __ldg(&aux[gn + 1]));
                    const float* Xr = X + (size_t)gm * Nout + gn;
                    float d0 = v0 - Xr[0], d1 = v1 - Xr[1];
                    lsum = fmaf(d0, d0, fmaf(d1, d1, lsum));
                    *(float2*)((float*)Cout + (size_t)gm * Nout + gn) =
                        make_float2(v0, v1);
                } else {  // EPI == 3
                    v0 += __ldg(&aux[gn]);
                    v1 += __ldg(&aux[gn + 1]);
                    *(float2*)((float*)Cout + (size_t)gm * Nout + gn) =
                        make_float2(v0, v1);
                    bf16 h0, l0, h1, l1;
                    split_bf16(v0, h0, l0); split_bf16(v1, h1, l1);
                    bf16* Cr = (bf16*)Cout2 + (size_t)gm * (2 * Nout);
                    bf162 hp; hp.x = h0; hp.y = h1;
                    bf162 lp; lp.x = l0; lp.y = l1;
                    *(bf162*)(Cr + gn)        = hp;
                    *(bf162*)(Cr + Nout + gn) = lp;
                }
            }
        }
    }

    if (EPI == 2) {
#pragma unroll
        for (int off = 16; off > 0; off >>= 1)
            lsum += __shfl_down_sync(0xffffffffu, lsum, off);
        if (lane == 0) red[wid] = lsum;
        __syncthreads();
        if (tid == 0) {
            float s = 0.f;
#pragma unroll
            for (int i = 0; i < 8; i++) s += red[i];
            atomicAdd(lossAcc, (double)s);
        }
    }
}

// ---------------- VQ: combine partial argmins + gather + residual ----------
// OUTF 0: tri <- bf16 split pair (residual_new) ; OUTF 1: tri <- fp16 (enc - r)
template <int OUTF>
__global__ void __launch_bounds__(256)
vq_pass_k(const float2* __restrict__ Sp, const float* __restrict__ cb,
          const float* __restrict__ rin, float* __restrict__ rout,
          const float* __restrict__ enc, void* __restrict__ tri,
          float* __restrict__ idx_out, int pass, double* __restrict__ commitAcc) {
    int warp = threadIdx.x >> 5, lane = threadIdx.x & 31;
    __shared__ float wsum[8];
    float csum = 0.f;

    for (int r = 0; r < 8; r++) {
        int m = blockIdx.x * 64 + warp * 8 + r;
        float2 c0 = Sp[(size_t)m * 2 + 0];
        float2 c1 = Sp[(size_t)m * 2 + 1];
        float2 b = (c1.x < c0.x || (c1.x == c0.x && c1.y < c0.y)) ? c1 : c0;
        int bi = (int)b.y;
        if (lane == 0) idx_out[(size_t)m * 2 + pass] = (float)bi;

        const float4* rin4 = (const float4*)(rin + (size_t)m * D_LAT);
        float4*       rout4 = (float4*)(rout + (size_t)m * D_LAT);
        const float4* cb4 = (const float4*)(cb + (size_t)bi * D_LAT);
#pragma unroll
        for (int t = 0; t < 2; t++) {
            int e = t * 32 + lane;
            float4 rv = rin4[e], cv = cb4[e];
            float4 o;
            o.x = rv.x - cv.x; o.y = rv.y - cv.y;
            o.z = rv.z - cv.z; o.w = rv.w - cv.w;
            rout4[e] = o;
            csum += o.x * o.x + o.y * o.y + o.z * o.z + o.w * o.w;

            if (OUTF == 0) {
                bf16 h0, l0, h1, l1, h2, l2, h3, l3;
                split_bf16(o.x, h0, l0); split_bf16(o.y, h1, l1);
                split_bf16(o.z, h2, l2); split_bf16(o.w, h3, l3);
                bf162* Qr = (bf162*)((bf16*)tri + (size_t)m * KA_E);
                bf162 hp0; hp0.x = h0; hp0.y = h1;
                bf162 hp1; hp1.x = h2; hp1.y = h3;
                bf162 lp0; lp0.x = l0; lp0.y = l1;
                bf162 lp1; lp1.x = l2; lp1.y = l3;
                Qr[e * 2 + 0]       = hp0;  Qr[e * 2 + 1]       = hp1;
                Qr[128 + e * 2 + 0] = lp0;  Qr[128 + e * 2 + 1] = lp1;
            } else {
                const float4* enc4 = (const float4*)(enc + (size_t)m * D_LAT);
                float4 ev = enc4[e];
                __half2 hp0, hp1;
                hp0.x = __float2half_rn(ev.x - o.x);
                hp0.y = __float2half_rn(ev.y - o.y);
                hp1.x = __float2half_rn(ev.z - o.z);
                hp1.y = __float2half_rn(ev.w - o.w);
                __half2* Qr = (__half2*)((__half*)tri + (size_t)m * D_LAT);
                Qr[e * 2 + 0] = hp0;  Qr[e * 2 + 1] = hp1;
            }
        }
    }

#pragma unroll
    for (int off = 16; off > 0; off >>= 1)
        csum += __shfl_down_sync(0xffffffffu, csum, off);
    if (lane == 0) wsum[warp] = csum;
    __syncthreads();
    if (threadIdx.x == 0) {
        float s = 0.f;
        for (int i = 0; i < 8; i++) s += wsum[i];
        atomicAdd(commitAcc, (double)s);
    }
}

// ---------------- launch ----------------------------------------------------
extern "C" void kernel_launch(void* const* d_in, const int* in_sizes, int n_in,
                              void* d_out, int out_size) {
    const float* x   = (const float*)d_in[0];
    const float* We1 = (const float*)d_in[1];
    const float* be1 = (const float*)d_in[2];
    const float* We2 = (const float*)d_in[3];
    const float* be2 = (const float*)d_in[4];
    const float* cb0 = (const float*)d_in[5];
    const float* cb1 = (const float*)d_in[6];
    const float* Wd1 = (const float*)d_in[7];
    const float* bd1 = (const float*)d_in[8];
    const float* Wd2 = (const float*)d_in[9];
    const float* bd2 = (const float*)d_in[10];

    float* out       = (float*)d_out;
    float* out_recon = out;
    float* out_idx   = out + (size_t)B_ROWS * D_IN;
    float* out_loss  = out + (size_t)B_ROWS * D_IN + (size_t)B_ROWS * 2;

    bf16 *px3, *ph3, *pe3, *pWe1b, *pWe2b, *pcb3;
    __half *pq1, *pd1, *pW1b, *pW2b;
    float *penc, *pr, *pcn;
    float2* pSp;
    double* pl;
    cudaGetSymbolAddress((void**)&px3,   g_x3);
    cudaGetSymbolAddress((void**)&ph3,   g_h3);
    cudaGetSymbolAddress((void**)&penc,  g_enc);
    cudaGetSymbolAddress((void**)&pe3,   g_e3);
    cudaGetSymbolAddress((void**)&pr,    g_r);
    cudaGetSymbolAddress((void**)&pSp,   g_Sp);
    cudaGetSymbolAddress((void**)&pq1,   g_q1);
    cudaGetSymbolAddress((void**)&pd1,   g_d1);
    cudaGetSymbolAddress((void**)&pWe1b, g_We1b);
    cudaGetSymbolAddress((void**)&pWe2b, g_We2b);
    cudaGetSymbolAddress((void**)&pcb3,  g_cb3);
    cudaGetSymbolAddress((void**)&pW1b,  g_W1b);
    cudaGetSymbolAddress((void**)&pW2b,  g_W2b);
    cudaGetSymbolAddress((void**)&pcn,   g_cnorm);
    cudaGetSymbolAddress((void**)&pl,    g_loss);

    cudaFuncSetAttribute((const void*)hmma_k<1, 8, 0>, cudaFuncAttributeMaxDynamicSharedMemorySize, SMEM_HMMA);
    cudaFuncSetAttribute((const void*)hmma_k<3, 8, 0>, cudaFuncAttributeMaxDynamicSharedMemorySize, SMEM_HMMA);
    cudaFuncSetAttribute((const void*)hmma_k<4, 8, 0>, cudaFuncAttributeMaxDynamicSharedMemorySize, SMEM_HMMA);
    cudaFuncSetAttribute((const void*)hmma_k<1, 8, 1>, cudaFuncAttributeMaxDynamicSharedMemorySize, SMEM_HMMA);
    cudaFuncSetAttribute((const void*)hmma_k<2, 7, 1>, cudaFuncAttributeMaxDynamicSharedMemorySize, SMEM_HMMA);

    dim3 blk(256);

    init_k<<<1, 32>>>();
    prep_x_k<<<(int)(((size_t)B_ROWS * (L_X / 4) + 255) / 256), 256>>>(x);
    prep_we1_k<<<(D_HID * L_X + 255) / 256, 256>>>(We1);
    prep_small_k<<<NB_WE2 + NB_WD1 + NB_WD2, 256>>>(We2, Wd1, Wd2);
    prep_cb_k<<<512, 256>>>(cb0, cb1);

    // encoder (bf16 3-term, bit-identical to R9/R10 -> indices protected)
    hmma_k<1, 8, 0><<<dim3(D_HID / 128, B_ROWS / HM), blk, SMEM_HMMA>>>(
        px3, pWe1b, be1, ph3, nullptr, KA_X, KB_X, D_HID, KA_H, nullptr, nullptr);
    hmma_k<3, 8, 0><<<dim3(D_LAT / 128, B_ROWS / HM), blk, SMEM_HMMA>>>(
        ph3, pWe2b, be2, penc, pe3, KA_H, KB_H, D_LAT, 0, nullptr, nullptr);

    // VQ quantizer 0
    hmma_k<4, 8, 0><<<dim3(N_CODES / 128, B_ROWS / HM), blk, SMEM_HMMA>>>(
        pe3, pcb3, pcn, pSp, nullptr, KA_E, KB_E, N_CODES, 0, nullptr, nullptr);
    vq_pass_k<0><<<B_ROWS / 64, 256>>>(pSp, cb0, penc, pr,
                                       nullptr, pe3, out_idx, 0, pl + 1);
    // VQ quantizer 1 (emits fp16 q, 1-term)
    hmma_k<4, 8, 0><<<dim3(N_CODES / 128, B_ROWS / HM), blk, SMEM_HMMA>>>(
        pe3, pcb3 + (size_t)N_CODES * KB_E, pcn + N_CODES, pSp, nullptr,
        KA_E, KB_E, N_CODES, 0, nullptr, nullptr);
    vq_pass_k<1><<<B_ROWS / 64, 256>>>(pSp, cb1, pr, pr,
                                       penc, pq1, out_idx, 1, pl + 2);

    // decoder (fp16 1-term: K = 256 / 512, no inflation)
    hmma_k<1, 8, 1><<<dim3(D_HID / 128, B_ROWS / HM), blk, SMEM_HMMA>>>(
        pq1, pW1b, bd1, pd1, nullptr, D_LAT, D_LAT, D_HID, D_HID, nullptr, nullptr);
    hmma_k<2, 7, 1><<<dim3(D_IN / 112, B_ROWS / HM), blk, SMEM_HMMA>>>(
        pd1, pW2b, bd2, out_recon, nullptr, D_HID, D_HID, D_IN, 0, x, pl + 0);

    finalize_k<<<1, 1>>>(out_loss);
}

// round 12
// speedup vs baseline: 3.4412x; 1.0371x over previous
#include <cuda_runtime.h>
#include <cuda_bf16.h>
#include <cuda_fp16.h>
#include <cstdint>
#include <math.h>

#define B_ROWS 65536
#define D_IN   784
#define D_HID  512
#define D_LAT  256
#define N_CODES 256
#define N_PAD  896
#define L_X    832            // D_IN padded to 13*64
#define KA_X   (2 * L_X)      // 1664
#define KB_X   (3 * L_X)      // 2496
#define KA_H   (2 * D_HID)    // 1024
#define KB_H   (3 * D_HID)    // 1536
#define KA_E   (2 * D_LAT)    // 512
#define KB_E   (3 * D_LAT)    // 768

typedef __nv_bfloat16 bf16;
typedef __nv_bfloat162 bf162;

// ---------------- scratch ----------------------------------------------------
__device__ bf16 g_x3 [(size_t)B_ROWS * KA_X];    // [xh|xl]
__device__ bf16 g_h3 [(size_t)B_ROWS * KA_H];    // [hh|hl]
__device__ float g_enc[(size_t)B_ROWS * D_LAT];
__device__ bf16 g_e3 [(size_t)B_ROWS * KA_E];    // [eh|el]
__device__ float2 g_Sp[(size_t)B_ROWS * 2];      // cb0 block argmins
__device__ float g_S1[(size_t)B_ROWS * N_CODES]; // raw enc.cb1^T
__device__ __half g_d1[(size_t)B_ROWS * D_HID];  // decoder hidden fp16
__device__ bf16 g_We1b[(size_t)D_HID * KB_X];
__device__ bf16 g_We2b[(size_t)D_LAT * KB_H];
__device__ bf16 g_cb3 [2 * N_CODES * KB_E];      // [cb0 rows | cb1 rows]
__device__ __half g_W2b[(size_t)N_PAD * D_HID];  // Wd2^T fp16
__device__ float g_cnorm[2 * N_CODES];
__device__ float g_cb1T[N_CODES * D_LAT];        // cb1 transposed f32
__device__ float g_T1 [N_CODES * N_CODES];       // cn1[j] + 2*cb0_i.cb1_j
__device__ float g_P0 [N_CODES * D_HID];         // cb0 @ Wd1
__device__ float g_P1 [N_CODES * D_HID];         // cb1 @ Wd1
__device__ double g_loss[3];

// ====================== PTX helpers ========================================
__device__ __forceinline__ uint32_t smem_u32(const void* p) {
    uint32_t a;
    asm("{ .reg .u64 t; cvta.to.shared.u64 t, %1; cvt.u32.u64 %0, t; }"
        : "=r"(a) : "l"(p));
    return a;
}
#define CP16(dst, src) \
    asm volatile("cp.async.cg.shared.global [%0], [%1], 16;" :: "r"(dst), "l"(src) : "memory")
#define CP_COMMIT() asm volatile("cp.async.commit_group;" ::: "memory")
#define CP_WAIT(n)  asm volatile("cp.async.wait_group %0;" :: "n"(n) : "memory")

__device__ __forceinline__ void ldsm_x4(uint32_t* r, uint32_t addr) {
    asm volatile("ldmatrix.sync.aligned.m8n8.x4.shared.b16 {%0,%1,%2,%3}, [%4];"
        : "=r"(r[0]), "=r"(r[1]), "=r"(r[2]), "=r"(r[3]) : "r"(addr));
}
__device__ __forceinline__ void ldsm_x2(uint32_t* r, uint32_t addr) {
    asm volatile("ldmatrix.sync.aligned.m8n8.x2.shared.b16 {%0,%1}, [%2];"
        : "=r"(r[0]), "=r"(r[1]) : "r"(addr));
}
__device__ __forceinline__ void mma_bf16(float* c, const uint32_t* a, const uint32_t* b) {
    asm volatile("mma.sync.aligned.m16n8k16.row.col.f32.bf16.bf16.f32 "
        "{%0,%1,%2,%3}, {%4,%5,%6,%7}, {%8,%9}, {%0,%1,%2,%3};"
        : "+f"(c[0]), "+f"(c[1]), "+f"(c[2]), "+f"(c[3])
        : "r"(a[0]), "r"(a[1]), "r"(a[2]), "r"(a[3]), "r"(b[0]), "r"(b[1]));
}
__device__ __forceinline__ void mma_f16(float* c, const uint32_t* a, const uint32_t* b) {
    asm volatile("mma.sync.aligned.m16n8k16.row.col.f32.f16.f16.f32 "
        "{%0,%1,%2,%3}, {%4,%5,%6,%7}, {%8,%9}, {%0,%1,%2,%3};"
        : "+f"(c[0]), "+f"(c[1]), "+f"(c[2]), "+f"(c[3])
        : "r"(a[0]), "r"(a[1]), "r"(a[2]), "r"(a[3]), "r"(b[0]), "r"(b[1]));
}
__device__ __forceinline__ void split_bf16(float v, bf16& hi, bf16& lo) {
    hi = __float2bfloat16_rn(v);
    lo = __float2bfloat16_rn(v - __bfloat162float(hi));
}

// ---------------- prep kernels ---------------------------------------------
__global__ void init_k() {
    if (threadIdx.x < 3) g_loss[threadIdx.x] = 0.0;
}

__global__ void prep_x_k(const float* __restrict__ x) {
    size_t idx = (size_t)blockIdx.x * blockDim.x + threadIdx.x;
    if (idx >= (size_t)B_ROWS * (L_X / 4)) return;
    size_t m = idx / (L_X / 4);
    int c = (int)(idx % (L_X / 4)) * 4;
    bf162 hp0, hp1, lp0, lp1;
    if (c < D_IN) {
        float4 v = *(const float4*)(x + m * D_IN + c);
        bf16 h0, l0, h1, l1, h2, l2, h3, l3;
        split_bf16(v.x, h0, l0); split_bf16(v.y, h1, l1);
        split_bf16(v.z, h2, l2); split_bf16(v.w, h3, l3);
        hp0.x = h0; hp0.y = h1; hp1.x = h2; hp1.y = h3;
        lp0.x = l0; lp0.y = l1; lp1.x = l2; lp1.y = l3;
    } else {
        bf16 z = __float2bfloat16(0.f);
        hp0.x = z; hp0.y = z; hp1 = hp0; lp0 = hp0; lp1 = hp0;
    }
    bf162* R = (bf162*)(g_x3 + m * KA_X);
    R[c / 2] = hp0;             R[c / 2 + 1] = hp1;
    R[(L_X + c) / 2] = lp0;     R[(L_X + c) / 2 + 1] = lp1;
}

__global__ void prep_we1_k(const float* __restrict__ We1) {
    int idx = blockIdx.x * blockDim.x + threadIdx.x;
    if (idx < D_HID * L_X) {
        int n = idx / L_X, k = idx % L_X;
        float v = (k < D_IN) ? We1[(size_t)k * D_HID + n] : 0.f;
        bf16 hi, lo; split_bf16(v, hi, lo);
        bf16* R = g_We1b + (size_t)n * KB_X;
        R[k] = hi; R[L_X + k] = hi; R[2 * L_X + k] = lo;
    }
}

// merged: We2 bf16-3 (512 blocks) | Wd2 fp16-1 (1792 blocks)
#define NB_WE2 (D_LAT * D_HID / 256)     // 512
#define NB_WD2 (N_PAD * D_HID / 256)     // 1792
__global__ void prep_small_k(const float* __restrict__ We2,
                             const float* __restrict__ Wd2) {
    int b = blockIdx.x;
    if (b < NB_WE2) {
        int idx = b * 256 + threadIdx.x;
        int n = idx / D_HID, k = idx % D_HID;
        bf16 hi, lo; split_bf16(We2[(size_t)k * D_LAT + n], hi, lo);
        bf16* R = g_We2b + (size_t)n * KB_H;
        R[k] = hi; R[D_HID + k] = hi; R[2 * D_HID + k] = lo;
        return;
    }
    b -= NB_WE2;
    {
        int idx = b * 256 + threadIdx.x;
        int n = idx / D_HID, k = idx % D_HID;
        g_W2b[(size_t)n * D_HID + k] =
            (n < D_IN) ? __float2half_rn(Wd2[(size_t)k * D_IN + n])
                       : __float2half_rn(0.f);
    }
}

// codebooks -> g_cb3 (split) + cnorm + cb1 transpose
__global__ void prep_cb_k(const float* __restrict__ cb0,
                          const float* __restrict__ cb1) {
    __shared__ float red[8];
    int c = blockIdx.x >> 8;
    int n = blockIdx.x & 255;
    int k = threadIdx.x;
    const float* cb = c ? cb1 : cb0;
    float v = cb[(size_t)n * D_LAT + k];
    bf16 hi, lo; split_bf16(v, hi, lo);
    bf16* R = g_cb3 + ((size_t)c * N_CODES + n) * KB_E;
    R[k] = hi; R[D_LAT + k] = hi; R[2 * D_LAT + k] = lo;
    if (c) g_cb1T[k * N_CODES + n] = v;   // transpose cb1

    float s = v * v;
    int lane = k & 31, warp = k >> 5;
#pragma unroll
    for (int off = 16; off > 0; off >>= 1)
        s += __shfl_down_sync(0xffffffffu, s, off);
    if (lane == 0) red[warp] = s;
    __syncthreads();
    if (k == 0) {
        float t = 0.f;
#pragma unroll
        for (int i = 0; i < 8; i++) t += red[i];
        g_cnorm[c * N_CODES + n] = t;
    }
}

// T1[i,j] = cn1[j] + 2*dot(cb0_i, cb1_j). 32 blocks x 8 rows, 256 thr (j).
__global__ void prep_T1_k(const float* __restrict__ cb0) {
    __shared__ float c0s[8][256];
    int j = threadIdx.x;
    int i0 = blockIdx.x * 8;
#pragma unroll
    for (int ii = 0; ii < 8; ii++)
        c0s[ii][j] = cb0[(size_t)(i0 + ii) * D_LAT + j];
    __syncthreads();
    float acc[8] = {0, 0, 0, 0, 0, 0, 0, 0};
    for (int k = 0; k < D_LAT; k++) {
        float bvv = g_cb1T[k * N_CODES + j];
#pragma unroll
        for (int ii = 0; ii < 8; ii++) acc[ii] = fmaf(c0s[ii][k], bvv, acc[ii]);
    }
    float cn1 = g_cnorm[N_CODES + j];
#pragma unroll
    for (int ii = 0; ii < 8; ii++)
        g_T1[(size_t)(i0 + ii) * N_CODES + j] = fmaf(2.f, acc[ii], cn1);
}

// P[i,n] = dot(cb_i, Wd1[:,n]). 64 blocks (32/cb) x 8 rows, 512 thr (n).
__global__ void prep_P_k(const float* __restrict__ cb0,
                         const float* __restrict__ cb1,
                         const float* __restrict__ Wd1) {
    __shared__ float cs[8][256];
    int cbi = blockIdx.x >> 5;
    int i0 = (blockIdx.x & 31) * 8;
    const float* cb = cbi ? cb1 : cb0;
    float* P = cbi ? g_P1 : g_P0;
    int tid = threadIdx.x;
#pragma unroll
    for (int t = 0; t < 4; t++) {
        int u = tid + t * 512;
        cs[u >> 8][u & 255] = cb[(size_t)(i0 + (u >> 8)) * D_LAT + (u & 255)];
    }
    __syncthreads();
    float acc[8] = {0, 0, 0, 0, 0, 0, 0, 0};
    for (int k = 0; k < D_LAT; k++) {
        float w = Wd1[(size_t)k * D_HID + tid];
#pragma unroll
        for (int ii = 0; ii < 8; ii++) acc[ii] = fmaf(cs[ii][k], w, acc[ii]);
    }
#pragma unroll
    for (int ii = 0; ii < 8; ii++)
        P[(size_t)(i0 + ii) * D_HID + tid] = acc[ii];
}

__global__ void finalize_k(float* __restrict__ out_loss) {
    double loss = g_loss[0] / ((double)B_ROWS * (double)D_IN)
                + 0.25 * ((g_loss[1] + g_loss[2]) / ((double)B_ROWS * (double)D_LAT));
    out_loss[0] = (float)loss;
}

// ---------------- universal split HMMA GEMM (3-stage pipeline) --------------
// EPI 1: +bias, relu -> bf16 split pair [h|l], row stride ldc
// EPI 2: +bias, tanh -> f32 store + sum((v-X)^2) into lossAcc
// EPI 3: +bias -> f32 (Cout) AND bf16 split pair (Cout2, 2*Nout)
// EPI 4: N=512 score GEMM: blockIdx.x<2 -> per-row argmin(aux[gn]-2acc) into
//        Cout float2[m*2+bx]; else raw f32 store acc into Cout2[m*256+col]
#define HM 128
#define HK 64
#define PITCH 144
#define NSTAGE 3
#define TILE_B (HM * PITCH)
#define SMEM_HMMA (2 * NSTAGE * TILE_B)

template <int EPI, int NT, int DT>
__global__ void __launch_bounds__(256)
hmma_k(const void* __restrict__ Av, const void* __restrict__ BTv,
       const float* __restrict__ aux, void* __restrict__ Cout,
       void* __restrict__ Cout2, int kA, int K, int Nout, int ldc,
       const float* __restrict__ X, double* __restrict__ lossAcc) {
    extern __shared__ char sm[];
    __shared__ float red[8];

    const int HN_T = 16 * NT;
    const int tid = threadIdx.x;
    const int wid = tid >> 5, lane = tid & 31;
    const int warp_m = wid >> 1, warp_n = wid & 1;
    const int m0 = blockIdx.y * HM, n0 = blockIdx.x * HN_T;
    const int NC = K / HK;

    const uint32_t smA = smem_u32(sm);
    const uint32_t smB = smA + NSTAGE * TILE_B;

    const int lrow = tid >> 3;
    const int lseg = (tid & 7) << 4;
    const size_t rsA = (size_t)kA * 2;
    const size_t rsB = (size_t)K * 2;
    const char* Ag = (const char*)Av + (size_t)m0 * rsA + (size_t)lrow * rsA + lseg;
    const char* Bg = (const char*)BTv + (size_t)n0 * rsB + (size_t)lrow * rsB + lseg;
    const uint32_t stoff = lrow * PITCH + lseg;
    const int kAb = kA * 2;

    const int a_row = (lane & 15);
    const int a_kb16 = (lane >> 4) << 4;
    const int b_row = (lane & 7) + ((lane >> 4) << 3);
    const int b_kb16 = ((lane >> 3) & 1) << 4;

    uint32_t a_sm[NSTAGE], b_sm[NSTAGE];
#pragma unroll
    for (int s = 0; s < NSTAGE; s++) {
        a_sm[s] = smA + s * TILE_B + (warp_m * 32 + a_row) * PITCH + a_kb16;
        b_sm[s] = smB + s * TILE_B + (warp_n * (NT * 8) + b_row) * PITCH + b_kb16;
    }

    float acc[2][NT][4];
#pragma unroll
    for (int i = 0; i < 2; i++)
#pragma unroll
        for (int j = 0; j < NT; j++)
#pragma unroll
            for (int t = 0; t < 4; t++) acc[i][j][t] = 0.f;

#pragma unroll
    for (int s = 0; s < NSTAGE - 1; s++) {
        int koffB = s * (HK * 2);
        int koffA = (koffB < kAb) ? koffB : koffB - kAb;
        uint32_t ast = smA + s * TILE_B + stoff;
        uint32_t bst = smB + s * TILE_B + stoff;
#pragma unroll
        for (int j = 0; j < 4; j++) {
            CP16(ast + j * 32 * PITCH, Ag + (size_t)j * 32 * rsA + koffA);
            CP16(bst + j * 32 * PITCH, Bg + (size_t)j * 32 * rsB + koffB);
        }
        CP_COMMIT();
    }

    int pf = NSTAGE - 1;
    for (int i = 0; i < NC; i++) {
        CP_WAIT(NSTAGE - 2);
        __syncthreads();

        if (pf < NC) {
            int buf = pf % NSTAGE;
            int koffB = pf * (HK * 2);
            int koffA = (koffB < kAb) ? koffB : koffB - kAb;
            uint32_t ast = smA + buf * TILE_B + stoff;
            uint32_t bst = smB + buf * TILE_B + stoff;
#pragma unroll
            for (int j = 0; j < 4; j++) {
                CP16(ast + j * 32 * PITCH, Ag + (size_t)j * 32 * rsA + koffA);
                CP16(bst + j * 32 * PITCH, Bg + (size_t)j * 32 * rsB + koffB);
            }
        }
        CP_COMMIT();
        pf++;

        int buf = i % NSTAGE;
#pragma unroll
        for (int ks = 0; ks < 4; ks++) {
            uint32_t af[2][4];
#pragma unroll
            for (int im = 0; im < 2; im++)
                ldsm_x4(af[im], a_sm[buf] + im * 16 * PITCH + ks * 32);
            uint32_t bfr[(NT + 1) / 2][4];
#pragma unroll
            for (int jp = 0; jp < NT / 2; jp++)
                ldsm_x4(bfr[jp], b_sm[buf] + jp * 16 * PITCH + ks * 32);
            if (NT & 1)
                ldsm_x2(bfr[NT / 2], b_sm[buf] + (NT - 1) * 8 * PITCH + ks * 32);
#pragma unroll
            for (int im = 0; im < 2; im++)
#pragma unroll
                for (int jn = 0; jn < NT; jn++) {
                    if (DT == 0)
                        mma_bf16(acc[im][jn], af[im], &bfr[jn >> 1][(jn & 1) * 2]);
                    else
                        mma_f16(acc[im][jn], af[im], &bfr[jn >> 1][(jn & 1) * 2]);
                }
        }
    }

    // ---- epilogue
    const int qr = lane >> 2, qc = (lane & 3) * 2;

    if (EPI == 4) {
        if (blockIdx.x < 2) {
            __syncthreads();
            float2* sMin = (float2*)sm;
            const float* cn = aux;
#pragma unroll
            for (int im = 0; im < 2; im++) {
#pragma unroll
                for (int h = 0; h < 2; h++) {
                    int row = warp_m * 32 + im * 16 + h * 8 + qr;
                    float bv = 3.4e38f; int bi = 0x7fffffff;
#pragma unroll
                    for (int jn = 0; jn < NT; jn++) {
#pragma unroll
                        for (int t = 0; t < 2; t++) {
                            int gn = n0 + warp_n * (NT * 8) + jn * 8 + qc + t;
                            float dv = fmaf(-2.f, acc[im][jn][h * 2 + t], __ldg(&cn[gn]));
                            if (dv < bv) { bv = dv; bi = gn; }
                        }
                    }
#pragma unroll
                    for (int off = 1; off < 4; off <<= 1) {
                        float ov = __shfl_xor_sync(0xffffffffu, bv, off);
                        int   oi = __shfl_xor_sync(0xffffffffu, bi, off);
                        if (ov < bv || (ov == bv && oi < bi)) { bv = ov; bi = oi; }
                    }
                    if ((lane & 3) == 0)
                        sMin[row * 2 + warp_n] = make_float2(bv, (float)bi);
                }
            }
            __syncthreads();
            if (tid < HM) {
                float2 c0 = sMin[tid * 2 + 0], c1 = sMin[tid * 2 + 1];
                float2 b = (c1.x < c0.x || (c1.x == c0.x && c1.y < c0.y)) ? c1 : c0;
                ((float2*)Cout)[(size_t)(m0 + tid) * 2 + blockIdx.x] = b;
            }
        } else {
            int colbase = n0 - 256;
#pragma unroll
            for (int im = 0; im < 2; im++) {
#pragma unroll
                for (int h = 0; h < 2; h++) {
                    int gm = m0 + warp_m * 32 + im * 16 + qr + h * 8;
#pragma unroll
                    for (int jn = 0; jn < NT; jn++) {
                        int col = colbase + warp_n * (NT * 8) + jn * 8 + qc;
                        *(float2*)((float*)Cout2 + (size_t)gm * 256 + col) =
                            make_float2(acc[im][jn][h * 2 + 0],
                                        acc[im][jn][h * 2 + 1]);
                    }
                }
            }
        }
        return;
    }

    float lsum = 0.f;
#pragma unroll
    for (int im = 0; im < 2; im++) {
#pragma unroll
        for (int h = 0; h < 2; h++) {
            int gm = m0 + warp_m * 32 + im * 16 + qr + h * 8;
#pragma unroll
            for (int jn = 0; jn < NT; jn++) {
                int gn = n0 + warp_n * (NT * 8) + jn * 8 + qc;
                float v0 = acc[im][jn][h * 2 + 0];
                float v1 = acc[im][jn][h * 2 + 1];
                if (EPI == 1) {
                    v0 = fmaxf(v0 + __ldg(&aux[gn]),     0.f);
                    v1 = fmaxf(v1 + __ldg(&aux[gn + 1]), 0.f);
                    bf16 h0, l0, h1, l1;
                    split_bf16(v0, h0, l0); split_bf16(v1, h1, l1);
                    bf16* Cr = (bf16*)Cout + (size_t)gm * ldc;
                    bf162 hp; hp.x = h0; hp.y = h1;
                    bf162 lp; lp.x = l0; lp.y = l1;
                    *(bf162*)(Cr + gn)        = hp;
                    *(bf162*)(Cr + Nout + gn) = lp;
                } else if (EPI == 2) {
                    v0 = tanhf(v0 + __ldg(&aux[gn]));
                    v1 = tanhf(v1 + __ldg(&aux[gn + 1]));
                    const float* Xr = X + (size_t)gm * Nout + gn;
                    float d0 = v0 - Xr[0], d1 = v1 - Xr[1];
                    lsum = fmaf(d0, d0, fmaf(d1, d1, lsum));
                    *(float2*)((float*)Cout + (size_t)gm * Nout + gn) =
                        make_float2(v0, v1);
                } else {  // EPI == 3
                    v0 += __ldg(&aux[gn]);
                    v1 += __ldg(&aux[gn + 1]);
                    *(float2*)((float*)Cout + (size_t)gm * Nout + gn) =
                        make_float2(v0, v1);
                    bf16 h0, l0, h1, l1;
                    split_bf16(v0, h0, l0); split_bf16(v1, h1, l1);
                    bf16* Cr = (bf16*)Cout2 + (size_t)gm * (2 * Nout);
                    bf162 hp; hp.x = h0; hp.y = h1;
                    bf162 lp; lp.x = l0; lp.y = l1;
                    *(bf162*)(Cr + gn)        = hp;
                    *(bf162*)(Cr + Nout + gn) = lp;
                }
            }
        }
    }

    if (EPI == 2) {
#pragma unroll
        for (int off = 16; off > 0; off >>= 1)
            lsum += __shfl_down_sync(0xffffffffu, lsum, off);
        if (lane == 0) red[wid] = lsum;
        __syncthreads();
        if (tid == 0) {
            float s = 0.f;
#pragma unroll
            for (int i = 0; i < 8; i++) s += red[i];
            atomicAdd(lossAcc, (double)s);
        }
    }
}

// ------------- combined VQ: argmin0 + argmin1 + commits + dec1 gather -------
// one warp per row; block = 8 warps = 8 rows
__global__ void __launch_bounds__(256)
vq_k(const float2* __restrict__ Sp, const float* __restrict__ S1e,
     const float* __restrict__ T1, const float* __restrict__ enc,
     const float* __restrict__ P0, const float* __restrict__ P1,
     const float* __restrict__ bd1, __half* __restrict__ dout,
     float* __restrict__ idx_out, double* __restrict__ lossBase) {
    __shared__ float w0s[8], w1s[8];
    int warp = threadIdx.x >> 5, lane = threadIdx.x & 31;
    size_t m = (size_t)blockIdx.x * 8 + warp;

    // argmin0 from the two block candidates
    float2 a0 = Sp[m * 2 + 0];
    float2 a1 = Sp[m * 2 + 1];
    float2 b0 = (a1.x < a0.x || (a1.x == a0.x && a1.y < a0.y)) ? a1 : a0;
    int i0 = (int)b0.y;
    float dmin0 = b0.x;

    // argmin1 over corrected scores: d1_j = T1[i0,j] - 2*S1e[m,j]
    const float* T1r = T1 + (size_t)i0 * N_CODES;
    const float* S1r = S1e + m * N_CODES;
    float bv = 3.4e38f; int bi = 0x7fffffff;
#pragma unroll
    for (int t = 0; t < 8; t++) {
        int j = t * 32 + lane;
        float dv = fmaf(-2.f, S1r[j], T1r[j]);
        if (dv < bv) { bv = dv; bi = j; }
    }
#pragma unroll
    for (int off = 16; off > 0; off >>= 1) {
        float ov = __shfl_down_sync(0xffffffffu, bv, off);
        int   oi = __shfl_down_sync(0xffffffffu, bi, off);
        if (ov < bv || (ov == bv && oi < bi)) { bv = ov; bi = oi; }
    }
    bi = __shfl_sync(0xffffffffu, bi, 0);
    bv = __shfl_sync(0xffffffffu, bv, 0);
    int i1 = bi;

    // ||enc||^2
    const float4* e4 = (const float4*)(enc + m * D_LAT);
    float4 u = e4[lane * 2], v = e4[lane * 2 + 1];
    float ss = u.x * u.x + u.y * u.y + u.z * u.z + u.w * u.w
             + v.x * v.x + v.y * v.y + v.z * v.z + v.w * v.w;
#pragma unroll
    for (int off = 16; off > 0; off >>= 1)
        ss += __shfl_down_sync(0xffffffffu, ss, off);

    if (lane == 0) {
        idx_out[m * 2 + 0] = (float)i0;
        idx_out[m * 2 + 1] = (float)i1;
        float c0v = ss + dmin0;          // ||r1||^2
        w0s[warp] = c0v;
        w1s[warp] = c0v + bv;            // ||r2||^2
    }

    // dec1: d = relu(P0[i0] + P1[i1] + bd1) -> fp16
    const float4* p0 = (const float4*)(P0 + (size_t)i0 * D_HID);
    const float4* p1 = (const float4*)(P1 + (size_t)i1 * D_HID);
    const float4* bz = (const float4*)bd1;
    __half2* dd = (__half2*)(dout + m * D_HID);
#pragma unroll
    for (int t = 0; t < 4; t++) {
        int n4 = t * 32 + lane;
        float4 xa = p0[n4], xb = p1[n4], xc = __ldg(&bz[n4]);
        float r0 = fmaxf(xa.x + xb.x + xc.x, 0.f);
        float r1 = fmaxf(xa.y + xb.y + xc.y, 0.f);
        float r2 = fmaxf(xa.z + xb.z + xc.z, 0.f);
        float r3 = fmaxf(xa.w + xb.w + xc.w, 0.f);
        __half2 h0; h0.x = __float2half_rn(r0); h0.y = __float2half_rn(r1);
        __half2 h1; h1.x = __float2half_rn(r2); h1.y = __float2half_rn(r3);
        dd[n4 * 2 + 0] = h0;
        dd[n4 * 2 + 1] = h1;
    }

    __syncthreads();
    if (threadIdx.x == 0) {
        float s0 = 0.f, s1 = 0.f;
#pragma unroll
        for (int i = 0; i < 8; i++) { s0 += w0s[i]; s1 += w1s[i]; }
        atomicAdd(lossBase + 1, (double)s0);
        atomicAdd(lossBase + 2, (double)s1);
    }
}

// ---------------- launch ----------------------------------------------------
extern "C" void kernel_launch(void* const* d_in, const int* in_sizes, int n_in,
                              void* d_out, int out_size) {
    const float* x   = (const float*)d_in[0];
    const float* We1 = (const float*)d_in[1];
    const float* be1 = (const float*)d_in[2];
    const float* We2 = (const float*)d_in[3];
    const float* be2 = (const float*)d_in[4];
    const float* cb0 = (const float*)d_in[5];
    const float* cb1 = (const float*)d_in[6];
    const float* Wd1 = (const float*)d_in[7];
    const float* bd1 = (const float*)d_in[8];
    const float* Wd2 = (const float*)d_in[9];
    const float* bd2 = (const float*)d_in[10];

    float* out       = (float*)d_out;
    float* out_recon = out;
    float* out_idx   = out + (size_t)B_ROWS * D_IN;
    float* out_loss  = out + (size_t)B_ROWS * D_IN + (size_t)B_ROWS * 2;

    bf16 *px3, *ph3, *pe3, *pWe1b, *pWe2b, *pcb3;
    __half *pd1, *pW2b;
    float *penc, *pcn, *pS1, *pT1, *pP0, *pP1;
    float2* pSp;
    double* pl;
    cudaGetSymbolAddress((void**)&px3,   g_x3);
    cudaGetSymbolAddress((void**)&ph3,   g_h3);
    cudaGetSymbolAddress((void**)&penc,  g_enc);
    cudaGetSymbolAddress((void**)&pe3,   g_e3);
    cudaGetSymbolAddress((void**)&pSp,   g_Sp);
    cudaGetSymbolAddress((void**)&pS1,   g_S1);
    cudaGetSymbolAddress((void**)&pd1,   g_d1);
    cudaGetSymbolAddress((void**)&pWe1b, g_We1b);
    cudaGetSymbolAddress((void**)&pWe2b, g_We2b);
    cudaGetSymbolAddress((void**)&pcb3,  g_cb3);
    cudaGetSymbolAddress((void**)&pW2b,  g_W2b);
    cudaGetSymbolAddress((void**)&pcn,   g_cnorm);
    cudaGetSymbolAddress((void**)&pT1,   g_T1);
    cudaGetSymbolAddress((void**)&pP0,   g_P0);
    cudaGetSymbolAddress((void**)&pP1,   g_P1);
    cudaGetSymbolAddress((void**)&pl,    g_loss);

    cudaFuncSetAttribute((const void*)hmma_k<1, 8, 0>, cudaFuncAttributeMaxDynamicSharedMemorySize, SMEM_HMMA);
    cudaFuncSetAttribute((const void*)hmma_k<3, 8, 0>, cudaFuncAttributeMaxDynamicSharedMemorySize, SMEM_HMMA);
    cudaFuncSetAttribute((const void*)hmma_k<4, 8, 0>, cudaFuncAttributeMaxDynamicSharedMemorySize, SMEM_HMMA);
    cudaFuncSetAttribute((const void*)hmma_k<2, 7, 1>, cudaFuncAttributeMaxDynamicSharedMemorySize, SMEM_HMMA);

    dim3 blk(256);

    init_k<<<1, 32>>>();
    prep_x_k<<<(int)(((size_t)B_ROWS * (L_X / 4) + 255) / 256), 256>>>(x);
    prep_we1_k<<<(D_HID * L_X + 255) / 256, 256>>>(We1);
    prep_small_k<<<NB_WE2 + NB_WD2, 256>>>(We2, Wd2);
    prep_cb_k<<<512, 256>>>(cb0, cb1);
    prep_T1_k<<<32, 256>>>(cb0);
    prep_P_k<<<64, 512>>>(cb0, cb1, Wd1);

    // encoder (bf16-3, bit-identical to R11 -> i0/indices protected)
    hmma_k<1, 8, 0><<<dim3(D_HID / 128, B_ROWS / HM), blk, SMEM_HMMA>>>(
        px3, pWe1b, be1, ph3, nullptr, KA_X, KB_X, D_HID, KA_H, nullptr, nullptr);
    hmma_k<3, 8, 0><<<dim3(D_LAT / 128, B_ROWS / HM), blk, SMEM_HMMA>>>(
        ph3, pWe2b, be2, penc, pe3, KA_H, KB_H, D_LAT, 0, nullptr, nullptr);

    // combined score GEMM over [cb0|cb1]: argmin blocks + raw S1
    hmma_k<4, 8, 0><<<dim3(512 / 128, B_ROWS / HM), blk, SMEM_HMMA>>>(
        pe3, pcb3, pcn, pSp, pS1, KA_E, KB_E, 512, 0, nullptr, nullptr);

    // combined VQ + dec1 gather
    vq_k<<<B_ROWS / 8, 256>>>(pSp, pS1, pT1, penc, pP0, pP1, bd1,
                              pd1, out_idx, pl);

    // dec2 (fp16-1)
    hmma_k<2, 7, 1><<<dim3(D_IN / 112, B_ROWS / HM), blk, SMEM_HMMA>>>(
        pd1, pW2b, bd2, out_recon, nullptr, D_HID, D_HID, D_IN, 0, x, pl + 0);

    finalize_k<<<1, 1>>>(out_loss);
}